// round 2
// baseline (speedup 1.0000x reference)
#include <cuda_runtime.h>
#include <cuda_bf16.h>

// Problem: x [N=256, M=512, D=256] fp32.
//  mean over M, center, sigma = xn^T xn / 511, trace-normalize,
//  4 Newton-Schulz iters: P = 1.5P - 0.5*(P@P@P@S), wm = P/sqrt(tr),
//  out = xn @ wm.

#define NB   256   // batches
#define MM   512   // rows (axis 1)
#define DD   256   // feature dim

// ---------------- scratch (device globals; no allocations allowed) -----------
__device__ float g_mean[NB * DD];                  // 256 KB
__device__ float g_tr[NB];
__device__ float g_S [NB * DD * DD];               // 64 MB  (sigma_norm)
__device__ float g_P0[NB * DD * DD];               // 64 MB
__device__ float g_P1[NB * DD * DD];               // 64 MB
__device__ float g_T2[NB * DD * DD];               // 64 MB  (P^2)
__device__ float g_T3[NB * DD * DD];               // 64 MB  (P^3)

// ---------------- mean over axis 1 ------------------------------------------
__global__ __launch_bounds__(256) void mean_kernel(const float* __restrict__ x) {
    int n = blockIdx.x, d = threadIdx.x;
    const float* xp = x + (size_t)n * MM * DD + d;
    float s0 = 0.f, s1 = 0.f, s2 = 0.f, s3 = 0.f;
    #pragma unroll 4
    for (int m = 0; m < MM; m += 4) {
        s0 += xp[(size_t)(m + 0) * DD];
        s1 += xp[(size_t)(m + 1) * DD];
        s2 += xp[(size_t)(m + 2) * DD];
        s3 += xp[(size_t)(m + 3) * DD];
    }
    g_mean[n * DD + d] = (s0 + s1 + s2 + s3) * (1.f / (float)MM);
}

// ---------------- sigma = xn^T xn / (M-1) ------------------------------------
// Both operands are "K-major" (xn stored [M rows][D cols]) -> no transpose.
// Block: 128x128 output tile, K=512, BK=8, 256 threads, 8x8 per thread.
__global__ __launch_bounds__(256) void sigma_kernel(const float* __restrict__ x) {
    const int n  = blockIdx.z;
    const int d0 = blockIdx.y * 128;
    const int e0 = blockIdx.x * 128;
    const float* X  = x + (size_t)n * MM * DD;
    const float* mn = g_mean + n * DD;

    __shared__ float As[8][128];
    __shared__ float Bs[8][128];
    __shared__ float ma[128], mb[128];

    const int tid = threadIdx.x;
    const int tx = tid & 15, ty = tid >> 4;

    if (tid < 128) ma[tid] = mn[d0 + tid];
    else           mb[tid - 128] = mn[e0 + (tid - 128)];
    __syncthreads();

    float acc[8][8] = {};

    for (int k0 = 0; k0 < MM; k0 += 8) {
        #pragma unroll
        for (int l = 0; l < 4; l++) {
            int idx = tid + 256 * l;           // 0..1023
            int kk = idx >> 7, c = idx & 127;
            As[kk][c] = X[(size_t)(k0 + kk) * DD + d0 + c] - ma[c];
            Bs[kk][c] = X[(size_t)(k0 + kk) * DD + e0 + c] - mb[c];
        }
        __syncthreads();
        #pragma unroll
        for (int kk = 0; kk < 8; kk++) {
            float4 a0 = *reinterpret_cast<const float4*>(&As[kk][ty * 8]);
            float4 a1 = *reinterpret_cast<const float4*>(&As[kk][ty * 8 + 4]);
            float4 b0 = *reinterpret_cast<const float4*>(&Bs[kk][tx * 8]);
            float4 b1 = *reinterpret_cast<const float4*>(&Bs[kk][tx * 8 + 4]);
            float a[8] = {a0.x,a0.y,a0.z,a0.w,a1.x,a1.y,a1.z,a1.w};
            float b[8] = {b0.x,b0.y,b0.z,b0.w,b1.x,b1.y,b1.z,b1.w};
            #pragma unroll
            for (int i = 0; i < 8; i++)
                #pragma unroll
                for (int j = 0; j < 8; j++)
                    acc[i][j] += a[i] * b[j];
        }
        __syncthreads();
    }

    float* Sn = g_S + (size_t)n * DD * DD;
    const float inv = 1.f / (float)(MM - 1);
    #pragma unroll
    for (int i = 0; i < 8; i++)
        #pragma unroll
        for (int j = 0; j < 8; j++)
            Sn[(size_t)(d0 + ty * 8 + i) * DD + (e0 + tx * 8 + j)] = acc[i][j] * inv;
}

// ---------------- trace, normalize S in place, init P0 = I -------------------
__global__ __launch_bounds__(256) void trace_norm_kernel() {
    int n = blockIdx.x, t = threadIdx.x;
    float* Sn = g_S  + (size_t)n * DD * DD;
    float* Pn = g_P0 + (size_t)n * DD * DD;

    __shared__ float red[256];
    __shared__ float inv_sh;
    red[t] = Sn[t * DD + t];
    __syncthreads();
    for (int s = 128; s > 0; s >>= 1) {
        if (t < s) red[t] += red[t + s];
        __syncthreads();
    }
    if (t == 0) { g_tr[n] = red[0]; inv_sh = 1.f / red[0]; }
    __syncthreads();
    const float inv = inv_sh;

    for (int idx = t; idx < DD * DD; idx += 256) {
        Sn[idx] *= inv;
        int r = idx >> 8, c = idx & 255;
        Pn[idx] = (r == c) ? 1.f : 0.f;
    }
}

// ---------------- generic batched 256x256x256 GEMM ---------------------------
// C = alpha * (A @ B) + beta * D   (D may be nullptr; all row-major 256x256)
__global__ __launch_bounds__(256) void gemm256_kernel(
    float* __restrict__ C, const float* __restrict__ A,
    const float* __restrict__ B, const float* __restrict__ Dm,
    float alpha, float beta)
{
    const int n = blockIdx.z;
    const int row0 = blockIdx.y * 128;
    const int col0 = blockIdx.x * 128;
    const float* An = A + (size_t)n * DD * DD;
    const float* Bn = B + (size_t)n * DD * DD;
    float*       Cn = C + (size_t)n * DD * DD;

    __shared__ float As[8][132];   // padded: conflict-free transposed stores
    __shared__ float Bs[8][128];

    const int tid = threadIdx.x;
    const int tx = tid & 15, ty = tid >> 4;

    float acc[8][8] = {};

    for (int k0 = 0; k0 < DD; k0 += 8) {
        #pragma unroll
        for (int l = 0; l < 4; l++) {
            int idx = tid + 256 * l;
            int i  = idx >> 3, kk = idx & 7;     // A: transpose into smem
            As[kk][i] = An[(size_t)(row0 + i) * DD + k0 + kk];
            int kk2 = idx >> 7, j = idx & 127;   // B: straight copy
            Bs[kk2][j] = Bn[(size_t)(k0 + kk2) * DD + col0 + j];
        }
        __syncthreads();
        #pragma unroll
        for (int kk = 0; kk < 8; kk++) {
            float4 a0 = *reinterpret_cast<const float4*>(&As[kk][ty * 8]);
            float4 a1 = *reinterpret_cast<const float4*>(&As[kk][ty * 8 + 4]);
            float4 b0 = *reinterpret_cast<const float4*>(&Bs[kk][tx * 8]);
            float4 b1 = *reinterpret_cast<const float4*>(&Bs[kk][tx * 8 + 4]);
            float a[8] = {a0.x,a0.y,a0.z,a0.w,a1.x,a1.y,a1.z,a1.w};
            float b[8] = {b0.x,b0.y,b0.z,b0.w,b1.x,b1.y,b1.z,b1.w};
            #pragma unroll
            for (int i = 0; i < 8; i++)
                #pragma unroll
                for (int j = 0; j < 8; j++)
                    acc[i][j] += a[i] * b[j];
        }
        __syncthreads();
    }

    const float* Dn = Dm ? Dm + (size_t)n * DD * DD : nullptr;
    #pragma unroll
    for (int i = 0; i < 8; i++)
        #pragma unroll
        for (int j = 0; j < 8; j++) {
            size_t off = (size_t)(row0 + ty * 8 + i) * DD + (col0 + tx * 8 + j);
            float v = alpha * acc[i][j];
            if (Dn) v += beta * Dn[off];
            Cn[off] = v;
        }
}

// ---------------- out = (x - mean) @ P * rsqrt(trace) -------------------------
// M=512, N=256, K=256.  A = xn (row-major), B = P.
__global__ __launch_bounds__(256) void final_kernel(
    float* __restrict__ out, const float* __restrict__ x,
    const float* __restrict__ P)
{
    const int n = blockIdx.z;
    const int m0 = blockIdx.y * 128;   // 4 tiles over M=512
    const int e0 = blockIdx.x * 128;   // 2 tiles over N=256
    const float* X  = x + (size_t)n * MM * DD;
    const float* Bn = P + (size_t)n * DD * DD;
    float*       On = out + (size_t)n * MM * DD;

    __shared__ float As[8][132];
    __shared__ float Bs[8][128];
    __shared__ float mk[256];

    const int tid = threadIdx.x;
    const int tx = tid & 15, ty = tid >> 4;

    mk[tid] = g_mean[n * DD + tid];
    __syncthreads();

    float acc[8][8] = {};

    for (int k0 = 0; k0 < DD; k0 += 8) {
        #pragma unroll
        for (int l = 0; l < 4; l++) {
            int idx = tid + 256 * l;
            int i  = idx >> 3, kk = idx & 7;
            As[kk][i] = X[(size_t)(m0 + i) * DD + k0 + kk] - mk[k0 + kk];
            int kk2 = idx >> 7, j = idx & 127;
            Bs[kk2][j] = Bn[(size_t)(k0 + kk2) * DD + e0 + j];
        }
        __syncthreads();
        #pragma unroll
        for (int kk = 0; kk < 8; kk++) {
            float4 a0 = *reinterpret_cast<const float4*>(&As[kk][ty * 8]);
            float4 a1 = *reinterpret_cast<const float4*>(&As[kk][ty * 8 + 4]);
            float4 b0 = *reinterpret_cast<const float4*>(&Bs[kk][tx * 8]);
            float4 b1 = *reinterpret_cast<const float4*>(&Bs[kk][tx * 8 + 4]);
            float a[8] = {a0.x,a0.y,a0.z,a0.w,a1.x,a1.y,a1.z,a1.w};
            float b[8] = {b0.x,b0.y,b0.z,b0.w,b1.x,b1.y,b1.z,b1.w};
            #pragma unroll
            for (int i = 0; i < 8; i++)
                #pragma unroll
                for (int j = 0; j < 8; j++)
                    acc[i][j] += a[i] * b[j];
        }
        __syncthreads();
    }

    const float sc = rsqrtf(g_tr[n]);
    #pragma unroll
    for (int i = 0; i < 8; i++)
        #pragma unroll
        for (int j = 0; j < 8; j++)
            On[(size_t)(m0 + ty * 8 + i) * DD + (e0 + tx * 8 + j)] = acc[i][j] * sc;
}

// ---------------- host launcher ----------------------------------------------
extern "C" void kernel_launch(void* const* d_in, const int* in_sizes, int n_in,
                              void* d_out, int out_size) {
    const float* x = (const float*)d_in[0];
    float* out = (float*)d_out;

    float *S, *P0, *P1, *T2, *T3;
    cudaGetSymbolAddress((void**)&S,  g_S);
    cudaGetSymbolAddress((void**)&P0, g_P0);
    cudaGetSymbolAddress((void**)&P1, g_P1);
    cudaGetSymbolAddress((void**)&T2, g_T2);
    cudaGetSymbolAddress((void**)&T3, g_T3);

    mean_kernel<<<NB, 256>>>(x);
    sigma_kernel<<<dim3(2, 2, NB), 256>>>(x);
    trace_norm_kernel<<<NB, 256>>>();

    float* pa = P0;
    float* pb = P1;
    for (int it = 0; it < 4; it++) {
        gemm256_kernel<<<dim3(2, 2, NB), 256>>>(T2, pa, pa, nullptr, 1.f, 0.f);
        gemm256_kernel<<<dim3(2, 2, NB), 256>>>(T3, T2, pa, nullptr, 1.f, 0.f);
        gemm256_kernel<<<dim3(2, 2, NB), 256>>>(pb, T3, S,  pa,   -0.5f, 1.5f);
        float* t = pa; pa = pb; pb = t;
    }

    final_kernel<<<dim3(2, 4, NB), 256>>>(out, x, pa);
}

// round 4
// speedup vs baseline: 2.6139x; 2.6139x over previous
#include <cuda_runtime.h>
#include <cstdint>
#include <cstddef>

#define NB   256
#define MM   512
#define DD   256

// ======================= scratch (device globals) ===========================
__device__ __align__(256) float g_mean[NB * DD];
__device__ __align__(256) float g_tr  [NB];           // sumsq = trace*(M-1)
__device__ __align__(256) float g_ssp [NB * 128];
__device__ __align__(256) float g_xn  [NB * MM * DD];
__device__ __align__(256) float g_xnT [NB * DD * MM];
__device__ __align__(256) float g_Ba  [NB * DD * DD];
__device__ __align__(256) float g_Bb  [NB * DD * DD];
__device__ __align__(256) float g_Cm  [NB * DD * DD];
__device__ __align__(256) float g_P0  [NB * DD * DD];
__device__ __align__(256) float g_P1  [NB * DD * DD];

// ======================= PTX helpers ========================================
__device__ __forceinline__ uint32_t smem_u32(const void* p) {
    uint32_t a;
    asm("{ .reg .u64 t; cvta.to.shared.u64 t, %1; cvt.u32.u64 %0, t; }"
        : "=r"(a) : "l"(p));
    return a;
}

#define CP_ASYNC16(dst_u32, src_gptr) \
    asm volatile("cp.async.cg.shared.global [%0], [%1], 16;" \
                 :: "r"(dst_u32), "l"(src_gptr) : "memory")
#define CP_COMMIT() asm volatile("cp.async.commit_group;" ::: "memory")
#define CP_WAIT1()  asm volatile("cp.async.wait_group 1;" ::: "memory")
#define CP_WAIT0()  asm volatile("cp.async.wait_group 0;" ::: "memory")

#define LDM_X4(r0, r1, r2, r3, addr) \
    asm volatile("ldmatrix.sync.aligned.m8n8.x4.shared.b16 {%0,%1,%2,%3}, [%4];" \
                 : "=r"(r0), "=r"(r1), "=r"(r2), "=r"(r3) : "r"(addr))

#define MMA_TF32(d, a, b0, b1) \
    asm volatile("mma.sync.aligned.m16n8k8.row.col.f32.tf32.tf32.f32 " \
                 "{%0,%1,%2,%3}, {%4,%5,%6,%7}, {%8,%9}, {%0,%1,%2,%3};" \
                 : "+f"((d)[0]), "+f"((d)[1]), "+f"((d)[2]), "+f"((d)[3]) \
                 : "r"((a)[0]), "r"((a)[1]), "r"((a)[2]), "r"((a)[3]),   \
                   "r"(b0), "r"(b1))

// lo residual of truncate-to-tf32 (HW reads only the top 19 bits of fp32)
__device__ __forceinline__ uint32_t lo_part(uint32_t x) {
    float f = __uint_as_float(x);
    float h = __uint_as_float(x & 0xFFFFE000u);
    return __float_as_uint(f - h);
}

// ======================= mean over axis 1 ===================================
__global__ __launch_bounds__(256) void mean_kernel(const float* __restrict__ x) {
    int n = blockIdx.x, d = threadIdx.x;
    const float* xp = x + (size_t)n * MM * DD + d;
    float s0 = 0.f, s1 = 0.f, s2 = 0.f, s3 = 0.f;
    #pragma unroll 4
    for (int m = 0; m < MM; m += 4) {
        s0 += xp[(size_t)(m + 0) * DD];
        s1 += xp[(size_t)(m + 1) * DD];
        s2 += xp[(size_t)(m + 2) * DD];
        s3 += xp[(size_t)(m + 3) * DD];
    }
    g_mean[n * DD + d] = (s0 + s1 + s2 + s3) * (1.f / (float)MM);
}

// ============ center: xn = x - mean, xnT = transpose, sumsq partials ========
__global__ __launch_bounds__(256) void center_kernel(const float* __restrict__ x) {
    const int n  = blockIdx.z;
    const int d0 = blockIdx.x * 32;
    const int m0 = blockIdx.y * 32;
    const int tx = threadIdx.x, ty = threadIdx.y;   // block (32, 8)

    __shared__ float tile[32][33];
    __shared__ float red[256];

    const int d = d0 + tx;
    const float mu = g_mean[n * DD + d];
    float ss = 0.f;
    #pragma unroll
    for (int r = 0; r < 4; r++) {
        int m = m0 + ty + r * 8;
        float v = x[(size_t)n * MM * DD + (size_t)m * DD + d] - mu;
        g_xn[(size_t)n * MM * DD + (size_t)m * DD + d] = v;
        tile[ty + r * 8][tx] = v;
        ss += v * v;
    }
    __syncthreads();
    #pragma unroll
    for (int r = 0; r < 4; r++) {
        int dd_ = ty + r * 8;
        g_xnT[(size_t)n * DD * MM + (size_t)(d0 + dd_) * MM + m0 + tx] = tile[tx][dd_];
    }
    int t = ty * 32 + tx;
    red[t] = ss;
    __syncthreads();
    for (int s = 128; s > 0; s >>= 1) {
        if (t < s) red[t] += red[t + s];
        __syncthreads();
    }
    if (t == 0) g_ssp[n * 128 + blockIdx.y * 8 + blockIdx.x] = red[0];
}

__global__ __launch_bounds__(128) void reduce_tr_kernel() {
    int n = blockIdx.x, t = threadIdx.x;
    __shared__ float red[128];
    red[t] = g_ssp[n * 128 + t];
    __syncthreads();
    for (int s = 64; s > 0; s >>= 1) {
        if (t < s) red[t] += red[t + s];
        __syncthreads();
    }
    if (t == 0) g_tr[n] = red[0];
}

// ======================= tf32x3 mma.sync batched GEMM =======================
// D[m][n] = sum_k A[m][k] * B[n][k]   (B read K-major; callers pass symmetric
// matrices or pre-transposed layouts).
// mode: 0: C = acc
//       1: C = acc - 1.5*Dm + 1.5*I       (NS B-update; Dm = B^2)
//       2: C = (-0.5/ts)*acc + 1.5*I      (sigma -> B0)
//       3: C = acc * rsqrt(ts/(M-1))      (final whitening scale)
//
// smem: 2 stages x (A 16KB + B 16KB) = 64KB dynamic.
#define TILE_BYTES 16384
#define SOFF_A(s)  ((uint32_t)(s) * 32768u)
#define SOFF_B(s)  ((uint32_t)(s) * 32768u + 16384u)

__global__ __launch_bounds__(256, 1) void gemm_mma(
    float* __restrict__ Cmat, const float* __restrict__ Amat,
    const float* __restrict__ Bmat, const float* __restrict__ Dmat,
    int lda, int ldb, int Ktot,
    long long sA, long long sB, long long sC, long long sD, int mode)
{
    extern __shared__ char smem[];
    const uint32_t sb = smem_u32(smem);

    const int tid  = threadIdx.x;
    const int wid  = tid >> 5, lane = tid & 31;
    const int wm   = wid & 1;          // 2 warp-rows (64 each)
    const int wn   = wid >> 1;         // 4 warp-cols (32 each)
    const int n    = blockIdx.z;
    const int rb   = blockIdx.x * 128; // CTA row base
    const int cb   = blockIdx.y * 128; // CTA col base

    const float* An = Amat + (size_t)n * sA;
    const float* Bn = Bmat + (size_t)n * sB;
    float*       Cn = Cmat + (size_t)n * sC;

    // staging indices (4 x float4 per tile per thread)
    int srow[4], sch[4];
    uint32_t sdst[4];
    #pragma unroll
    for (int j = 0; j < 4; j++) {
        int idx = tid + 256 * j;
        srow[j] = idx >> 3;
        sch[j]  = idx & 7;
        sdst[j] = (uint32_t)(srow[j] * 128 + ((sch[j] ^ (srow[j] & 7)) << 4));
    }

    // ldmatrix lane geometry
    const int t  = lane >> 3, s7 = lane & 7;
    const int chA = t >> 1;
    const int rAl = wm * 64 + (t & 1) * 8 + s7;
    const int chB = t & 1;
    const int rBl = wn * 32 + (t >> 1) * 8 + s7;

    float acc[4][4][4];
    #pragma unroll
    for (int i = 0; i < 4; i++)
        #pragma unroll
        for (int j = 0; j < 4; j++)
            #pragma unroll
            for (int q = 0; q < 4; q++) acc[i][j][q] = 0.f;

    const int nch = Ktot >> 5;

    // prologue: stage chunk 0 into buffer 0
    {
        #pragma unroll
        for (int j = 0; j < 4; j++) {
            const float* s = An + (size_t)(rb + srow[j]) * lda + sch[j] * 4;
            CP_ASYNC16(sb + SOFF_A(0) + sdst[j], (const void*)s);
        }
        #pragma unroll
        for (int j = 0; j < 4; j++) {
            const float* s = Bn + (size_t)(cb + srow[j]) * ldb + sch[j] * 4;
            CP_ASYNC16(sb + SOFF_B(0) + sdst[j], (const void*)s);
        }
        CP_COMMIT();
    }

    for (int c = 0; c < nch; c++) {
        if (c + 1 < nch) {
            const int bs = (c + 1) & 1;
            const int k0 = (c + 1) * 32;
            #pragma unroll
            for (int j = 0; j < 4; j++) {
                const float* s = An + (size_t)(rb + srow[j]) * lda + k0 + sch[j] * 4;
                CP_ASYNC16(sb + SOFF_A(bs) + sdst[j], (const void*)s);
            }
            #pragma unroll
            for (int j = 0; j < 4; j++) {
                const float* s = Bn + (size_t)(cb + srow[j]) * ldb + k0 + sch[j] * 4;
                CP_ASYNC16(sb + SOFF_B(bs) + sdst[j], (const void*)s);
            }
            CP_COMMIT();
            CP_WAIT1();
        } else {
            CP_WAIT0();
        }
        __syncthreads();

        const uint32_t aB = sb + SOFF_A(c & 1);
        const uint32_t bB = sb + SOFF_B(c & 1);

        #pragma unroll
        for (int kk = 0; kk < 4; kk++) {
            uint32_t af[4][4], al[4][4];
            uint32_t bf[2][4], bl[2][4];
            #pragma unroll
            for (int mi = 0; mi < 4; mi++) {
                uint32_t addr = aB + (uint32_t)((rAl + mi * 16) * 128 +
                                (((kk << 1) + chA) ^ s7) * 16);
                LDM_X4(af[mi][0], af[mi][1], af[mi][2], af[mi][3], addr);
            }
            #pragma unroll
            for (int p = 0; p < 2; p++) {
                uint32_t addr = bB + (uint32_t)((rBl + p * 16) * 128 +
                                (((kk << 1) + chB) ^ s7) * 16);
                LDM_X4(bf[p][0], bf[p][1], bf[p][2], bf[p][3], addr);
            }
            #pragma unroll
            for (int mi = 0; mi < 4; mi++)
                #pragma unroll
                for (int q = 0; q < 4; q++) al[mi][q] = lo_part(af[mi][q]);
            #pragma unroll
            for (int p = 0; p < 2; p++)
                #pragma unroll
                for (int q = 0; q < 4; q++) bl[p][q] = lo_part(bf[p][q]);

            #pragma unroll
            for (int mi = 0; mi < 4; mi++) {
                #pragma unroll
                for (int p = 0; p < 2; p++) {
                    #pragma unroll
                    for (int q = 0; q < 2; q++) {
                        const int nj = p * 2 + q;
                        MMA_TF32(acc[mi][nj], af[mi], bf[p][2*q], bf[p][2*q+1]);
                        MMA_TF32(acc[mi][nj], af[mi], bl[p][2*q], bl[p][2*q+1]);
                        MMA_TF32(acc[mi][nj], al[mi], bf[p][2*q], bf[p][2*q+1]);
                    }
                }
            }
        }
        __syncthreads();
    }

    // ---------------- epilogue ----------------
    const int g = lane >> 2, tig = lane & 3;
    float ts = 0.f;
    if (mode >= 2) ts = g_tr[n];
    const float sc2 = (mode == 2) ? (-0.5f / ts) : 0.f;
    const float sc3 = (mode == 3) ? rsqrtf(ts / (float)(MM - 1)) : 0.f;
    const float* Dn = Dmat ? (Dmat + (size_t)n * sD) : nullptr;

    #pragma unroll
    for (int mi = 0; mi < 4; mi++) {
        #pragma unroll
        for (int nj = 0; nj < 4; nj++) {
            const int col = cb + wn * 32 + nj * 8 + 2 * tig;
            #pragma unroll
            for (int h = 0; h < 2; h++) {
                const int row = rb + wm * 64 + mi * 16 + g + 8 * h;
                float v0 = acc[mi][nj][2 * h];
                float v1 = acc[mi][nj][2 * h + 1];
                if (mode == 1) {
                    const float2 d = *reinterpret_cast<const float2*>(
                        Dn + (size_t)row * DD + col);
                    v0 -= 1.5f * d.x;
                    v1 -= 1.5f * d.y;
                    if (row == col)     v0 += 1.5f;
                    if (row == col + 1) v1 += 1.5f;
                } else if (mode == 2) {
                    v0 *= sc2; v1 *= sc2;
                    if (row == col)     v0 += 1.5f;
                    if (row == col + 1) v1 += 1.5f;
                } else if (mode == 3) {
                    v0 *= sc3; v1 *= sc3;
                }
                *reinterpret_cast<float2*>(Cn + (size_t)row * DD + col) =
                    make_float2(v0, v1);
            }
        }
    }
}

// ======================= host launcher ======================================
extern "C" void kernel_launch(void* const* d_in, const int* in_sizes, int n_in,
                              void* d_out, int out_size) {
    const float* x = (const float*)d_in[0];
    float* out = (float*)d_out;

    float *xn, *xnT, *Ba, *Bb, *Cm, *P0, *P1;
    cudaGetSymbolAddress((void**)&xn,  g_xn);
    cudaGetSymbolAddress((void**)&xnT, g_xnT);
    cudaGetSymbolAddress((void**)&Ba,  g_Ba);
    cudaGetSymbolAddress((void**)&Bb,  g_Bb);
    cudaGetSymbolAddress((void**)&Cm,  g_Cm);
    cudaGetSymbolAddress((void**)&P0,  g_P0);
    cudaGetSymbolAddress((void**)&P1,  g_P1);

    static bool attr_set = false;
    if (!attr_set) {
        cudaFuncSetAttribute(gemm_mma,
                             cudaFuncAttributeMaxDynamicSharedMemorySize, 65536);
        attr_set = true;
    }

    const long long sM = (long long)DD * DD;   // 65536
    const long long sX = (long long)MM * DD;   // 131072
    const int SM = 65536;

    mean_kernel<<<NB, 256>>>(x);
    center_kernel<<<dim3(DD / 32, MM / 32, NB), dim3(32, 8)>>>(x);
    reduce_tr_kernel<<<NB, 128>>>();

    // sigma -> Ba = B0 = 1.5 I - 0.5 * (xn^T xn) / sumsq   [K = 512]
    gemm_mma<<<dim3(2, 2, NB), 256, SM>>>(Ba, xnT, xnT, nullptr,
                                          MM, MM, MM, sX, sX, sM, 0, 2);
    // iter 1: Cm = B0^2 ; Bb = Cm*B0 - 1.5Cm + 1.5I  (B1)
    gemm_mma<<<dim3(2, 2, NB), 256, SM>>>(Cm, Ba, Ba, nullptr,
                                          DD, DD, DD, sM, sM, sM, 0, 0);
    gemm_mma<<<dim3(2, 2, NB), 256, SM>>>(Bb, Cm, Ba, Cm,
                                          DD, DD, DD, sM, sM, sM, sM, 1);
    // iter 2: P0 = B0*B1 (P2) ; Cm = B1^2 ; Ba = Cm*B1 - 1.5Cm + 1.5I (B2)
    gemm_mma<<<dim3(2, 2, NB), 256, SM>>>(P0, Ba, Bb, nullptr,
                                          DD, DD, DD, sM, sM, sM, 0, 0);
    gemm_mma<<<dim3(2, 2, NB), 256, SM>>>(Cm, Bb, Bb, nullptr,
                                          DD, DD, DD, sM, sM, sM, 0, 0);
    gemm_mma<<<dim3(2, 2, NB), 256, SM>>>(Ba, Cm, Bb, Cm,
                                          DD, DD, DD, sM, sM, sM, sM, 1);
    // iter 3: P1 = P2*B2 (P3) ; Cm = B2^2 ; Bb = Cm*B2 - 1.5Cm + 1.5I (B3)
    gemm_mma<<<dim3(2, 2, NB), 256, SM>>>(P1, P0, Ba, nullptr,
                                          DD, DD, DD, sM, sM, sM, 0, 0);
    gemm_mma<<<dim3(2, 2, NB), 256, SM>>>(Cm, Ba, Ba, nullptr,
                                          DD, DD, DD, sM, sM, sM, 0, 0);
    gemm_mma<<<dim3(2, 2, NB), 256, SM>>>(Bb, Cm, Ba, Cm,
                                          DD, DD, DD, sM, sM, sM, sM, 1);
    // iter 4: P0 = P3*B3 (P4)
    gemm_mma<<<dim3(2, 2, NB), 256, SM>>>(P0, P1, Bb, nullptr,
                                          DD, DD, DD, sM, sM, sM, 0, 0);
    // final: out = xn * P4 * rsqrt(sumsq/(M-1))   [M = 512]
    gemm_mma<<<dim3(4, 2, NB), 256, SM>>>(out, xn, P0, nullptr,
                                          DD, DD, DD, sX, sM, sX, 0, 3);
}

// round 5
// speedup vs baseline: 2.8321x; 1.0835x over previous
#include <cuda_runtime.h>
#include <cstdint>
#include <cstddef>

#define NB   256
#define MM   512
#define DD   256

// ======================= scratch (device globals) ===========================
__device__ __align__(256) float g_mean[NB * DD];
__device__ __align__(256) float g_tr  [NB];           // sumsq = trace*(M-1)
__device__ __align__(256) float g_ssp [NB * 128];
__device__ __align__(256) float g_xn  [NB * MM * DD];
__device__ __align__(256) float g_xnT [NB * DD * MM];
__device__ __align__(256) float g_Ba  [NB * DD * DD];
__device__ __align__(256) float g_Bb  [NB * DD * DD];
__device__ __align__(256) float g_Cm  [NB * DD * DD];
__device__ __align__(256) float g_P0  [NB * DD * DD];
__device__ __align__(256) float g_P1  [NB * DD * DD];

// ======================= PTX helpers ========================================
__device__ __forceinline__ uint32_t smem_u32(const void* p) {
    uint32_t a;
    asm("{ .reg .u64 t; cvta.to.shared.u64 t, %1; cvt.u32.u64 %0, t; }"
        : "=r"(a) : "l"(p));
    return a;
}

#define CP_ASYNC16(dst_u32, src_gptr) \
    asm volatile("cp.async.cg.shared.global [%0], [%1], 16;" \
                 :: "r"(dst_u32), "l"(src_gptr) : "memory")
#define CP_COMMIT() asm volatile("cp.async.commit_group;" ::: "memory")
#define CP_WAIT1()  asm volatile("cp.async.wait_group 1;" ::: "memory")
#define CP_WAIT0()  asm volatile("cp.async.wait_group 0;" ::: "memory")

#define LDM_X4(r0, r1, r2, r3, addr) \
    asm volatile("ldmatrix.sync.aligned.m8n8.x4.shared.b16 {%0,%1,%2,%3}, [%4];" \
                 : "=r"(r0), "=r"(r1), "=r"(r2), "=r"(r3) : "r"(addr))

#define MMA_TF32(d, a, b0, b1) \
    asm volatile("mma.sync.aligned.m16n8k8.row.col.f32.tf32.tf32.f32 " \
                 "{%0,%1,%2,%3}, {%4,%5,%6,%7}, {%8,%9}, {%0,%1,%2,%3};" \
                 : "+f"((d)[0]), "+f"((d)[1]), "+f"((d)[2]), "+f"((d)[3]) \
                 : "r"((a)[0]), "r"((a)[1]), "r"((a)[2]), "r"((a)[3]),   \
                   "r"(b0), "r"(b1))

// lo residual of truncate-to-tf32
__device__ __forceinline__ uint32_t lo_part(uint32_t x) {
    float f = __uint_as_float(x);
    float h = __uint_as_float(x & 0xFFFFE000u);
    return __float_as_uint(f - h);
}

// ======================= mean over axis 1 ===================================
__global__ __launch_bounds__(256) void mean_kernel(const float* __restrict__ x) {
    int n = blockIdx.x, d = threadIdx.x;
    const float* xp = x + (size_t)n * MM * DD + d;
    float s0 = 0.f, s1 = 0.f, s2 = 0.f, s3 = 0.f;
    #pragma unroll 4
    for (int m = 0; m < MM; m += 4) {
        s0 += xp[(size_t)(m + 0) * DD];
        s1 += xp[(size_t)(m + 1) * DD];
        s2 += xp[(size_t)(m + 2) * DD];
        s3 += xp[(size_t)(m + 3) * DD];
    }
    g_mean[n * DD + d] = (s0 + s1 + s2 + s3) * (1.f / (float)MM);
}

// ============ center: xn = x - mean, xnT = transpose, sumsq partials ========
__global__ __launch_bounds__(256) void center_kernel(const float* __restrict__ x) {
    const int n  = blockIdx.z;
    const int d0 = blockIdx.x * 32;
    const int m0 = blockIdx.y * 32;
    const int tx = threadIdx.x, ty = threadIdx.y;   // block (32, 8)

    __shared__ float tile[32][33];
    __shared__ float red[256];

    const int d = d0 + tx;
    const float mu = g_mean[n * DD + d];
    float ss = 0.f;
    #pragma unroll
    for (int r = 0; r < 4; r++) {
        int m = m0 + ty + r * 8;
        float v = x[(size_t)n * MM * DD + (size_t)m * DD + d] - mu;
        g_xn[(size_t)n * MM * DD + (size_t)m * DD + d] = v;
        tile[ty + r * 8][tx] = v;
        ss += v * v;
    }
    __syncthreads();
    #pragma unroll
    for (int r = 0; r < 4; r++) {
        int dd_ = ty + r * 8;
        g_xnT[(size_t)n * DD * MM + (size_t)(d0 + dd_) * MM + m0 + tx] = tile[tx][dd_];
    }
    int t = ty * 32 + tx;
    red[t] = ss;
    __syncthreads();
    for (int s = 128; s > 0; s >>= 1) {
        if (t < s) red[t] += red[t + s];
        __syncthreads();
    }
    if (t == 0) g_ssp[n * 128 + blockIdx.y * 8 + blockIdx.x] = red[0];
}

__global__ __launch_bounds__(128) void reduce_tr_kernel() {
    int n = blockIdx.x, t = threadIdx.x;
    __shared__ float red[128];
    red[t] = g_ssp[n * 128 + t];
    __syncthreads();
    for (int s = 64; s > 0; s >>= 1) {
        if (t < s) red[t] += red[t + s];
        __syncthreads();
    }
    if (t == 0) g_tr[n] = red[0];
}

// ======================= tf32x3 mma.sync batched GEMM =======================
// D[m][n] = sum_k A[m][k] * B[n][k]   (B read K-major)
// mode: 0: C = acc
//       1: C = acc - 1.5*Dm + 1.5*I       (NS B-update; Dm = B^2, symmetric)
//       2: C = (-0.5/ts)*acc + 1.5*I      (sigma -> B0)
//       3: C = acc * rsqrt(ts/(M-1))      (final whitening scale)
// sym:  1 => output is symmetric 256x256; grid.x in {0,1,2} maps to tiles
//       (0,0),(0,1),(1,1); the (0,1) tile is mirrored to (1,0) through smem.
#define SOFF_A(s)  ((uint32_t)(s) * 32768u)
#define SOFF_B(s)  ((uint32_t)(s) * 32768u + 16384u)
#define SMEM_DYN   66048   // >= 2*32KB stages; >= 128*129*4 transpose staging

__global__ __launch_bounds__(256, 1) void gemm_mma(
    float* __restrict__ Cmat, const float* __restrict__ Amat,
    const float* __restrict__ Bmat, const float* __restrict__ Dmat,
    int lda, int ldb, int Ktot,
    long long sA, long long sB, long long sC, long long sD, int mode, int sym)
{
    extern __shared__ char smem[];
    const uint32_t sb = smem_u32(smem);

    const int tid  = threadIdx.x;
    const int wid  = tid >> 5, lane = tid & 31;
    const int wm   = wid & 1;          // 2 warp-rows (64 each)
    const int wn   = wid >> 1;         // 4 warp-cols (32 each)
    const int n    = blockIdx.z;

    int ti, tj;
    if (sym) { ti = (blockIdx.x == 2) ? 1 : 0; tj = (blockIdx.x != 0) ? 1 : 0; }
    else     { ti = blockIdx.x;                tj = blockIdx.y; }
    const int rb = ti * 128;
    const int cb = tj * 128;

    const float* An = Amat + (size_t)n * sA;
    const float* Bn = Bmat + (size_t)n * sB;
    float*       Cn = Cmat + (size_t)n * sC;

    // staging indices (4 x float4 per tile per thread)
    int srow[4], sch[4];
    uint32_t sdst[4];
    #pragma unroll
    for (int j = 0; j < 4; j++) {
        int idx = tid + 256 * j;
        srow[j] = idx >> 3;
        sch[j]  = idx & 7;
        sdst[j] = (uint32_t)(srow[j] * 128 + ((sch[j] ^ (srow[j] & 7)) << 4));
    }

    // ldmatrix lane geometry
    const int t  = lane >> 3, s7 = lane & 7;
    const int chA = t >> 1;
    const int rAl = wm * 64 + (t & 1) * 8 + s7;
    const int chB = t & 1;
    const int rBl = wn * 32 + (t >> 1) * 8 + s7;

    float acc[4][4][4];
    #pragma unroll
    for (int i = 0; i < 4; i++)
        #pragma unroll
        for (int j = 0; j < 4; j++)
            #pragma unroll
            for (int q = 0; q < 4; q++) acc[i][j][q] = 0.f;

    const int nch = Ktot >> 5;

    // prologue: stage chunk 0 into buffer 0
    {
        #pragma unroll
        for (int j = 0; j < 4; j++) {
            const float* s = An + (size_t)(rb + srow[j]) * lda + sch[j] * 4;
            CP_ASYNC16(sb + SOFF_A(0) + sdst[j], (const void*)s);
        }
        #pragma unroll
        for (int j = 0; j < 4; j++) {
            const float* s = Bn + (size_t)(cb + srow[j]) * ldb + sch[j] * 4;
            CP_ASYNC16(sb + SOFF_B(0) + sdst[j], (const void*)s);
        }
        CP_COMMIT();
    }

    for (int c = 0; c < nch; c++) {
        if (c + 1 < nch) {
            const int bs = (c + 1) & 1;
            const int k0 = (c + 1) * 32;
            #pragma unroll
            for (int j = 0; j < 4; j++) {
                const float* s = An + (size_t)(rb + srow[j]) * lda + k0 + sch[j] * 4;
                CP_ASYNC16(sb + SOFF_A(bs) + sdst[j], (const void*)s);
            }
            #pragma unroll
            for (int j = 0; j < 4; j++) {
                const float* s = Bn + (size_t)(cb + srow[j]) * ldb + k0 + sch[j] * 4;
                CP_ASYNC16(sb + SOFF_B(bs) + sdst[j], (const void*)s);
            }
            CP_COMMIT();
            CP_WAIT1();
        } else {
            CP_WAIT0();
        }
        __syncthreads();

        const uint32_t aB = sb + SOFF_A(c & 1);
        const uint32_t bB = sb + SOFF_B(c & 1);

        #pragma unroll
        for (int kk = 0; kk < 4; kk++) {
            uint32_t af[4][4], al[4][4];
            uint32_t bf[2][4], bl[2][4];
            #pragma unroll
            for (int mi = 0; mi < 4; mi++) {
                uint32_t addr = aB + (uint32_t)((rAl + mi * 16) * 128 +
                                (((kk << 1) + chA) ^ s7) * 16);
                LDM_X4(af[mi][0], af[mi][1], af[mi][2], af[mi][3], addr);
            }
            #pragma unroll
            for (int p = 0; p < 2; p++) {
                uint32_t addr = bB + (uint32_t)((rBl + p * 16) * 128 +
                                (((kk << 1) + chB) ^ s7) * 16);
                LDM_X4(bf[p][0], bf[p][1], bf[p][2], bf[p][3], addr);
            }
            #pragma unroll
            for (int mi = 0; mi < 4; mi++)
                #pragma unroll
                for (int q = 0; q < 4; q++) al[mi][q] = lo_part(af[mi][q]);
            #pragma unroll
            for (int p = 0; p < 2; p++)
                #pragma unroll
                for (int q = 0; q < 4; q++) bl[p][q] = lo_part(bf[p][q]);

            #pragma unroll
            for (int mi = 0; mi < 4; mi++) {
                #pragma unroll
                for (int p = 0; p < 2; p++) {
                    #pragma unroll
                    for (int q = 0; q < 2; q++) {
                        const int nj = p * 2 + q;
                        MMA_TF32(acc[mi][nj], af[mi], bf[p][2*q], bf[p][2*q+1]);
                        MMA_TF32(acc[mi][nj], af[mi], bl[p][2*q], bl[p][2*q+1]);
                        MMA_TF32(acc[mi][nj], al[mi], bf[p][2*q], bf[p][2*q+1]);
                    }
                }
            }
        }
        __syncthreads();
    }

    // ---------------- epilogue ----------------
    const int g = lane >> 2, tig = lane & 3;
    float ts = 0.f;
    if (mode >= 2) ts = g_tr[n];
    const float sc2 = (mode == 2) ? (-0.5f / ts) : 0.f;
    const float sc3 = (mode == 3) ? rsqrtf(ts / (float)(MM - 1)) : 0.f;
    const float* Dn = Dmat ? (Dmat + (size_t)n * sD) : nullptr;

    const bool do_t = sym && (rb != cb);
    float* stg = reinterpret_cast<float*>(smem);   // reuse stages: 128x129 f32

    #pragma unroll
    for (int mi = 0; mi < 4; mi++) {
        #pragma unroll
        for (int nj = 0; nj < 4; nj++) {
            const int cl = wn * 32 + nj * 8 + 2 * tig;     // tile-local col
            const int col = cb + cl;
            #pragma unroll
            for (int h = 0; h < 2; h++) {
                const int rl = wm * 64 + mi * 16 + g + 8 * h;  // tile-local row
                const int row = rb + rl;
                float v0 = acc[mi][nj][2 * h];
                float v1 = acc[mi][nj][2 * h + 1];
                if (mode == 1) {
                    const float2 d = *reinterpret_cast<const float2*>(
                        Dn + (size_t)row * DD + col);
                    v0 -= 1.5f * d.x;
                    v1 -= 1.5f * d.y;
                    if (row == col)     v0 += 1.5f;
                    if (row == col + 1) v1 += 1.5f;
                } else if (mode == 2) {
                    v0 *= sc2; v1 *= sc2;
                    if (row == col)     v0 += 1.5f;
                    if (row == col + 1) v1 += 1.5f;
                } else if (mode == 3) {
                    v0 *= sc3; v1 *= sc3;
                }
                *reinterpret_cast<float2*>(Cn + (size_t)row * DD + col) =
                    make_float2(v0, v1);
                if (do_t) {
                    stg[rl * 129 + cl]     = v0;
                    stg[rl * 129 + cl + 1] = v1;
                }
            }
        }
    }

    // mirrored tile: C[cb..][rb..] = (this tile)^T, coalesced via smem
    if (do_t) {
        __syncthreads();
        const int r2    = tid >> 1;            // row of transposed tile
        const int cbase = (tid & 1) * 64;      // 2 threads per row, 64 cols each
        float* orow = Cn + (size_t)(cb + r2) * DD + rb + cbase;
        #pragma unroll
        for (int q = 0; q < 16; q++) {
            float4 vv;
            vv.x = stg[(cbase + q * 4 + 0) * 129 + r2];
            vv.y = stg[(cbase + q * 4 + 1) * 129 + r2];
            vv.z = stg[(cbase + q * 4 + 2) * 129 + r2];
            vv.w = stg[(cbase + q * 4 + 3) * 129 + r2];
            *reinterpret_cast<float4*>(orow + q * 4) = vv;
        }
    }
}

// ======================= host launcher ======================================
extern "C" void kernel_launch(void* const* d_in, const int* in_sizes, int n_in,
                              void* d_out, int out_size) {
    const float* x = (const float*)d_in[0];
    float* out = (float*)d_out;

    float *xn, *xnT, *Ba, *Bb, *Cm, *P0, *P1;
    cudaGetSymbolAddress((void**)&xn,  g_xn);
    cudaGetSymbolAddress((void**)&xnT, g_xnT);
    cudaGetSymbolAddress((void**)&Ba,  g_Ba);
    cudaGetSymbolAddress((void**)&Bb,  g_Bb);
    cudaGetSymbolAddress((void**)&Cm,  g_Cm);
    cudaGetSymbolAddress((void**)&P0,  g_P0);
    cudaGetSymbolAddress((void**)&P1,  g_P1);

    cudaFuncSetAttribute(gemm_mma,
                         cudaFuncAttributeMaxDynamicSharedMemorySize, SMEM_DYN);

    const long long sM = (long long)DD * DD;   // 65536
    const long long sX = (long long)MM * DD;   // 131072
    const dim3 gSym(3, 1, NB);                 // symmetric-output launches

    mean_kernel<<<NB, 256>>>(x);
    center_kernel<<<dim3(DD / 32, MM / 32, NB), dim3(32, 8)>>>(x);
    reduce_tr_kernel<<<NB, 128>>>();

    // sigma -> Ba = B0 = 1.5 I - 0.5 * (xn^T xn) / sumsq   [K = 512, symmetric]
    gemm_mma<<<gSym, 256, SMEM_DYN>>>(Ba, xnT, xnT, nullptr,
                                      MM, MM, MM, sX, sX, sM, 0, 2, 1);
    // iter 1: Cm = B0^2 ; Bb = Cm*B0 - 1.5Cm + 1.5I  (B1)
    gemm_mma<<<gSym, 256, SMEM_DYN>>>(Cm, Ba, Ba, nullptr,
                                      DD, DD, DD, sM, sM, sM, 0, 0, 1);
    gemm_mma<<<gSym, 256, SMEM_DYN>>>(Bb, Cm, Ba, Cm,
                                      DD, DD, DD, sM, sM, sM, sM, 1, 1);
    // iter 2: P0 = B0*B1 (P2) ; Cm = B1^2 ; Ba = Cm*B1 - 1.5Cm + 1.5I (B2)
    gemm_mma<<<gSym, 256, SMEM_DYN>>>(P0, Ba, Bb, nullptr,
                                      DD, DD, DD, sM, sM, sM, 0, 0, 1);
    gemm_mma<<<gSym, 256, SMEM_DYN>>>(Cm, Bb, Bb, nullptr,
                                      DD, DD, DD, sM, sM, sM, 0, 0, 1);
    gemm_mma<<<gSym, 256, SMEM_DYN>>>(Ba, Cm, Bb, Cm,
                                      DD, DD, DD, sM, sM, sM, sM, 1, 1);
    // iter 3: P1 = P2*B2 (P3) ; Cm = B2^2 ; Bb = Cm*B2 - 1.5Cm + 1.5I (B3)
    gemm_mma<<<gSym, 256, SMEM_DYN>>>(P1, P0, Ba, nullptr,
                                      DD, DD, DD, sM, sM, sM, 0, 0, 1);
    gemm_mma<<<gSym, 256, SMEM_DYN>>>(Cm, Ba, Ba, nullptr,
                                      DD, DD, DD, sM, sM, sM, 0, 0, 1);
    gemm_mma<<<gSym, 256, SMEM_DYN>>>(Bb, Cm, Ba, Cm,
                                      DD, DD, DD, sM, sM, sM, sM, 1, 1);
    // iter 4: P0 = P3*B3 (P4)
    gemm_mma<<<gSym, 256, SMEM_DYN>>>(P0, P1, Bb, nullptr,
                                      DD, DD, DD, sM, sM, sM, 0, 0, 1);
    // final: out = xn * P4 * rsqrt(sumsq/(M-1))   [M = 512, not symmetric]
    gemm_mma<<<dim3(4, 2, NB), 256, SMEM_DYN>>>(out, xn, P0, nullptr,
                                                DD, DD, DD, sX, sM, sX, 0, 3, 0);
}

// round 6
// speedup vs baseline: 3.2110x; 1.1338x over previous
#include <cuda_runtime.h>
#include <cstdint>
#include <cstddef>

#define NB   256
#define MM   512
#define DD   256

// ======================= scratch (device globals) ===========================
__device__ __align__(256) float g_mean[NB * DD];
__device__ __align__(256) float g_tr  [NB];           // sumsq = trace*(M-1)
__device__ __align__(256) float g_ssp [NB * 128];
__device__ __align__(256) float g_xn  [NB * MM * DD];
__device__ __align__(256) float g_xnT [NB * DD * MM];
__device__ __align__(256) float g_Ba  [NB * DD * DD];
__device__ __align__(256) float g_Bb  [NB * DD * DD];
__device__ __align__(256) float g_Cm  [NB * DD * DD];
__device__ __align__(256) float g_P0  [NB * DD * DD];
__device__ __align__(256) float g_P1  [NB * DD * DD];

// ======================= PTX helpers ========================================
__device__ __forceinline__ uint32_t smem_u32(const void* p) {
    uint32_t a;
    asm("{ .reg .u64 t; cvta.to.shared.u64 t, %1; cvt.u32.u64 %0, t; }"
        : "=r"(a) : "l"(p));
    return a;
}

#define CP_ASYNC16(dst_u32, src_gptr) \
    asm volatile("cp.async.cg.shared.global [%0], [%1], 16;" \
                 :: "r"(dst_u32), "l"(src_gptr) : "memory")
#define CP_COMMIT() asm volatile("cp.async.commit_group;" ::: "memory")
#define CP_WAIT1()  asm volatile("cp.async.wait_group 1;" ::: "memory")
#define CP_WAIT0()  asm volatile("cp.async.wait_group 0;" ::: "memory")

#define LDM_X4(r0, r1, r2, r3, addr) \
    asm volatile("ldmatrix.sync.aligned.m8n8.x4.shared.b16 {%0,%1,%2,%3}, [%4];" \
                 : "=r"(r0), "=r"(r1), "=r"(r2), "=r"(r3) : "r"(addr))

#define MMA_TF32(d, a0, a1, a2, a3, b0, b1) \
    asm volatile("mma.sync.aligned.m16n8k8.row.col.f32.tf32.tf32.f32 " \
                 "{%0,%1,%2,%3}, {%4,%5,%6,%7}, {%8,%9}, {%0,%1,%2,%3};" \
                 : "+f"((d)[0]), "+f"((d)[1]), "+f"((d)[2]), "+f"((d)[3]) \
                 : "r"(a0), "r"(a1), "r"(a2), "r"(a3), "r"(b0), "r"(b1))

// lo residual of truncate-to-tf32
__device__ __forceinline__ uint32_t lo_part(uint32_t x) {
    float f = __uint_as_float(x);
    float h = __uint_as_float(x & 0xFFFFE000u);
    return __float_as_uint(f - h);
}

// ======================= mean over axis 1 ===================================
__global__ __launch_bounds__(256) void mean_kernel(const float* __restrict__ x) {
    int n = blockIdx.x, d = threadIdx.x;
    const float* xp = x + (size_t)n * MM * DD + d;
    float s0 = 0.f, s1 = 0.f, s2 = 0.f, s3 = 0.f;
    #pragma unroll 4
    for (int m = 0; m < MM; m += 4) {
        s0 += xp[(size_t)(m + 0) * DD];
        s1 += xp[(size_t)(m + 1) * DD];
        s2 += xp[(size_t)(m + 2) * DD];
        s3 += xp[(size_t)(m + 3) * DD];
    }
    g_mean[n * DD + d] = (s0 + s1 + s2 + s3) * (1.f / (float)MM);
}

// ============ center: xn = x - mean, xnT = transpose, sumsq partials ========
__global__ __launch_bounds__(256) void center_kernel(const float* __restrict__ x) {
    const int n  = blockIdx.z;
    const int d0 = blockIdx.x * 32;
    const int m0 = blockIdx.y * 32;
    const int tx = threadIdx.x, ty = threadIdx.y;   // block (32, 8)

    __shared__ float tile[32][33];
    __shared__ float red[256];

    const int d = d0 + tx;
    const float mu = g_mean[n * DD + d];
    float ss = 0.f;
    #pragma unroll
    for (int r = 0; r < 4; r++) {
        int m = m0 + ty + r * 8;
        float v = x[(size_t)n * MM * DD + (size_t)m * DD + d] - mu;
        g_xn[(size_t)n * MM * DD + (size_t)m * DD + d] = v;
        tile[ty + r * 8][tx] = v;
        ss += v * v;
    }
    __syncthreads();
    #pragma unroll
    for (int r = 0; r < 4; r++) {
        int dd_ = ty + r * 8;
        g_xnT[(size_t)n * DD * MM + (size_t)(d0 + dd_) * MM + m0 + tx] = tile[tx][dd_];
    }
    int t = ty * 32 + tx;
    red[t] = ss;
    __syncthreads();
    for (int s = 128; s > 0; s >>= 1) {
        if (t < s) red[t] += red[t + s];
        __syncthreads();
    }
    if (t == 0) g_ssp[n * 128 + blockIdx.y * 8 + blockIdx.x] = red[0];
}

__global__ __launch_bounds__(128) void reduce_tr_kernel() {
    int n = blockIdx.x, t = threadIdx.x;
    __shared__ float red[128];
    red[t] = g_ssp[n * 128 + t];
    __syncthreads();
    for (int s = 64; s > 0; s >>= 1) {
        if (t < s) red[t] += red[t + s];
        __syncthreads();
    }
    if (t == 0) g_tr[n] = red[0];
}

// ======================= tf32x3 mma.sync batched GEMM =======================
// job0: C  = epi(A  * B^T-read)   job1 (optional): C2 = A2 * B^T-read (mode 0)
// mode: 0: C = acc
//       1: C = acc - 1.5*Dm + 1.5*I       (NS B-update; Dm = B^2, symmetric)
//       2: C = (-0.5/ts)*acc + 1.5*I      (sigma -> B0)
//       3: C = acc * rsqrt(ts/(M-1))      (final whitening scale)
// sym: outputs are symmetric 256x256; per-job tiles (0,0),(0,1),(1,1); the
//      (0,1) tile is mirrored to (1,0) through smem.
#define SOFF_A(s)  ((uint32_t)(s) * 32768u)
#define SOFF_B(s)  ((uint32_t)(s) * 32768u + 16384u)
#define SMEM_DYN   66048   // >= 2*32KB stages; >= 128*129*4 transpose staging

__global__ __launch_bounds__(256, 2) void gemm_mma(
    float* __restrict__ Cmat, const float* __restrict__ Amat,
    const float* __restrict__ Bmat, const float* __restrict__ Dmat,
    float* __restrict__ C2mat, const float* __restrict__ A2mat,
    int lda, int ldb, int Ktot,
    long long sA, long long sB, long long sC, long long sD, int mode, int sym)
{
    extern __shared__ char smem[];
    const uint32_t sb = smem_u32(smem);

    const int tid  = threadIdx.x;
    const int wid  = tid >> 5, lane = tid & 31;
    const int wm   = wid & 1;          // 2 warp-rows (64 each)
    const int wn   = wid >> 1;         // 4 warp-cols (32 each)
    const int n    = blockIdx.z;

    int ti, tj, job = 0, mymode = mode;
    if (sym) {
        int tt = blockIdx.x;
        if (tt >= 3) { job = 1; tt -= 3; mymode = 0; }
        ti = (tt == 2) ? 1 : 0; tj = (tt != 0) ? 1 : 0;
    } else {
        ti = blockIdx.x; tj = blockIdx.y;
    }
    const int rb = ti * 128;
    const int cb = tj * 128;

    const float* An = (job ? A2mat : Amat) + (size_t)n * sA;
    const float* Bn = Bmat + (size_t)n * sB;
    float*       Cn = (job ? C2mat : Cmat) + (size_t)n * sC;

    // staging indices (4 x float4 per tile per thread)
    int srow[4], sch[4];
    uint32_t sdst[4];
    #pragma unroll
    for (int j = 0; j < 4; j++) {
        int idx = tid + 256 * j;
        srow[j] = idx >> 3;
        sch[j]  = idx & 7;
        sdst[j] = (uint32_t)(srow[j] * 128 + ((sch[j] ^ (srow[j] & 7)) << 4));
    }

    // ldmatrix lane geometry
    const int t  = lane >> 3, s7 = lane & 7;
    const int chA = t >> 1;
    const int rAl = wm * 64 + (t & 1) * 8 + s7;
    const int chB = t & 1;
    const int rBl = wn * 32 + (t >> 1) * 8 + s7;

    float acc[4][4][4];
    #pragma unroll
    for (int i = 0; i < 4; i++)
        #pragma unroll
        for (int j = 0; j < 4; j++)
            #pragma unroll
            for (int q = 0; q < 4; q++) acc[i][j][q] = 0.f;

    const int nch = Ktot >> 5;

    // prologue: stage chunk 0 into buffer 0
    {
        #pragma unroll
        for (int j = 0; j < 4; j++) {
            const float* s = An + (size_t)(rb + srow[j]) * lda + sch[j] * 4;
            CP_ASYNC16(sb + SOFF_A(0) + sdst[j], (const void*)s);
        }
        #pragma unroll
        for (int j = 0; j < 4; j++) {
            const float* s = Bn + (size_t)(cb + srow[j]) * ldb + sch[j] * 4;
            CP_ASYNC16(sb + SOFF_B(0) + sdst[j], (const void*)s);
        }
        CP_COMMIT();
    }

    for (int c = 0; c < nch; c++) {
        if (c + 1 < nch) {
            const int bs = (c + 1) & 1;
            const int k0 = (c + 1) * 32;
            #pragma unroll
            for (int j = 0; j < 4; j++) {
                const float* s = An + (size_t)(rb + srow[j]) * lda + k0 + sch[j] * 4;
                CP_ASYNC16(sb + SOFF_A(bs) + sdst[j], (const void*)s);
            }
            #pragma unroll
            for (int j = 0; j < 4; j++) {
                const float* s = Bn + (size_t)(cb + srow[j]) * ldb + k0 + sch[j] * 4;
                CP_ASYNC16(sb + SOFF_B(bs) + sdst[j], (const void*)s);
            }
            CP_COMMIT();
            CP_WAIT1();
        } else {
            CP_WAIT0();
        }
        __syncthreads();

        const uint32_t aB = sb + SOFF_A(c & 1);
        const uint32_t bB = sb + SOFF_B(c & 1);

        #pragma unroll
        for (int kk = 0; kk < 4; kk++) {
            uint32_t af[4][4];
            uint32_t bf[2][4];
            #pragma unroll
            for (int mi = 0; mi < 4; mi++) {
                uint32_t addr = aB + (uint32_t)((rAl + mi * 16) * 128 +
                                (((kk << 1) + chA) ^ s7) * 16);
                LDM_X4(af[mi][0], af[mi][1], af[mi][2], af[mi][3], addr);
            }
            #pragma unroll
            for (int p = 0; p < 2; p++) {
                uint32_t addr = bB + (uint32_t)((rBl + p * 16) * 128 +
                                (((kk << 1) + chB) ^ s7) * 16);
                LDM_X4(bf[p][0], bf[p][1], bf[p][2], bf[p][3], addr);
            }

            // pass 1+2 per mi: Ah*Bh, then Al*Bh (al computed and retired here)
            #pragma unroll
            for (int mi = 0; mi < 4; mi++) {
                #pragma unroll
                for (int p = 0; p < 2; p++) {
                    MMA_TF32(acc[mi][p*2+0], af[mi][0], af[mi][1], af[mi][2],
                             af[mi][3], bf[p][0], bf[p][1]);
                    MMA_TF32(acc[mi][p*2+1], af[mi][0], af[mi][1], af[mi][2],
                             af[mi][3], bf[p][2], bf[p][3]);
                }
                uint32_t a0 = lo_part(af[mi][0]), a1 = lo_part(af[mi][1]);
                uint32_t a2 = lo_part(af[mi][2]), a3 = lo_part(af[mi][3]);
                #pragma unroll
                for (int p = 0; p < 2; p++) {
                    MMA_TF32(acc[mi][p*2+0], a0, a1, a2, a3, bf[p][0], bf[p][1]);
                    MMA_TF32(acc[mi][p*2+1], a0, a1, a2, a3, bf[p][2], bf[p][3]);
                }
            }
            // pass 3: Ah*Bl (bl computed in-place over bf, then dead)
            #pragma unroll
            for (int p = 0; p < 2; p++)
                #pragma unroll
                for (int q = 0; q < 4; q++) bf[p][q] = lo_part(bf[p][q]);
            #pragma unroll
            for (int mi = 0; mi < 4; mi++)
                #pragma unroll
                for (int p = 0; p < 2; p++) {
                    MMA_TF32(acc[mi][p*2+0], af[mi][0], af[mi][1], af[mi][2],
                             af[mi][3], bf[p][0], bf[p][1]);
                    MMA_TF32(acc[mi][p*2+1], af[mi][0], af[mi][1], af[mi][2],
                             af[mi][3], bf[p][2], bf[p][3]);
                }
        }
        __syncthreads();
    }

    // ---------------- epilogue ----------------
    const int g = lane >> 2, tig = lane & 3;
    float ts = 0.f;
    if (mymode >= 2) ts = g_tr[n];
    const float sc2 = (mymode == 2) ? (-0.5f / ts) : 0.f;
    const float sc3 = (mymode == 3) ? rsqrtf(ts / (float)(MM - 1)) : 0.f;
    const float* Dn = Dmat ? (Dmat + (size_t)n * sD) : nullptr;

    const bool do_t = sym && (rb != cb);
    float* stg = reinterpret_cast<float*>(smem);   // reuse stages: 128x129 f32

    #pragma unroll
    for (int mi = 0; mi < 4; mi++) {
        #pragma unroll
        for (int nj = 0; nj < 4; nj++) {
            const int cl = wn * 32 + nj * 8 + 2 * tig;     // tile-local col
            const int col = cb + cl;
            #pragma unroll
            for (int h = 0; h < 2; h++) {
                const int rl = wm * 64 + mi * 16 + g + 8 * h;  // tile-local row
                const int row = rb + rl;
                float v0 = acc[mi][nj][2 * h];
                float v1 = acc[mi][nj][2 * h + 1];
                if (mymode == 1) {
                    const float2 d = *reinterpret_cast<const float2*>(
                        Dn + (size_t)row * DD + col);
                    v0 -= 1.5f * d.x;
                    v1 -= 1.5f * d.y;
                    if (row == col)     v0 += 1.5f;
                    if (row == col + 1) v1 += 1.5f;
                } else if (mymode == 2) {
                    v0 *= sc2; v1 *= sc2;
                    if (row == col)     v0 += 1.5f;
                    if (row == col + 1) v1 += 1.5f;
                } else if (mymode == 3) {
                    v0 *= sc3; v1 *= sc3;
                }
                *reinterpret_cast<float2*>(Cn + (size_t)row * DD + col) =
                    make_float2(v0, v1);
                if (do_t) {
                    stg[rl * 129 + cl]     = v0;
                    stg[rl * 129 + cl + 1] = v1;
                }
            }
        }
    }

    // mirrored tile: C[cb..][rb..] = (this tile)^T, coalesced via smem
    if (do_t) {
        __syncthreads();
        const int r2    = tid >> 1;            // row of transposed tile
        const int cbase = (tid & 1) * 64;      // 2 threads per row, 64 cols each
        float* orow = Cn + (size_t)(cb + r2) * DD + rb + cbase;
        #pragma unroll
        for (int q = 0; q < 16; q++) {
            float4 vv;
            vv.x = stg[(cbase + q * 4 + 0) * 129 + r2];
            vv.y = stg[(cbase + q * 4 + 1) * 129 + r2];
            vv.z = stg[(cbase + q * 4 + 2) * 129 + r2];
            vv.w = stg[(cbase + q * 4 + 3) * 129 + r2];
            *reinterpret_cast<float4*>(orow + q * 4) = vv;
        }
    }
}

// ======================= host launcher ======================================
extern "C" void kernel_launch(void* const* d_in, const int* in_sizes, int n_in,
                              void* d_out, int out_size) {
    const float* x = (const float*)d_in[0];
    float* out = (float*)d_out;

    float *xn, *xnT, *Ba, *Bb, *Cm, *P0, *P1;
    cudaGetSymbolAddress((void**)&xn,  g_xn);
    cudaGetSymbolAddress((void**)&xnT, g_xnT);
    cudaGetSymbolAddress((void**)&Ba,  g_Ba);
    cudaGetSymbolAddress((void**)&Bb,  g_Bb);
    cudaGetSymbolAddress((void**)&Cm,  g_Cm);
    cudaGetSymbolAddress((void**)&P0,  g_P0);
    cudaGetSymbolAddress((void**)&P1,  g_P1);

    cudaFuncSetAttribute(gemm_mma,
                         cudaFuncAttributeMaxDynamicSharedMemorySize, SMEM_DYN);

    const long long sM = (long long)DD * DD;   // 65536
    const long long sX = (long long)MM * DD;   // 131072
    const dim3 gSym(3, 1, NB);                 // symmetric, single job
    const dim3 gSym2(6, 1, NB);                // symmetric, two jobs

    mean_kernel<<<NB, 256>>>(x);
    center_kernel<<<dim3(DD / 32, MM / 32, NB), dim3(32, 8)>>>(x);
    reduce_tr_kernel<<<NB, 128>>>();

    // sigma -> Ba = B0 = 1.5 I - 0.5 * (xn^T xn) / sumsq   [K = 512, symmetric]
    gemm_mma<<<gSym, 256, SMEM_DYN>>>(Ba, xnT, xnT, nullptr, nullptr, nullptr,
                                      MM, MM, MM, sX, sX, sM, 0, 2, 1);
    // iter 1: Cm = B0^2 ; then Bb = Cm*B0 - 1.5Cm + 1.5I  (B1)  [P1 = B0]
    gemm_mma<<<gSym, 256, SMEM_DYN>>>(Cm, Ba, Ba, nullptr, nullptr, nullptr,
                                      DD, DD, DD, sM, sM, sM, 0, 0, 1);
    gemm_mma<<<gSym, 256, SMEM_DYN>>>(Bb, Cm, Ba, Cm, nullptr, nullptr,
                                      DD, DD, DD, sM, sM, sM, sM, 1, 1);
    // iter 2: {Cm = B1^2 , P0 = B0*B1 (P2)} ; Ba = Cm*B1 - 1.5Cm + 1.5I (B2)
    gemm_mma<<<gSym2, 256, SMEM_DYN>>>(Cm, Bb, Bb, nullptr, P0, Ba,
                                       DD, DD, DD, sM, sM, sM, 0, 0, 1);
    gemm_mma<<<gSym, 256, SMEM_DYN>>>(Ba, Cm, Bb, Cm, nullptr, nullptr,
                                      DD, DD, DD, sM, sM, sM, sM, 1, 1);
    // iter 3: {Cm = B2^2 , P1 = P2*B2 (P3)} ; Bb = Cm*B2 - 1.5Cm + 1.5I (B3)
    gemm_mma<<<gSym2, 256, SMEM_DYN>>>(Cm, Ba, Ba, nullptr, P1, P0,
                                       DD, DD, DD, sM, sM, sM, 0, 0, 1);
    gemm_mma<<<gSym, 256, SMEM_DYN>>>(Bb, Cm, Ba, Cm, nullptr, nullptr,
                                      DD, DD, DD, sM, sM, sM, sM, 1, 1);
    // iter 4: P0 = P3*B3 (P4)
    gemm_mma<<<gSym, 256, SMEM_DYN>>>(P0, P1, Bb, nullptr, nullptr, nullptr,
                                      DD, DD, DD, sM, sM, sM, 0, 0, 1);
    // final: out = xn * P4 * rsqrt(sumsq/(M-1))   [M = 512, not symmetric]
    gemm_mma<<<dim3(4, 2, NB), 256, SMEM_DYN>>>(out, xn, P0, nullptr, nullptr,
                                                nullptr, DD, DD, DD,
                                                sX, sM, sX, 0, 3, 0);
}

// round 7
// speedup vs baseline: 3.5480x; 1.1049x over previous
#include <cuda_runtime.h>
#include <cstdint>
#include <cstddef>

#define NB   256
#define MM   512
#define DD   256

// ======================= scratch (device globals) ===========================
__device__ __align__(256) float g_mean[NB * DD];
__device__ __align__(256) float g_tr  [NB];           // sumsq = trace*(M-1)
__device__ __align__(256) float g_ssp [NB * 128];
__device__ __align__(256) float g_xn  [NB * MM * DD];
__device__ __align__(256) float g_xnT [NB * DD * MM];
__device__ __align__(256) float g_Ba  [NB * DD * DD];
__device__ __align__(256) float g_Bb  [NB * DD * DD];
__device__ __align__(256) float g_Cm  [NB * DD * DD];
__device__ __align__(256) float g_P0  [NB * DD * DD];
__device__ __align__(256) float g_P1  [NB * DD * DD];

// ======================= PTX helpers ========================================
__device__ __forceinline__ uint32_t smem_u32(const void* p) {
    uint32_t a;
    asm("{ .reg .u64 t; cvta.to.shared.u64 t, %1; cvt.u32.u64 %0, t; }"
        : "=r"(a) : "l"(p));
    return a;
}

#define CP_ASYNC16(dst_u32, src_gptr) \
    asm volatile("cp.async.cg.shared.global [%0], [%1], 16;" \
                 :: "r"(dst_u32), "l"(src_gptr) : "memory")
#define CP_COMMIT() asm volatile("cp.async.commit_group;" ::: "memory")
#define CP_WAIT1()  asm volatile("cp.async.wait_group 1;" ::: "memory")
#define CP_WAIT0()  asm volatile("cp.async.wait_group 0;" ::: "memory")

#define LDM_X4(r0, r1, r2, r3, addr) \
    asm volatile("ldmatrix.sync.aligned.m8n8.x4.shared.b16 {%0,%1,%2,%3}, [%4];" \
                 : "=r"(r0), "=r"(r1), "=r"(r2), "=r"(r3) : "r"(addr))

#define MMA_TF32(d, a0, a1, a2, a3, b0, b1) \
    asm volatile("mma.sync.aligned.m16n8k8.row.col.f32.tf32.tf32.f32 " \
                 "{%0,%1,%2,%3}, {%4,%5,%6,%7}, {%8,%9}, {%0,%1,%2,%3};" \
                 : "+f"((d)[0]), "+f"((d)[1]), "+f"((d)[2]), "+f"((d)[3]) \
                 : "r"(a0), "r"(a1), "r"(a2), "r"(a3), "r"(b0), "r"(b1))

// lo residual of truncate-to-tf32
__device__ __forceinline__ uint32_t lo_part(uint32_t x) {
    float f = __uint_as_float(x);
    float h = __uint_as_float(x & 0xFFFFE000u);
    return __float_as_uint(f - h);
}
__device__ __forceinline__ uint32_t half_f(uint32_t x) {
    return __float_as_uint(__uint_as_float(x) * 0.5f);
}

// ======================= mean over axis 1 ===================================
__global__ __launch_bounds__(256) void mean_kernel(const float* __restrict__ x) {
    int n = blockIdx.x, d = threadIdx.x;
    const float* xp = x + (size_t)n * MM * DD + d;
    float s0 = 0.f, s1 = 0.f, s2 = 0.f, s3 = 0.f;
    #pragma unroll 4
    for (int m = 0; m < MM; m += 4) {
        s0 += xp[(size_t)(m + 0) * DD];
        s1 += xp[(size_t)(m + 1) * DD];
        s2 += xp[(size_t)(m + 2) * DD];
        s3 += xp[(size_t)(m + 3) * DD];
    }
    g_mean[n * DD + d] = (s0 + s1 + s2 + s3) * (1.f / (float)MM);
}

// ============ center: xn = x - mean, xnT = transpose, sumsq partials ========
__global__ __launch_bounds__(256) void center_kernel(const float* __restrict__ x) {
    const int n  = blockIdx.z;
    const int d0 = blockIdx.x * 32;
    const int m0 = blockIdx.y * 32;
    const int tx = threadIdx.x, ty = threadIdx.y;   // block (32, 8)

    __shared__ float tile[32][33];
    __shared__ float red[256];

    const int d = d0 + tx;
    const float mu = g_mean[n * DD + d];
    float ss = 0.f;
    #pragma unroll
    for (int r = 0; r < 4; r++) {
        int m = m0 + ty + r * 8;
        float v = x[(size_t)n * MM * DD + (size_t)m * DD + d] - mu;
        g_xn[(size_t)n * MM * DD + (size_t)m * DD + d] = v;
        tile[ty + r * 8][tx] = v;
        ss += v * v;
    }
    __syncthreads();
    #pragma unroll
    for (int r = 0; r < 4; r++) {
        int dd_ = ty + r * 8;
        g_xnT[(size_t)n * DD * MM + (size_t)(d0 + dd_) * MM + m0 + tx] = tile[tx][dd_];
    }
    int t = ty * 32 + tx;
    red[t] = ss;
    __syncthreads();
    for (int s = 128; s > 0; s >>= 1) {
        if (t < s) red[t] += red[t + s];
        __syncthreads();
    }
    if (t == 0) g_ssp[n * 128 + blockIdx.y * 8 + blockIdx.x] = red[0];
}

__global__ __launch_bounds__(128) void reduce_tr_kernel() {
    int n = blockIdx.x, t = threadIdx.x;
    __shared__ float red[128];
    red[t] = g_ssp[n * 128 + t];
    __syncthreads();
    for (int s = 64; s > 0; s >>= 1) {
        if (t < s) red[t] += red[t + s];
        __syncthreads();
    }
    if (t == 0) g_tr[n] = red[0];
}

// ======================= tf32x3 mma.sync batched GEMM =======================
// job0: C  = epi(A  * B^T-read)   job1 (optional): C2 = A2 * B^T-read (mode 0)
// mode: 0: C = acc
//       1: C = acc - 1.5*Dm + 1.5*I       (NS B-update; Dm = B^2, symmetric)
//       2: C = (-0.5/ts)*acc + 1.5*I      (sigma -> B0)
//       3: C = acc * rsqrt(ts/(M-1))      (final whitening scale)
// sym: symmetric 256x256 outputs; per-job tiles (0,0),(0,1),(1,1); (0,1)
//      mirrored to (1,0) through smem.
// sqr: squaring launch (A==B, job0): diagonal tiles use the 2-pass trick
//      acc = 0.5*AhBh + AhBl ; C = acc + acc^T  (exact tf32x3 algebra).
// pass3: 0 => drop the Al*Bh pass (2-pass tf32; only for unamplified outputs)
#define SOFF_A(s)  ((uint32_t)(s) * 32768u)
#define SOFF_B(s)  ((uint32_t)(s) * 32768u + 16384u)
#define SMEM_DYN   98304   // 3 x 32KB stages; >= 128*129*4 transpose staging

__global__ __launch_bounds__(256, 2) void gemm_mma(
    float* __restrict__ Cmat, const float* __restrict__ Amat,
    const float* __restrict__ Bmat, const float* __restrict__ Dmat,
    float* __restrict__ C2mat, const float* __restrict__ A2mat,
    int lda, int ldb, int Ktot,
    long long sA, long long sB, long long sC, long long sD,
    int mode, int sym, int sqr, int pass3)
{
    extern __shared__ char smem[];
    const uint32_t sb = smem_u32(smem);

    const int tid  = threadIdx.x;
    const int wid  = tid >> 5, lane = tid & 31;
    const int wm   = wid & 1;          // 2 warp-rows (64 each)
    const int wn   = wid >> 1;         // 4 warp-cols (32 each)
    const int n    = blockIdx.z;

    int ti, tj, job = 0, mymode = mode;
    if (sym) {
        int tt = blockIdx.x;
        if (tt >= 3) { job = 1; tt -= 3; mymode = 0; }
        ti = (tt == 2) ? 1 : 0; tj = (tt != 0) ? 1 : 0;
    } else {
        ti = blockIdx.x; tj = blockIdx.y;
    }
    const int rb = ti * 128;
    const int cb = tj * 128;

    const bool do_diag = sqr && sym && (job == 0) && (ti == tj);
    const bool do_p3   = (pass3 != 0);

    const float* An = (job ? A2mat : Amat) + (size_t)n * sA;
    const float* Bn = Bmat + (size_t)n * sB;
    float*       Cn = (job ? C2mat : Cmat) + (size_t)n * sC;

    // staging indices (4 x float4 per tile per thread)
    int srow[4], sch[4];
    uint32_t sdst[4];
    #pragma unroll
    for (int j = 0; j < 4; j++) {
        int idx = tid + 256 * j;
        srow[j] = idx >> 3;
        sch[j]  = idx & 7;
        sdst[j] = (uint32_t)(srow[j] * 128 + ((sch[j] ^ (srow[j] & 7)) << 4));
    }

    // ldmatrix lane geometry
    const int t  = lane >> 3, s7 = lane & 7;
    const int chA = t >> 1;
    const int rAl = wm * 64 + (t & 1) * 8 + s7;
    const int chB = t & 1;
    const int rBl = wn * 32 + (t >> 1) * 8 + s7;

    float acc[4][4][4];
    #pragma unroll
    for (int i = 0; i < 4; i++)
        #pragma unroll
        for (int j = 0; j < 4; j++)
            #pragma unroll
            for (int q = 0; q < 4; q++) acc[i][j][q] = 0.f;

    const int nch = Ktot >> 5;

    // prologue: stage chunks 0,1 into buffers 0,1 (3-stage pipeline)
    #pragma unroll
    for (int pc = 0; pc < 2; pc++) {
        const int k0 = pc * 32;
        #pragma unroll
        for (int j = 0; j < 4; j++) {
            const float* s = An + (size_t)(rb + srow[j]) * lda + k0 + sch[j] * 4;
            CP_ASYNC16(sb + SOFF_A(pc) + sdst[j], (const void*)s);
        }
        #pragma unroll
        for (int j = 0; j < 4; j++) {
            const float* s = Bn + (size_t)(cb + srow[j]) * ldb + k0 + sch[j] * 4;
            CP_ASYNC16(sb + SOFF_B(pc) + sdst[j], (const void*)s);
        }
        CP_COMMIT();
    }

    for (int c = 0; c < nch; c++) {
        if (c + 1 < nch) CP_WAIT1(); else CP_WAIT0();
        __syncthreads();   // chunk c visible to all; buffer (c+2)%3 reusable

        if (c + 2 < nch) {
            const int bs = (c + 2) % 3;
            const int k0 = (c + 2) * 32;
            #pragma unroll
            for (int j = 0; j < 4; j++) {
                const float* s = An + (size_t)(rb + srow[j]) * lda + k0 + sch[j] * 4;
                CP_ASYNC16(sb + SOFF_A(bs) + sdst[j], (const void*)s);
            }
            #pragma unroll
            for (int j = 0; j < 4; j++) {
                const float* s = Bn + (size_t)(cb + srow[j]) * ldb + k0 + sch[j] * 4;
                CP_ASYNC16(sb + SOFF_B(bs) + sdst[j], (const void*)s);
            }
            CP_COMMIT();
        }

        const uint32_t aB = sb + SOFF_A(c % 3);
        const uint32_t bB = sb + SOFF_B(c % 3);

        #pragma unroll
        for (int kk = 0; kk < 4; kk++) {
            uint32_t af[4][4];
            uint32_t bf[2][4];
            #pragma unroll
            for (int mi = 0; mi < 4; mi++) {
                uint32_t addr = aB + (uint32_t)((rAl + mi * 16) * 128 +
                                (((kk << 1) + chA) ^ s7) * 16);
                LDM_X4(af[mi][0], af[mi][1], af[mi][2], af[mi][3], addr);
            }
            #pragma unroll
            for (int p = 0; p < 2; p++) {
                uint32_t addr = bB + (uint32_t)((rBl + p * 16) * 128 +
                                (((kk << 1) + chB) ^ s7) * 16);
                LDM_X4(bf[p][0], bf[p][1], bf[p][2], bf[p][3], addr);
            }

            if (do_diag) {
                // acc += Ah*(0.5*Bh) + Ah*Bl   (pass3 == pass2^T, added later)
                uint32_t bl[2][4];
                #pragma unroll
                for (int p = 0; p < 2; p++)
                    #pragma unroll
                    for (int q = 0; q < 4; q++) {
                        bl[p][q] = lo_part(bf[p][q]);
                        bf[p][q] = half_f(bf[p][q]);
                    }
                #pragma unroll
                for (int mi = 0; mi < 4; mi++)
                    #pragma unroll
                    for (int p = 0; p < 2; p++) {
                        MMA_TF32(acc[mi][p*2+0], af[mi][0], af[mi][1], af[mi][2],
                                 af[mi][3], bf[p][0], bf[p][1]);
                        MMA_TF32(acc[mi][p*2+1], af[mi][0], af[mi][1], af[mi][2],
                                 af[mi][3], bf[p][2], bf[p][3]);
                    }
                #pragma unroll
                for (int mi = 0; mi < 4; mi++)
                    #pragma unroll
                    for (int p = 0; p < 2; p++) {
                        MMA_TF32(acc[mi][p*2+0], af[mi][0], af[mi][1], af[mi][2],
                                 af[mi][3], bl[p][0], bl[p][1]);
                        MMA_TF32(acc[mi][p*2+1], af[mi][0], af[mi][1], af[mi][2],
                                 af[mi][3], bl[p][2], bl[p][3]);
                    }
            } else {
                // pass 1 (+ pass 2 Al*Bh if enabled), per mi
                #pragma unroll
                for (int mi = 0; mi < 4; mi++) {
                    #pragma unroll
                    for (int p = 0; p < 2; p++) {
                        MMA_TF32(acc[mi][p*2+0], af[mi][0], af[mi][1], af[mi][2],
                                 af[mi][3], bf[p][0], bf[p][1]);
                        MMA_TF32(acc[mi][p*2+1], af[mi][0], af[mi][1], af[mi][2],
                                 af[mi][3], bf[p][2], bf[p][3]);
                    }
                    if (do_p3) {
                        uint32_t a0 = lo_part(af[mi][0]), a1 = lo_part(af[mi][1]);
                        uint32_t a2 = lo_part(af[mi][2]), a3 = lo_part(af[mi][3]);
                        #pragma unroll
                        for (int p = 0; p < 2; p++) {
                            MMA_TF32(acc[mi][p*2+0], a0, a1, a2, a3,
                                     bf[p][0], bf[p][1]);
                            MMA_TF32(acc[mi][p*2+1], a0, a1, a2, a3,
                                     bf[p][2], bf[p][3]);
                        }
                    }
                }
                // pass 3: Ah*Bl (bl computed in-place over bf, then dead)
                #pragma unroll
                for (int p = 0; p < 2; p++)
                    #pragma unroll
                    for (int q = 0; q < 4; q++) bf[p][q] = lo_part(bf[p][q]);
                #pragma unroll
                for (int mi = 0; mi < 4; mi++)
                    #pragma unroll
                    for (int p = 0; p < 2; p++) {
                        MMA_TF32(acc[mi][p*2+0], af[mi][0], af[mi][1], af[mi][2],
                                 af[mi][3], bf[p][0], bf[p][1]);
                        MMA_TF32(acc[mi][p*2+1], af[mi][0], af[mi][1], af[mi][2],
                                 af[mi][3], bf[p][2], bf[p][3]);
                    }
            }
        }
    }
    __syncthreads();   // all MMA smem reads done before staging reuse

    // ---------------- epilogue ----------------
    const int g = lane >> 2, tig = lane & 3;
    float* stg = reinterpret_cast<float*>(smem);   // reuse stages: 128x129 f32

    // diagonal squaring tiles: C_raw = acc + acc^T
    if (do_diag) {
        #pragma unroll
        for (int mi = 0; mi < 4; mi++)
            #pragma unroll
            for (int nj = 0; nj < 4; nj++) {
                const int cl = wn * 32 + nj * 8 + 2 * tig;
                #pragma unroll
                for (int h = 0; h < 2; h++) {
                    const int rl = wm * 64 + mi * 16 + g + 8 * h;
                    stg[rl * 129 + cl]     = acc[mi][nj][2 * h];
                    stg[rl * 129 + cl + 1] = acc[mi][nj][2 * h + 1];
                }
            }
        __syncthreads();
        #pragma unroll
        for (int mi = 0; mi < 4; mi++)
            #pragma unroll
            for (int nj = 0; nj < 4; nj++) {
                const int cl = wn * 32 + nj * 8 + 2 * tig;
                #pragma unroll
                for (int h = 0; h < 2; h++) {
                    const int rl = wm * 64 + mi * 16 + g + 8 * h;
                    acc[mi][nj][2 * h]     += stg[cl * 129 + rl];
                    acc[mi][nj][2 * h + 1] += stg[(cl + 1) * 129 + rl];
                }
            }
    }

    float ts = 0.f;
    if (mymode >= 2) ts = g_tr[n];
    const float sc2 = (mymode == 2) ? (-0.5f / ts) : 0.f;
    const float sc3 = (mymode == 3) ? rsqrtf(ts / (float)(MM - 1)) : 0.f;
    const float* Dn = Dmat ? (Dmat + (size_t)n * sD) : nullptr;

    const bool do_t = sym && (rb != cb);
    if (do_t) __syncthreads();   // diag CTAs never mirror; reuse stg safely

    #pragma unroll
    for (int mi = 0; mi < 4; mi++) {
        #pragma unroll
        for (int nj = 0; nj < 4; nj++) {
            const int cl = wn * 32 + nj * 8 + 2 * tig;     // tile-local col
            const int col = cb + cl;
            #pragma unroll
            for (int h = 0; h < 2; h++) {
                const int rl = wm * 64 + mi * 16 + g + 8 * h;  // tile-local row
                const int row = rb + rl;
                float v0 = acc[mi][nj][2 * h];
                float v1 = acc[mi][nj][2 * h + 1];
                if (mymode == 1) {
                    const float2 d = *reinterpret_cast<const float2*>(
                        Dn + (size_t)row * DD + col);
                    v0 -= 1.5f * d.x;
                    v1 -= 1.5f * d.y;
                    if (row == col)     v0 += 1.5f;
                    if (row == col + 1) v1 += 1.5f;
                } else if (mymode == 2) {
                    v0 *= sc2; v1 *= sc2;
                    if (row == col)     v0 += 1.5f;
                    if (row == col + 1) v1 += 1.5f;
                } else if (mymode == 3) {
                    v0 *= sc3; v1 *= sc3;
                }
                *reinterpret_cast<float2*>(Cn + (size_t)row * DD + col) =
                    make_float2(v0, v1);
                if (do_t) {
                    stg[rl * 129 + cl]     = v0;
                    stg[rl * 129 + cl + 1] = v1;
                }
            }
        }
    }

    // mirrored tile: C[cb..][rb..] = (this tile)^T, coalesced via smem
    if (do_t) {
        __syncthreads();
        const int r2    = tid >> 1;            // row of transposed tile
        const int cbase = (tid & 1) * 64;      // 2 threads per row, 64 cols each
        float* orow = Cn + (size_t)(cb + r2) * DD + rb + cbase;
        #pragma unroll
        for (int q = 0; q < 16; q++) {
            float4 vv;
            vv.x = stg[(cbase + q * 4 + 0) * 129 + r2];
            vv.y = stg[(cbase + q * 4 + 1) * 129 + r2];
            vv.z = stg[(cbase + q * 4 + 2) * 129 + r2];
            vv.w = stg[(cbase + q * 4 + 3) * 129 + r2];
            *reinterpret_cast<float4*>(orow + q * 4) = vv;
        }
    }
}

// ======================= host launcher ======================================
extern "C" void kernel_launch(void* const* d_in, const int* in_sizes, int n_in,
                              void* d_out, int out_size) {
    const float* x = (const float*)d_in[0];
    float* out = (float*)d_out;

    float *xn, *xnT, *Ba, *Bb, *Cm, *P0, *P1;
    cudaGetSymbolAddress((void**)&xn,  g_xn);
    cudaGetSymbolAddress((void**)&xnT, g_xnT);
    cudaGetSymbolAddress((void**)&Ba,  g_Ba);
    cudaGetSymbolAddress((void**)&Bb,  g_Bb);
    cudaGetSymbolAddress((void**)&Cm,  g_Cm);
    cudaGetSymbolAddress((void**)&P0,  g_P0);
    cudaGetSymbolAddress((void**)&P1,  g_P1);

    cudaFuncSetAttribute(gemm_mma,
                         cudaFuncAttributeMaxDynamicSharedMemorySize, SMEM_DYN);

    const long long sM = (long long)DD * DD;   // 65536
    const long long sX = (long long)MM * DD;   // 131072
    const dim3 gSym(3, 1, NB);                 // symmetric, single job
    const dim3 gSym2(6, 1, NB);                // symmetric, two jobs

    mean_kernel<<<NB, 256>>>(x);
    center_kernel<<<dim3(DD / 32, MM / 32, NB), dim3(32, 8)>>>(x);
    reduce_tr_kernel<<<NB, 128>>>();

    // sigma -> Ba = B0 = 1.5I - 0.5*(xnT xnT^T)/sumsq  [K=512, sym, squaring]
    gemm_mma<<<gSym, 256, SMEM_DYN>>>(Ba, xnT, xnT, nullptr, nullptr, nullptr,
                                      MM, MM, MM, sX, sX, sM, 0, 2, 1, 1, 1);
    // iter 1: Cm = B0^2 (squaring) ; Bb = Cm*B0 - 1.5Cm + 1.5I  (B1)
    gemm_mma<<<gSym, 256, SMEM_DYN>>>(Cm, Ba, Ba, nullptr, nullptr, nullptr,
                                      DD, DD, DD, sM, sM, sM, 0, 0, 1, 1, 1);
    gemm_mma<<<gSym, 256, SMEM_DYN>>>(Bb, Cm, Ba, Cm, nullptr, nullptr,
                                      DD, DD, DD, sM, sM, sM, sM, 1, 1, 0, 1);
    // iter 2: {Cm = B1^2 (squaring) , P0 = B0*B1 (P2)} ; Ba = B2
    gemm_mma<<<gSym2, 256, SMEM_DYN>>>(Cm, Bb, Bb, nullptr, P0, Ba,
                                       DD, DD, DD, sM, sM, sM, 0, 0, 1, 1, 1);
    gemm_mma<<<gSym, 256, SMEM_DYN>>>(Ba, Cm, Bb, Cm, nullptr, nullptr,
                                      DD, DD, DD, sM, sM, sM, sM, 1, 1, 0, 1);
    // iter 3: {Cm = B2^2 (squaring) , P1 = P2*B2 (P3)} ; Bb = B3
    gemm_mma<<<gSym2, 256, SMEM_DYN>>>(Cm, Ba, Ba, nullptr, P1, P0,
                                       DD, DD, DD, sM, sM, sM, 0, 0, 1, 1, 1);
    gemm_mma<<<gSym, 256, SMEM_DYN>>>(Bb, Cm, Ba, Cm, nullptr, nullptr,
                                      DD, DD, DD, sM, sM, sM, sM, 1, 1, 0, 1);
    // iter 4: P0 = P3*B3 (P4) — unamplified, 2-pass tf32
    gemm_mma<<<gSym, 256, SMEM_DYN>>>(P0, P1, Bb, nullptr, nullptr, nullptr,
                                      DD, DD, DD, sM, sM, sM, 0, 0, 1, 0, 0);
    // final: out = xn * P4 * rsqrt(sumsq/(M-1)) — unamplified, 2-pass tf32
    gemm_mma<<<dim3(4, 2, NB), 256, SMEM_DYN>>>(out, xn, P0, nullptr, nullptr,
                                                nullptr, DD, DD, DD,
                                                sX, sM, sX, 0, 3, 0, 0, 0);
}

// round 8
// speedup vs baseline: 3.5494x; 1.0004x over previous
#include <cuda_runtime.h>
#include <cuda_fp16.h>
#include <cstdint>
#include <cstddef>

#define NB   256
#define MM   512
#define DD   256

// ======================= scratch (device globals) ===========================
// All matrices stored as split fp16: each row = [hi halves 0..C-1][lo halves].
__device__ __align__(256) float  g_mean[NB * DD];
__device__ __align__(256) float  g_tr  [NB];          // sumsq = trace*(M-1)
__device__ __align__(256) float  g_ssp [NB * 128];
__device__ __align__(256) __half g_xn  [NB * MM * 2 * DD];   // 134 MB
__device__ __align__(256) __half g_xnT [NB * DD * 2 * MM];   // 134 MB
__device__ __align__(256) __half g_Ba  [NB * DD * 2 * DD];
__device__ __align__(256) __half g_Bb  [NB * DD * 2 * DD];
__device__ __align__(256) __half g_Cm  [NB * DD * 2 * DD];
__device__ __align__(256) __half g_P0  [NB * DD * 2 * DD];
__device__ __align__(256) __half g_P1  [NB * DD * 2 * DD];

// ======================= PTX helpers ========================================
__device__ __forceinline__ uint32_t smem_u32(const void* p) {
    uint32_t a;
    asm("{ .reg .u64 t; cvta.to.shared.u64 t, %1; cvt.u32.u64 %0, t; }"
        : "=r"(a) : "l"(p));
    return a;
}

#define CP_ASYNC16(dst_u32, src_gptr) \
    asm volatile("cp.async.cg.shared.global [%0], [%1], 16;" \
                 :: "r"(dst_u32), "l"(src_gptr) : "memory")
#define CP_COMMIT() asm volatile("cp.async.commit_group;" ::: "memory")
#define CP_WAIT1()  asm volatile("cp.async.wait_group 1;" ::: "memory")
#define CP_WAIT0()  asm volatile("cp.async.wait_group 0;" ::: "memory")

#define LDM_X4(r0, r1, r2, r3, addr) \
    asm volatile("ldmatrix.sync.aligned.m8n8.x4.shared.b16 {%0,%1,%2,%3}, [%4];" \
                 : "=r"(r0), "=r"(r1), "=r"(r2), "=r"(r3) : "r"(addr))

#define MMA_FP16(d, a0, a1, a2, a3, b0, b1) \
    asm volatile("mma.sync.aligned.m16n8k16.row.col.f32.f16.f16.f32 " \
                 "{%0,%1,%2,%3}, {%4,%5,%6,%7}, {%8,%9}, {%0,%1,%2,%3};" \
                 : "+f"((d)[0]), "+f"((d)[1]), "+f"((d)[2]), "+f"((d)[3]) \
                 : "r"(a0), "r"(a1), "r"(a2), "r"(a3), "r"(b0), "r"(b1))

__device__ __forceinline__ uint32_t h2_half(uint32_t x) {   // *0.5 packed fp16x2
    uint32_t d;
    asm("mul.rn.f16x2 %0, %1, %2;" : "=r"(d) : "r"(x), "r"(0x38003800u));
    return d;
}

// ======================= mean over axis 1 ===================================
__global__ __launch_bounds__(256) void mean_kernel(const float* __restrict__ x) {
    int n = blockIdx.x, d = threadIdx.x;
    const float* xp = x + (size_t)n * MM * DD + d;
    float s0 = 0.f, s1 = 0.f, s2 = 0.f, s3 = 0.f;
    #pragma unroll 4
    for (int m = 0; m < MM; m += 4) {
        s0 += xp[(size_t)(m + 0) * DD];
        s1 += xp[(size_t)(m + 1) * DD];
        s2 += xp[(size_t)(m + 2) * DD];
        s3 += xp[(size_t)(m + 3) * DD];
    }
    g_mean[n * DD + d] = (s0 + s1 + s2 + s3) * (1.f / (float)MM);
}

// ==== center: xn = x - mean (split fp16), xnT (split fp16), sumsq partials ==
__global__ __launch_bounds__(256) void center_kernel(const float* __restrict__ x) {
    const int n  = blockIdx.z;
    const int d0 = blockIdx.x * 32;
    const int m0 = blockIdx.y * 32;
    const int tx = threadIdx.x, ty = threadIdx.y;   // block (32, 8)

    __shared__ float tile[32][33];
    __shared__ float red[256];

    const int d = d0 + tx;
    const float mu = g_mean[n * DD + d];
    float ss = 0.f;
    #pragma unroll
    for (int r = 0; r < 4; r++) {
        int m = m0 + ty + r * 8;
        float v = x[(size_t)n * MM * DD + (size_t)m * DD + d] - mu;
        __half hh = __float2half_rn(v);
        __half hl = __float2half_rn(v - __half2float(hh));
        size_t base = (size_t)n * MM * 2 * DD + (size_t)m * 2 * DD;
        g_xn[base + d]      = hh;
        g_xn[base + DD + d] = hl;
        tile[ty + r * 8][tx] = v;
        ss += v * v;
    }
    __syncthreads();
    #pragma unroll
    for (int r = 0; r < 4; r++) {
        int dd_ = ty + r * 8;
        float v = tile[tx][dd_];
        __half hh = __float2half_rn(v);
        __half hl = __float2half_rn(v - __half2float(hh));
        size_t base = (size_t)n * DD * 2 * MM + (size_t)(d0 + dd_) * 2 * MM;
        g_xnT[base + m0 + tx]      = hh;
        g_xnT[base + MM + m0 + tx] = hl;
    }
    int t = ty * 32 + tx;
    red[t] = ss;
    __syncthreads();
    for (int s = 128; s > 0; s >>= 1) {
        if (t < s) red[t] += red[t + s];
        __syncthreads();
    }
    if (t == 0) g_ssp[n * 128 + blockIdx.y * 8 + blockIdx.x] = red[0];
}

__global__ __launch_bounds__(128) void reduce_tr_kernel() {
    int n = blockIdx.x, t = threadIdx.x;
    __shared__ float red[128];
    red[t] = g_ssp[n * 128 + t];
    __syncthreads();
    for (int s = 64; s > 0; s >>= 1) {
        if (t < s) red[t] += red[t + s];
        __syncthreads();
    }
    if (t == 0) g_tr[n] = red[0];
}

// ===================== fp16x3 mma.sync batched GEMM =========================
// D[m][n] = sum_k A[m][k] * B[n][k]; operands are split-fp16 (hi row ‖ lo row).
// job0: C = epi(A*B)   job1 (sym launches, optional): C2 = A2*B (mode 0)
// mode: 0: C = acc
//       1: C = acc - 1.5*Dm + 1.5*I       (NS update; Dm split fp16, = B^2)
//       2: C = (-0.5/ts)*acc + 1.5*I      (sigma -> B0)
//       3: C = acc * rsqrt(ts/(M-1))      (final scaling; fp32 output)
// sym:  symmetric 256x256 output, 3 tiles/job, (0,1) mirrored via smem.
// sqr:  A==B squaring launch: diagonal tiles use acc = Ah*(0.5Bh) + Ah*Bl,
//       C = acc + acc^T (exact 3-pass algebra).
// pass3: 0 => drop Al*Bh pass (2-pass; unamplified outputs only).
// ofmt: 0 => split-fp16 output, 1 => fp32 output.
#define STG_B      32768u
#define SMEM_DYN   98304   // 3 stages x 32KB; >= 128*129*4 transpose staging

__global__ __launch_bounds__(256, 2) void gemm_h(
    void* __restrict__ Cout, const __half* __restrict__ Amat,
    const __half* __restrict__ Bmat, const __half* __restrict__ Dmat,
    void* __restrict__ C2out, const __half* __restrict__ A2mat,
    int lda, int ldb, int Ktot,
    long long sA, long long sB, long long sC, long long sD,
    int mode, int sym, int sqr, int pass3, int ofmt)
{
    extern __shared__ char smem[];
    const uint32_t sb = smem_u32(smem);

    const int tid  = threadIdx.x;
    const int wid  = tid >> 5, lane = tid & 31;
    const int wm   = wid & 1;          // 2 warp-rows (64 each)
    const int wn   = wid >> 1;         // 4 warp-cols (32 each)
    const int n    = blockIdx.z;

    int ti, tj, job = 0, mymode = mode;
    if (sym) {
        int tt = blockIdx.x;
        if (tt >= 3) { job = 1; tt -= 3; mymode = 0; }
        ti = (tt == 2) ? 1 : 0; tj = (tt != 0) ? 1 : 0;
    } else {
        ti = blockIdx.x; tj = blockIdx.y;
    }
    const int rb = ti * 128;
    const int cb = tj * 128;

    const bool do_diag = sqr && sym && (job == 0) && (ti == tj);
    const bool need_al = (pass3 != 0) && !do_diag;

    const __half* An = (job ? A2mat : Amat) + (size_t)n * sA;
    const __half* Bn = Bmat + (size_t)n * sB;

    const int ld2a = 2 * lda, ld2b = 2 * ldb;

    // staging indices: 1024 16B-groups per tile (128 rows x 8 groups: 4 hi+4 lo)
    int srow[4], sg[4];
    uint32_t sdst[4];
    #pragma unroll
    for (int j = 0; j < 4; j++) {
        int idx = tid + 256 * j;
        srow[j] = idx >> 3;
        sg[j]   = idx & 7;
        sdst[j] = (uint32_t)(srow[j] * 128 + ((sg[j] ^ (srow[j] & 7)) << 4));
    }

    // ldmatrix lane geometry
    const int t  = lane >> 3, s7 = lane & 7;
    const int chA = t >> 1;                        // k16-half select for A
    const int rAl = wm * 64 + (t & 1) * 8 + s7;
    const int chB = t & 1;                         // k16-half select for B
    const int rBl = wn * 32 + (t >> 1) * 8 + s7;

    float acc[4][4][4];
    #pragma unroll
    for (int i = 0; i < 4; i++)
        #pragma unroll
        for (int j = 0; j < 4; j++)
            #pragma unroll
            for (int q = 0; q < 4; q++) acc[i][j][q] = 0.f;

    const int nch = Ktot >> 5;

    // prologue: stage chunks 0,1 (3-stage pipeline)
    #pragma unroll
    for (int pc = 0; pc < 2; pc++) {
        const int k0 = pc * 32;
        #pragma unroll
        for (int j = 0; j < 4; j++) {
            const __half* s = An + (size_t)(rb + srow[j]) * ld2a +
                              ((sg[j] & 4) ? lda : 0) + k0 + (sg[j] & 3) * 8;
            CP_ASYNC16(sb + pc * STG_B + sdst[j], (const void*)s);
        }
        #pragma unroll
        for (int j = 0; j < 4; j++) {
            const __half* s = Bn + (size_t)(cb + srow[j]) * ld2b +
                              ((sg[j] & 4) ? ldb : 0) + k0 + (sg[j] & 3) * 8;
            CP_ASYNC16(sb + pc * STG_B + 16384u + sdst[j], (const void*)s);
        }
        CP_COMMIT();
    }

    for (int c = 0; c < nch; c++) {
        if (c + 1 < nch) CP_WAIT1(); else CP_WAIT0();
        __syncthreads();

        if (c + 2 < nch) {
            const uint32_t bs = (uint32_t)((c + 2) % 3);
            const int k0 = (c + 2) * 32;
            #pragma unroll
            for (int j = 0; j < 4; j++) {
                const __half* s = An + (size_t)(rb + srow[j]) * ld2a +
                                  ((sg[j] & 4) ? lda : 0) + k0 + (sg[j] & 3) * 8;
                CP_ASYNC16(sb + bs * STG_B + sdst[j], (const void*)s);
            }
            #pragma unroll
            for (int j = 0; j < 4; j++) {
                const __half* s = Bn + (size_t)(cb + srow[j]) * ld2b +
                                  ((sg[j] & 4) ? ldb : 0) + k0 + (sg[j] & 3) * 8;
                CP_ASYNC16(sb + bs * STG_B + 16384u + sdst[j], (const void*)s);
            }
            CP_COMMIT();
        }

        const uint32_t aB = sb + (uint32_t)(c % 3) * STG_B;
        const uint32_t bB = aB + 16384u;

        #pragma unroll
        for (int kk = 0; kk < 2; kk++) {
            uint32_t bh[2][4], bl[2][4];
            #pragma unroll
            for (int p = 0; p < 2; p++) {
                const int ghB = (kk << 1) + chB;
                uint32_t ah_ = bB + (uint32_t)((rBl + p * 16) * 128 +
                               ((ghB) ^ s7) * 16);
                LDM_X4(bh[p][0], bh[p][1], bh[p][2], bh[p][3], ah_);
                uint32_t al_ = bB + (uint32_t)((rBl + p * 16) * 128 +
                               ((4 + ghB) ^ s7) * 16);
                LDM_X4(bl[p][0], bl[p][1], bl[p][2], bl[p][3], al_);
            }
            if (do_diag) {
                #pragma unroll
                for (int p = 0; p < 2; p++)
                    #pragma unroll
                    for (int q = 0; q < 4; q++) bh[p][q] = h2_half(bh[p][q]);
            }

            #pragma unroll
            for (int mi = 0; mi < 4; mi++) {
                const int ghA = (kk << 1) + chA;
                uint32_t ah[4];
                uint32_t aadr = aB + (uint32_t)((rAl + mi * 16) * 128 +
                                ((ghA) ^ s7) * 16);
                LDM_X4(ah[0], ah[1], ah[2], ah[3], aadr);
                #pragma unroll
                for (int p = 0; p < 2; p++)
                    #pragma unroll
                    for (int q = 0; q < 2; q++) {
                        MMA_FP16(acc[mi][p*2+q], ah[0], ah[1], ah[2], ah[3],
                                 bh[p][2*q], bh[p][2*q+1]);
                        MMA_FP16(acc[mi][p*2+q], ah[0], ah[1], ah[2], ah[3],
                                 bl[p][2*q], bl[p][2*q+1]);
                    }
                if (need_al) {
                    uint32_t al[4];
                    uint32_t ladr = aB + (uint32_t)((rAl + mi * 16) * 128 +
                                    ((4 + ghA) ^ s7) * 16);
                    LDM_X4(al[0], al[1], al[2], al[3], ladr);
                    #pragma unroll
                    for (int p = 0; p < 2; p++)
                        #pragma unroll
                        for (int q = 0; q < 2; q++)
                            MMA_FP16(acc[mi][p*2+q], al[0], al[1], al[2], al[3],
                                     bh[p][2*q], bh[p][2*q+1]);
                }
            }
        }
    }
    __syncthreads();   // mainloop smem dead; staging buffer reusable

    // ---------------- epilogue ----------------
    const int g = lane >> 2, tig = lane & 3;
    float* stg = reinterpret_cast<float*>(smem);   // 128x129 fp32 staging

    if (do_diag) {      // C_raw = acc + acc^T
        #pragma unroll
        for (int mi = 0; mi < 4; mi++)
            #pragma unroll
            for (int nj = 0; nj < 4; nj++) {
                const int cl = wn * 32 + nj * 8 + 2 * tig;
                #pragma unroll
                for (int h = 0; h < 2; h++) {
                    const int rl = wm * 64 + mi * 16 + g + 8 * h;
                    stg[rl * 129 + cl]     = acc[mi][nj][2 * h];
                    stg[rl * 129 + cl + 1] = acc[mi][nj][2 * h + 1];
                }
            }
        __syncthreads();
        #pragma unroll
        for (int mi = 0; mi < 4; mi++)
            #pragma unroll
            for (int nj = 0; nj < 4; nj++) {
                const int cl = wn * 32 + nj * 8 + 2 * tig;
                #pragma unroll
                for (int h = 0; h < 2; h++) {
                    const int rl = wm * 64 + mi * 16 + g + 8 * h;
                    acc[mi][nj][2 * h]     += stg[cl * 129 + rl];
                    acc[mi][nj][2 * h + 1] += stg[(cl + 1) * 129 + rl];
                }
            }
    }

    float ts = 0.f;
    if (mymode >= 2) ts = g_tr[n];
    const float sc2 = (mymode == 2) ? (-0.5f / ts) : 0.f;
    const float sc3 = (mymode == 3) ? rsqrtf(ts / (float)(MM - 1)) : 0.f;
    const __half* Dn = Dmat ? (Dmat + (size_t)n * sD) : nullptr;

    __half* Ch = nullptr;
    float*  Cf = nullptr;
    if (ofmt == 0) Ch = (__half*)(job ? C2out : Cout) + (size_t)n * sC;
    else           Cf = (float*)Cout + (size_t)n * sC;

    const bool do_t = sym && (rb != cb);
    if (do_t) __syncthreads();

    #pragma unroll
    for (int mi = 0; mi < 4; mi++) {
        #pragma unroll
        for (int nj = 0; nj < 4; nj++) {
            const int cl = wn * 32 + nj * 8 + 2 * tig;
            const int col = cb + cl;
            #pragma unroll
            for (int h = 0; h < 2; h++) {
                const int rl = wm * 64 + mi * 16 + g + 8 * h;
                const int row = rb + rl;
                float v0 = acc[mi][nj][2 * h];
                float v1 = acc[mi][nj][2 * h + 1];
                if (mymode == 1) {
                    const __half2 dh = *reinterpret_cast<const __half2*>(
                        Dn + (size_t)row * 2 * DD + col);
                    const __half2 dl = *reinterpret_cast<const __half2*>(
                        Dn + (size_t)row * 2 * DD + DD + col);
                    v0 -= 1.5f * (__half2float(dh.x) + __half2float(dl.x));
                    v1 -= 1.5f * (__half2float(dh.y) + __half2float(dl.y));
                    if (row == col)     v0 += 1.5f;
                    if (row == col + 1) v1 += 1.5f;
                } else if (mymode == 2) {
                    v0 *= sc2; v1 *= sc2;
                    if (row == col)     v0 += 1.5f;
                    if (row == col + 1) v1 += 1.5f;
                } else if (mymode == 3) {
                    v0 *= sc3; v1 *= sc3;
                }
                if (ofmt == 0) {
                    __half h0 = __float2half_rn(v0), h1 = __float2half_rn(v1);
                    __half l0 = __float2half_rn(v0 - __half2float(h0));
                    __half l1 = __float2half_rn(v1 - __half2float(h1));
                    *reinterpret_cast<__half2*>(Ch + (size_t)row * 2 * DD + col)
                        = __halves2half2(h0, h1);
                    *reinterpret_cast<__half2*>(Ch + (size_t)row * 2 * DD + DD + col)
                        = __halves2half2(l0, l1);
                } else {
                    *reinterpret_cast<float2*>(Cf + (size_t)row * DD + col) =
                        make_float2(v0, v1);
                }
                if (do_t) {
                    stg[rl * 129 + cl]     = v0;
                    stg[rl * 129 + cl + 1] = v1;
                }
            }
        }
    }

    // mirrored tile: C[cb..][rb..] = (this tile)^T  (split-fp16 outputs only)
    if (do_t) {
        __syncthreads();
        const int r2    = tid >> 1;
        const int cbase = (tid & 1) * 64;
        __half* orow = Ch + (size_t)(cb + r2) * 2 * DD + rb + cbase;
        #pragma unroll
        for (int q = 0; q < 16; q++) {
            float w0 = stg[(cbase + q * 4 + 0) * 129 + r2];
            float w1 = stg[(cbase + q * 4 + 1) * 129 + r2];
            float w2 = stg[(cbase + q * 4 + 2) * 129 + r2];
            float w3 = stg[(cbase + q * 4 + 3) * 129 + r2];
            __half h0 = __float2half_rn(w0), h1 = __float2half_rn(w1);
            __half h2 = __float2half_rn(w2), h3 = __float2half_rn(w3);
            *reinterpret_cast<__half2*>(orow + q * 4)     = __halves2half2(h0, h1);
            *reinterpret_cast<__half2*>(orow + q * 4 + 2) = __halves2half2(h2, h3);
            __half l0 = __float2half_rn(w0 - __half2float(h0));
            __half l1 = __float2half_rn(w1 - __half2float(h1));
            __half l2 = __float2half_rn(w2 - __half2float(h2));
            __half l3 = __float2half_rn(w3 - __half2float(h3));
            *reinterpret_cast<__half2*>(orow + DD + q * 4)     = __halves2half2(l0, l1);
            *reinterpret_cast<__half2*>(orow + DD + q * 4 + 2) = __halves2half2(l2, l3);
        }
    }
}

// ======================= host launcher ======================================
extern "C" void kernel_launch(void* const* d_in, const int* in_sizes, int n_in,
                              void* d_out, int out_size) {
    const float* x = (const float*)d_in[0];
    float* out = (float*)d_out;

    __half *xn, *xnT, *Ba, *Bb, *Cm, *P0, *P1;
    cudaGetSymbolAddress((void**)&xn,  g_xn);
    cudaGetSymbolAddress((void**)&xnT, g_xnT);
    cudaGetSymbolAddress((void**)&Ba,  g_Ba);
    cudaGetSymbolAddress((void**)&Bb,  g_Bb);
    cudaGetSymbolAddress((void**)&Cm,  g_Cm);
    cudaGetSymbolAddress((void**)&P0,  g_P0);
    cudaGetSymbolAddress((void**)&P1,  g_P1);

    cudaFuncSetAttribute(gemm_h,
                         cudaFuncAttributeMaxDynamicSharedMemorySize, SMEM_DYN);

    const long long sM  = (long long)DD * 2 * DD;   // chain mats (halves)
    const long long sXT = (long long)DD * 2 * MM;   // xnT (halves)
    const long long sXN = (long long)MM * 2 * DD;   // xn (halves)
    const long long sO  = (long long)MM * DD;       // out (floats)
    const dim3 gSym(3, 1, NB);
    const dim3 gSym2(6, 1, NB);

    mean_kernel<<<NB, 256>>>(x);
    center_kernel<<<dim3(DD / 32, MM / 32, NB), dim3(32, 8)>>>(x);
    reduce_tr_kernel<<<NB, 128>>>();

    // sigma -> Ba = B0 = 1.5I - 0.5*(xnT xnT^T)/sumsq  [K=512, sym, squaring]
    gemm_h<<<gSym, 256, SMEM_DYN>>>(Ba, xnT, xnT, nullptr, nullptr, nullptr,
                                    MM, MM, MM, sXT, sXT, sM, 0, 2, 1, 1, 1, 0);
    // iter 1: Cm = B0^2 (squaring) ; Bb = Cm*B0 - 1.5Cm + 1.5I  (B1)
    gemm_h<<<gSym, 256, SMEM_DYN>>>(Cm, Ba, Ba, nullptr, nullptr, nullptr,
                                    DD, DD, DD, sM, sM, sM, 0, 0, 1, 1, 1, 0);
    gemm_h<<<gSym, 256, SMEM_DYN>>>(Bb, Cm, Ba, Cm, nullptr, nullptr,
                                    DD, DD, DD, sM, sM, sM, sM, 1, 1, 0, 1, 0);
    // iter 2: {Cm = B1^2 (squaring) , P0 = B0*B1 (P2)} ; Ba = B2
    gemm_h<<<gSym2, 256, SMEM_DYN>>>(Cm, Bb, Bb, nullptr, P0, Ba,
                                     DD, DD, DD, sM, sM, sM, 0, 0, 1, 1, 1, 0);
    gemm_h<<<gSym, 256, SMEM_DYN>>>(Ba, Cm, Bb, Cm, nullptr, nullptr,
                                    DD, DD, DD, sM, sM, sM, sM, 1, 1, 0, 1, 0);
    // iter 3: {Cm = B2^2 (squaring) , P1 = P2*B2 (P3)} ; Bb = B3
    gemm_h<<<gSym2, 256, SMEM_DYN>>>(Cm, Ba, Ba, nullptr, P1, P0,
                                     DD, DD, DD, sM, sM, sM, 0, 0, 1, 1, 1, 0);
    gemm_h<<<gSym, 256, SMEM_DYN>>>(Bb, Cm, Ba, Cm, nullptr, nullptr,
                                    DD, DD, DD, sM, sM, sM, sM, 1, 1, 0, 1, 0);
    // iter 4: P0 = P3*B3 (P4) — unamplified, 2-pass
    gemm_h<<<gSym, 256, SMEM_DYN>>>(P0, P1, Bb, nullptr, nullptr, nullptr,
                                    DD, DD, DD, sM, sM, sM, 0, 0, 1, 0, 0, 0);
    // final: out = xn * P4 * rsqrt(sumsq/(M-1)) — unamplified, 2-pass, fp32 out
    gemm_h<<<dim3(4, 2, NB), 256, SMEM_DYN>>>(out, xn, P0, nullptr, nullptr,
                                              nullptr, DD, DD, DD,
                                              sXN, sM, sO, 0, 3, 0, 0, 0, 1);
}

// round 9
// speedup vs baseline: 3.6286x; 1.0223x over previous
#include <cuda_runtime.h>
#include <cuda_fp16.h>
#include <cstdint>
#include <cstddef>

#define NB   256
#define MM   512
#define DD   256

// ======================= scratch (device globals) ===========================
// All matrices stored as split fp16: each row = [hi halves 0..C-1][lo halves].
__device__ __align__(256) float  g_mean[NB * DD];
__device__ __align__(256) float  g_tr  [NB];          // sumsq = trace*(M-1)
__device__ __align__(256) float  g_ssp [NB * 128];
__device__ __align__(256) __half g_xn  [NB * MM * 2 * DD];
__device__ __align__(256) __half g_xnT [NB * DD * 2 * MM];
__device__ __align__(256) __half g_Ba  [NB * DD * 2 * DD];
__device__ __align__(256) __half g_Bb  [NB * DD * 2 * DD];
__device__ __align__(256) __half g_Cm  [NB * DD * 2 * DD];
__device__ __align__(256) __half g_P0  [NB * DD * 2 * DD];
__device__ __align__(256) __half g_P1  [NB * DD * 2 * DD];

// ======================= PTX helpers ========================================
__device__ __forceinline__ uint32_t smem_u32(const void* p) {
    uint32_t a;
    asm("{ .reg .u64 t; cvta.to.shared.u64 t, %1; cvt.u32.u64 %0, t; }"
        : "=r"(a) : "l"(p));
    return a;
}

#define CP_ASYNC16(dst_u32, src_gptr) \
    asm volatile("cp.async.cg.shared.global [%0], [%1], 16;" \
                 :: "r"(dst_u32), "l"(src_gptr) : "memory")
#define CP_COMMIT() asm volatile("cp.async.commit_group;" ::: "memory")
#define CP_WAIT1()  asm volatile("cp.async.wait_group 1;" ::: "memory")
#define CP_WAIT0()  asm volatile("cp.async.wait_group 0;" ::: "memory")

#define LDM_X4(r0, r1, r2, r3, addr) \
    asm volatile("ldmatrix.sync.aligned.m8n8.x4.shared.b16 {%0,%1,%2,%3}, [%4];" \
                 : "=r"(r0), "=r"(r1), "=r"(r2), "=r"(r3) : "r"(addr))

#define MMA_FP16(d, a0, a1, a2, a3, b0, b1) \
    asm volatile("mma.sync.aligned.m16n8k16.row.col.f32.f16.f16.f32 " \
                 "{%0,%1,%2,%3}, {%4,%5,%6,%7}, {%8,%9}, {%0,%1,%2,%3};" \
                 : "+f"((d)[0]), "+f"((d)[1]), "+f"((d)[2]), "+f"((d)[3]) \
                 : "r"(a0), "r"(a1), "r"(a2), "r"(a3), "r"(b0), "r"(b1))

__device__ __forceinline__ uint32_t h2_half(uint32_t x) {   // *0.5 packed fp16x2
    uint32_t d;
    asm("mul.rn.f16x2 %0, %1, %2;" : "=r"(d) : "r"(x), "r"(0x38003800u));
    return d;
}

// ======================= mean over axis 1 ===================================
__global__ __launch_bounds__(256) void mean_kernel(const float* __restrict__ x) {
    int n = blockIdx.x, d = threadIdx.x;
    const float* xp = x + (size_t)n * MM * DD + d;
    float s0 = 0.f, s1 = 0.f, s2 = 0.f, s3 = 0.f;
    #pragma unroll 4
    for (int m = 0; m < MM; m += 4) {
        s0 += xp[(size_t)(m + 0) * DD];
        s1 += xp[(size_t)(m + 1) * DD];
        s2 += xp[(size_t)(m + 2) * DD];
        s3 += xp[(size_t)(m + 3) * DD];
    }
    g_mean[n * DD + d] = (s0 + s1 + s2 + s3) * (1.f / (float)MM);
}

// ==== center: xn = x - mean (split fp16), xnT (split fp16), sumsq partials ==
__global__ __launch_bounds__(256) void center_kernel(const float* __restrict__ x) {
    const int n  = blockIdx.z;
    const int d0 = blockIdx.x * 32;
    const int m0 = blockIdx.y * 32;
    const int tx = threadIdx.x, ty = threadIdx.y;   // block (32, 8)

    __shared__ float tile[32][33];
    __shared__ float red[256];

    const int d = d0 + tx;
    const float mu = g_mean[n * DD + d];
    float ss = 0.f;
    #pragma unroll
    for (int r = 0; r < 4; r++) {
        int m = m0 + ty + r * 8;
        float v = x[(size_t)n * MM * DD + (size_t)m * DD + d] - mu;
        __half hh = __float2half_rn(v);
        __half hl = __float2half_rn(v - __half2float(hh));
        size_t base = (size_t)n * MM * 2 * DD + (size_t)m * 2 * DD;
        g_xn[base + d]      = hh;
        g_xn[base + DD + d] = hl;
        tile[ty + r * 8][tx] = v;
        ss += v * v;
    }
    __syncthreads();
    #pragma unroll
    for (int r = 0; r < 4; r++) {
        int dd_ = ty + r * 8;
        float v = tile[tx][dd_];
        __half hh = __float2half_rn(v);
        __half hl = __float2half_rn(v - __half2float(hh));
        size_t base = (size_t)n * DD * 2 * MM + (size_t)(d0 + dd_) * 2 * MM;
        g_xnT[base + m0 + tx]      = hh;
        g_xnT[base + MM + m0 + tx] = hl;
    }
    int t = ty * 32 + tx;
    red[t] = ss;
    __syncthreads();
    for (int s = 128; s > 0; s >>= 1) {
        if (t < s) red[t] += red[t + s];
        __syncthreads();
    }
    if (t == 0) g_ssp[n * 128 + blockIdx.y * 8 + blockIdx.x] = red[0];
}

__global__ __launch_bounds__(128) void reduce_tr_kernel() {
    int n = blockIdx.x, t = threadIdx.x;
    __shared__ float red[128];
    red[t] = g_ssp[n * 128 + t];
    __syncthreads();
    for (int s = 64; s > 0; s >>= 1) {
        if (t < s) red[t] += red[t + s];
        __syncthreads();
    }
    if (t == 0) g_tr[n] = red[0];
}

// ===================== fp16x3 mma.sync batched GEMM =========================
// (semantics identical to round 8; inner loop restructured for latency)
#define STG_B      32768u
#define SMEM_DYN   98304

__global__ __launch_bounds__(256, 2) void gemm_h(
    void* __restrict__ Cout, const __half* __restrict__ Amat,
    const __half* __restrict__ Bmat, const __half* __restrict__ Dmat,
    void* __restrict__ C2out, const __half* __restrict__ A2mat,
    int lda, int ldb, int Ktot,
    long long sA, long long sB, long long sC, long long sD,
    int mode, int sym, int sqr, int pass3, int ofmt)
{
    extern __shared__ char smem[];
    const uint32_t sb = smem_u32(smem);

    const int tid  = threadIdx.x;
    const int wid  = tid >> 5, lane = tid & 31;
    const int wm   = wid & 1;
    const int wn   = wid >> 1;
    const int n    = blockIdx.z;

    int ti, tj, job = 0, mymode = mode;
    if (sym) {
        int tt = blockIdx.x;
        if (tt >= 3) { job = 1; tt -= 3; mymode = 0; }
        ti = (tt == 2) ? 1 : 0; tj = (tt != 0) ? 1 : 0;
    } else {
        ti = blockIdx.x; tj = blockIdx.y;
    }
    const int rb = ti * 128;
    const int cb = tj * 128;

    const bool do_diag = sqr && sym && (job == 0) && (ti == tj);
    const bool need_al = (pass3 != 0) && !do_diag;

    const __half* An = (job ? A2mat : Amat) + (size_t)n * sA;
    const __half* Bn = Bmat + (size_t)n * sB;

    const int ld2a = 2 * lda, ld2b = 2 * ldb;

    int srow[4], sg[4];
    uint32_t sdst[4];
    #pragma unroll
    for (int j = 0; j < 4; j++) {
        int idx = tid + 256 * j;
        srow[j] = idx >> 3;
        sg[j]   = idx & 7;
        sdst[j] = (uint32_t)(srow[j] * 128 + ((sg[j] ^ (srow[j] & 7)) << 4));
    }

    const int t  = lane >> 3, s7 = lane & 7;
    const int chA = t >> 1;
    const int rAl = wm * 64 + (t & 1) * 8 + s7;
    const int chB = t & 1;
    const int rBl = wn * 32 + (t >> 1) * 8 + s7;

    float acc[4][4][4];
    #pragma unroll
    for (int i = 0; i < 4; i++)
        #pragma unroll
        for (int j = 0; j < 4; j++)
            #pragma unroll
            for (int q = 0; q < 4; q++) acc[i][j][q] = 0.f;

    const int nch = Ktot >> 5;

    #pragma unroll
    for (int pc = 0; pc < 2; pc++) {
        const int k0 = pc * 32;
        #pragma unroll
        for (int j = 0; j < 4; j++) {
            const __half* s = An + (size_t)(rb + srow[j]) * ld2a +
                              ((sg[j] & 4) ? lda : 0) + k0 + (sg[j] & 3) * 8;
            CP_ASYNC16(sb + pc * STG_B + sdst[j], (const void*)s);
        }
        #pragma unroll
        for (int j = 0; j < 4; j++) {
            const __half* s = Bn + (size_t)(cb + srow[j]) * ld2b +
                              ((sg[j] & 4) ? ldb : 0) + k0 + (sg[j] & 3) * 8;
            CP_ASYNC16(sb + pc * STG_B + 16384u + sdst[j], (const void*)s);
        }
        CP_COMMIT();
    }

    for (int c = 0; c < nch; c++) {
        if (c + 1 < nch) CP_WAIT1(); else CP_WAIT0();
        __syncthreads();

        if (c + 2 < nch) {
            const uint32_t bs = (uint32_t)((c + 2) % 3);
            const int k0 = (c + 2) * 32;
            #pragma unroll
            for (int j = 0; j < 4; j++) {
                const __half* s = An + (size_t)(rb + srow[j]) * ld2a +
                                  ((sg[j] & 4) ? lda : 0) + k0 + (sg[j] & 3) * 8;
                CP_ASYNC16(sb + bs * STG_B + sdst[j], (const void*)s);
            }
            #pragma unroll
            for (int j = 0; j < 4; j++) {
                const __half* s = Bn + (size_t)(cb + srow[j]) * ld2b +
                                  ((sg[j] & 4) ? ldb : 0) + k0 + (sg[j] & 3) * 8;
                CP_ASYNC16(sb + bs * STG_B + 16384u + sdst[j], (const void*)s);
            }
            CP_COMMIT();
        }

        const uint32_t aB = sb + (uint32_t)(c % 3) * STG_B;
        const uint32_t bB = aB + 16384u;

        #pragma unroll
        for (int kk = 0; kk < 2; kk++) {
            // ---- batch ALL fragment loads up front (LSU pipelining) ----
            uint32_t bh[2][4], bl[2][4], ah[4][4], al[4][4];
            const int ghA = (kk << 1) + chA;
            const int ghB = (kk << 1) + chB;
            #pragma unroll
            for (int p = 0; p < 2; p++) {
                uint32_t h_ = bB + (uint32_t)((rBl + p * 16) * 128 + (ghB ^ s7) * 16);
                LDM_X4(bh[p][0], bh[p][1], bh[p][2], bh[p][3], h_);
            }
            #pragma unroll
            for (int p = 0; p < 2; p++) {
                uint32_t l_ = bB + (uint32_t)((rBl + p * 16) * 128 + ((4 + ghB) ^ s7) * 16);
                LDM_X4(bl[p][0], bl[p][1], bl[p][2], bl[p][3], l_);
            }
            #pragma unroll
            for (int mi = 0; mi < 4; mi++) {
                uint32_t h_ = aB + (uint32_t)((rAl + mi * 16) * 128 + (ghA ^ s7) * 16);
                LDM_X4(ah[mi][0], ah[mi][1], ah[mi][2], ah[mi][3], h_);
            }
            if (need_al) {
                #pragma unroll
                for (int mi = 0; mi < 4; mi++) {
                    uint32_t l_ = aB + (uint32_t)((rAl + mi * 16) * 128 + ((4 + ghA) ^ s7) * 16);
                    LDM_X4(al[mi][0], al[mi][1], al[mi][2], al[mi][3], l_);
                }
            }
            if (do_diag) {
                #pragma unroll
                for (int p = 0; p < 2; p++)
                    #pragma unroll
                    for (int q = 0; q < 4; q++) bh[p][q] = h2_half(bh[p][q]);
            }

            // ---- pass 1: Ah x Bh (16 MMAs, all-distinct accumulators) ----
            #pragma unroll
            for (int mi = 0; mi < 4; mi++)
                #pragma unroll
                for (int p = 0; p < 2; p++)
                    #pragma unroll
                    for (int q = 0; q < 2; q++)
                        MMA_FP16(acc[mi][p*2+q], ah[mi][0], ah[mi][1], ah[mi][2],
                                 ah[mi][3], bh[p][2*q], bh[p][2*q+1]);
            // ---- pass 2: Ah x Bl ----
            #pragma unroll
            for (int mi = 0; mi < 4; mi++)
                #pragma unroll
                for (int p = 0; p < 2; p++)
                    #pragma unroll
                    for (int q = 0; q < 2; q++)
                        MMA_FP16(acc[mi][p*2+q], ah[mi][0], ah[mi][1], ah[mi][2],
                                 ah[mi][3], bl[p][2*q], bl[p][2*q+1]);
            // ---- pass 3: Al x Bh (full 3-pass launches only) ----
            if (need_al) {
                #pragma unroll
                for (int mi = 0; mi < 4; mi++)
                    #pragma unroll
                    for (int p = 0; p < 2; p++)
                        #pragma unroll
                        for (int q = 0; q < 2; q++)
                            MMA_FP16(acc[mi][p*2+q], al[mi][0], al[mi][1], al[mi][2],
                                     al[mi][3], bh[p][2*q], bh[p][2*q+1]);
            }
        }
    }
    __syncthreads();

    // ---------------- epilogue ----------------
    const int g = lane >> 2, tig = lane & 3;
    float* stg = reinterpret_cast<float*>(smem);

    if (do_diag) {      // C_raw = acc + acc^T
        #pragma unroll
        for (int mi = 0; mi < 4; mi++)
            #pragma unroll
            for (int nj = 0; nj < 4; nj++) {
                const int cl = wn * 32 + nj * 8 + 2 * tig;
                #pragma unroll
                for (int h = 0; h < 2; h++) {
                    const int rl = wm * 64 + mi * 16 + g + 8 * h;
                    stg[rl * 129 + cl]     = acc[mi][nj][2 * h];
                    stg[rl * 129 + cl + 1] = acc[mi][nj][2 * h + 1];
                }
            }
        __syncthreads();
        #pragma unroll
        for (int mi = 0; mi < 4; mi++)
            #pragma unroll
            for (int nj = 0; nj < 4; nj++) {
                const int cl = wn * 32 + nj * 8 + 2 * tig;
                #pragma unroll
                for (int h = 0; h < 2; h++) {
                    const int rl = wm * 64 + mi * 16 + g + 8 * h;
                    acc[mi][nj][2 * h]     += stg[cl * 129 + rl];
                    acc[mi][nj][2 * h + 1] += stg[(cl + 1) * 129 + rl];
                }
            }
    }

    float ts = 0.f;
    if (mymode >= 2) ts = g_tr[n];
    const float sc2 = (mymode == 2) ? (-0.5f / ts) : 0.f;
    const float sc3 = (mymode == 3) ? rsqrtf(ts / (float)(MM - 1)) : 0.f;
    const __half* Dn = Dmat ? (Dmat + (size_t)n * sD) : nullptr;

    __half* Ch = nullptr;
    float*  Cf = nullptr;
    if (ofmt == 0) Ch = (__half*)(job ? C2out : Cout) + (size_t)n * sC;
    else           Cf = (float*)Cout + (size_t)n * sC;

    const bool do_t = sym && (rb != cb);
    if (do_t) __syncthreads();

    #pragma unroll
    for (int mi = 0; mi < 4; mi++) {
        #pragma unroll
        for (int nj = 0; nj < 4; nj++) {
            const int cl = wn * 32 + nj * 8 + 2 * tig;
            const int col = cb + cl;
            #pragma unroll
            for (int h = 0; h < 2; h++) {
                const int rl = wm * 64 + mi * 16 + g + 8 * h;
                const int row = rb + rl;
                float v0 = acc[mi][nj][2 * h];
                float v1 = acc[mi][nj][2 * h + 1];
                if (mymode == 1) {
                    const __half2 dh = *reinterpret_cast<const __half2*>(
                        Dn + (size_t)row * 2 * DD + col);
                    const __half2 dl = *reinterpret_cast<const __half2*>(
                        Dn + (size_t)row * 2 * DD + DD + col);
                    v0 -= 1.5f * (__half2float(dh.x) + __half2float(dl.x));
                    v1 -= 1.5f * (__half2float(dh.y) + __half2float(dl.y));
                    if (row == col)     v0 += 1.5f;
                    if (row == col + 1) v1 += 1.5f;
                } else if (mymode == 2) {
                    v0 *= sc2; v1 *= sc2;
                    if (row == col)     v0 += 1.5f;
                    if (row == col + 1) v1 += 1.5f;
                } else if (mymode == 3) {
                    v0 *= sc3; v1 *= sc3;
                }
                if (ofmt == 0) {
                    __half h0 = __float2half_rn(v0), h1 = __float2half_rn(v1);
                    __half l0 = __float2half_rn(v0 - __half2float(h0));
                    __half l1 = __float2half_rn(v1 - __half2float(h1));
                    *reinterpret_cast<__half2*>(Ch + (size_t)row * 2 * DD + col)
                        = __halves2half2(h0, h1);
                    *reinterpret_cast<__half2*>(Ch + (size_t)row * 2 * DD + DD + col)
                        = __halves2half2(l0, l1);
                } else {
                    *reinterpret_cast<float2*>(Cf + (size_t)row * DD + col) =
                        make_float2(v0, v1);
                }
                if (do_t) {
                    stg[rl * 129 + cl]     = v0;
                    stg[rl * 129 + cl + 1] = v1;
                }
            }
        }
    }

    if (do_t) {
        __syncthreads();
        const int r2    = tid >> 1;
        const int cbase = (tid & 1) * 64;
        __half* orow = Ch + (size_t)(cb + r2) * 2 * DD + rb + cbase;
        #pragma unroll
        for (int q = 0; q < 16; q++) {
            float w0 = stg[(cbase + q * 4 + 0) * 129 + r2];
            float w1 = stg[(cbase + q * 4 + 1) * 129 + r2];
            float w2 = stg[(cbase + q * 4 + 2) * 129 + r2];
            float w3 = stg[(cbase + q * 4 + 3) * 129 + r2];
            __half h0 = __float2half_rn(w0), h1 = __float2half_rn(w1);
            __half h2 = __float2half_rn(w2), h3 = __float2half_rn(w3);
            *reinterpret_cast<__half2*>(orow + q * 4)     = __halves2half2(h0, h1);
            *reinterpret_cast<__half2*>(orow + q * 4 + 2) = __halves2half2(h2, h3);
            __half l0 = __float2half_rn(w0 - __half2float(h0));
            __half l1 = __float2half_rn(w1 - __half2float(h1));
            __half l2 = __float2half_rn(w2 - __half2float(h2));
            __half l3 = __float2half_rn(w3 - __half2float(h3));
            *reinterpret_cast<__half2*>(orow + DD + q * 4)     = __halves2half2(l0, l1);
            *reinterpret_cast<__half2*>(orow + DD + q * 4 + 2) = __halves2half2(l2, l3);
        }
    }
}

// ======================= host launcher ======================================
extern "C" void kernel_launch(void* const* d_in, const int* in_sizes, int n_in,
                              void* d_out, int out_size) {
    const float* x = (const float*)d_in[0];
    float* out = (float*)d_out;

    __half *xn, *xnT, *Ba, *Bb, *Cm, *P0, *P1;
    cudaGetSymbolAddress((void**)&xn,  g_xn);
    cudaGetSymbolAddress((void**)&xnT, g_xnT);
    cudaGetSymbolAddress((void**)&Ba,  g_Ba);
    cudaGetSymbolAddress((void**)&Bb,  g_Bb);
    cudaGetSymbolAddress((void**)&Cm,  g_Cm);
    cudaGetSymbolAddress((void**)&P0,  g_P0);
    cudaGetSymbolAddress((void**)&P1,  g_P1);

    cudaFuncSetAttribute(gemm_h,
                         cudaFuncAttributeMaxDynamicSharedMemorySize, SMEM_DYN);

    const long long sM  = (long long)DD * 2 * DD;
    const long long sXT = (long long)DD * 2 * MM;
    const long long sXN = (long long)MM * 2 * DD;
    const long long sO  = (long long)MM * DD;
    const dim3 gSym(3, 1, NB);
    const dim3 gSym2(6, 1, NB);

    mean_kernel<<<NB, 256>>>(x);
    center_kernel<<<dim3(DD / 32, MM / 32, NB), dim3(32, 8)>>>(x);
    reduce_tr_kernel<<<NB, 128>>>();

    gemm_h<<<gSym, 256, SMEM_DYN>>>(Ba, xnT, xnT, nullptr, nullptr, nullptr,
                                    MM, MM, MM, sXT, sXT, sM, 0, 2, 1, 1, 1, 0);
    gemm_h<<<gSym, 256, SMEM_DYN>>>(Cm, Ba, Ba, nullptr, nullptr, nullptr,
                                    DD, DD, DD, sM, sM, sM, 0, 0, 1, 1, 1, 0);
    gemm_h<<<gSym, 256, SMEM_DYN>>>(Bb, Cm, Ba, Cm, nullptr, nullptr,
                                    DD, DD, DD, sM, sM, sM, sM, 1, 1, 0, 1, 0);
    gemm_h<<<gSym2, 256, SMEM_DYN>>>(Cm, Bb, Bb, nullptr, P0, Ba,
                                     DD, DD, DD, sM, sM, sM, 0, 0, 1, 1, 1, 0);
    gemm_h<<<gSym, 256, SMEM_DYN>>>(Ba, Cm, Bb, Cm, nullptr, nullptr,
                                    DD, DD, DD, sM, sM, sM, sM, 1, 1, 0, 1, 0);
    gemm_h<<<gSym2, 256, SMEM_DYN>>>(Cm, Ba, Ba, nullptr, P1, P0,
                                     DD, DD, DD, sM, sM, sM, 0, 0, 1, 1, 1, 0);
    gemm_h<<<gSym, 256, SMEM_DYN>>>(Bb, Cm, Ba, Cm, nullptr, nullptr,
                                    DD, DD, DD, sM, sM, sM, sM, 1, 1, 0, 1, 0);
    gemm_h<<<gSym, 256, SMEM_DYN>>>(P0, P1, Bb, nullptr, nullptr, nullptr,
                                    DD, DD, DD, sM, sM, sM, 0, 0, 1, 0, 0, 0);
    gemm_h<<<dim3(4, 2, NB), 256, SMEM_DYN>>>(out, xn, P0, nullptr, nullptr,
                                              nullptr, DD, DD, DD,
                                              sXN, sM, sO, 0, 3, 0, 0, 0, 1);
}

// round 11
// speedup vs baseline: 3.7999x; 1.0472x over previous
#include <cuda_runtime.h>
#include <cuda_fp16.h>
#include <cstdint>
#include <cstddef>

#define NB   256
#define MM   512
#define DD   256

// ======================= scratch (device globals) ===========================
// Matrices stored as split fp16: each row = [hi halves 0..C-1][lo halves].
__device__ __align__(256) float  g_mean[NB * DD];
__device__ __align__(256) float  g_tr  [NB];          // sumsq = trace*(M-1)
__device__ __align__(256) float  g_ssp [NB * 128];
__device__ __align__(256) __half g_xn  [NB * MM * 2 * DD];  // lo plane unused
__device__ __align__(256) __half g_xnT [NB * DD * 2 * MM];
__device__ __align__(256) __half g_Ba  [NB * DD * 2 * DD];
__device__ __align__(256) __half g_Bb  [NB * DD * 2 * DD];
__device__ __align__(256) __half g_Cm  [NB * DD * 2 * DD];
__device__ __align__(256) __half g_P0  [NB * DD * 2 * DD];
__device__ __align__(256) __half g_P1  [NB * DD * 2 * DD];

// ======================= PTX helpers ========================================
__device__ __forceinline__ uint32_t smem_u32(const void* p) {
    uint32_t a;
    asm("{ .reg .u64 t; cvta.to.shared.u64 t, %1; cvt.u32.u64 %0, t; }"
        : "=r"(a) : "l"(p));
    return a;
}

#define CP_ASYNC16(dst_u32, src_gptr) \
    asm volatile("cp.async.cg.shared.global [%0], [%1], 16;" \
                 :: "r"(dst_u32), "l"(src_gptr) : "memory")
#define CP_COMMIT() asm volatile("cp.async.commit_group;" ::: "memory")
#define CP_WAIT1()  asm volatile("cp.async.wait_group 1;" ::: "memory")
#define CP_WAIT0()  asm volatile("cp.async.wait_group 0;" ::: "memory")

#define LDM_X4(r0, r1, r2, r3, addr) \
    asm volatile("ldmatrix.sync.aligned.m8n8.x4.shared.b16 {%0,%1,%2,%3}, [%4];" \
                 : "=r"(r0), "=r"(r1), "=r"(r2), "=r"(r3) : "r"(addr))

#define MMA_FP16(d, a0, a1, a2, a3, b0, b1) \
    asm volatile("mma.sync.aligned.m16n8k16.row.col.f32.f16.f16.f32 " \
                 "{%0,%1,%2,%3}, {%4,%5,%6,%7}, {%8,%9}, {%0,%1,%2,%3};" \
                 : "+f"((d)[0]), "+f"((d)[1]), "+f"((d)[2]), "+f"((d)[3]) \
                 : "r"(a0), "r"(a1), "r"(a2), "r"(a3), "r"(b0), "r"(b1))

__device__ __forceinline__ uint32_t h2_half(uint32_t x) {   // *0.5 packed fp16x2
    uint32_t d;
    asm("mul.rn.f16x2 %0, %1, %2;" : "=r"(d) : "r"(x), "r"(0x38003800u));
    return d;
}

// packed split-fp16 store: hi = rn(v), lo = rn(v - hi); lo optional
__device__ __forceinline__ void split_store(__half2* hp, __half2* lp,
                                            float v0, float v1, bool wlo) {
    __half2 h = __float22half2_rn(make_float2(v0, v1));
    *hp = h;
    if (wlo) {
        float2 f = __half22float2(h);
        *lp = __float22half2_rn(make_float2(v0 - f.x, v1 - f.y));
    }
}

// ======================= mean over axis 1 ===================================
__global__ __launch_bounds__(256) void mean_kernel(const float* __restrict__ x) {
    int n = blockIdx.x, d = threadIdx.x;
    const float* xp = x + (size_t)n * MM * DD + d;
    float s0 = 0.f, s1 = 0.f, s2 = 0.f, s3 = 0.f;
    #pragma unroll 4
    for (int m = 0; m < MM; m += 4) {
        s0 += xp[(size_t)(m + 0) * DD];
        s1 += xp[(size_t)(m + 1) * DD];
        s2 += xp[(size_t)(m + 2) * DD];
        s3 += xp[(size_t)(m + 3) * DD];
    }
    g_mean[n * DD + d] = (s0 + s1 + s2 + s3) * (1.f / (float)MM);
}

// ==== center: xn hi-only (lo never read), xnT split, sumsq partials =========
__global__ __launch_bounds__(256) void center_kernel(const float* __restrict__ x) {
    const int n  = blockIdx.z;
    const int d0 = blockIdx.x * 32;
    const int m0 = blockIdx.y * 32;
    const int tx = threadIdx.x, ty = threadIdx.y;   // block (32, 8)

    __shared__ float tile[32][33];
    __shared__ float red[256];

    const int d = d0 + tx;
    const float mu = g_mean[n * DD + d];
    float ss = 0.f;
    #pragma unroll
    for (int r = 0; r < 4; r++) {
        int m = m0 + ty + r * 8;
        float v = x[(size_t)n * MM * DD + (size_t)m * DD + d] - mu;
        size_t base = (size_t)n * MM * 2 * DD + (size_t)m * 2 * DD;
        g_xn[base + d] = __float2half_rn(v);     // hi only; lo plane never read
        tile[ty + r * 8][tx] = v;
        ss += v * v;
    }
    __syncthreads();
    #pragma unroll
    for (int r = 0; r < 4; r++) {
        int dd_ = ty + r * 8;
        float v = tile[tx][dd_];
        __half hh = __float2half_rn(v);
        __half hl = __float2half_rn(v - __half2float(hh));
        size_t base = (size_t)n * DD * 2 * MM + (size_t)(d0 + dd_) * 2 * MM;
        g_xnT[base + m0 + tx]      = hh;
        g_xnT[base + MM + m0 + tx] = hl;
    }
    int t = ty * 32 + tx;
    red[t] = ss;
    __syncthreads();
    for (int s = 128; s > 0; s >>= 1) {
        if (t < s) red[t] += red[t + s];
        __syncthreads();
    }
    if (t == 0) g_ssp[n * 128 + blockIdx.y * 8 + blockIdx.x] = red[0];
}

__global__ __launch_bounds__(128) void reduce_tr_kernel() {
    int n = blockIdx.x, t = threadIdx.x;
    __shared__ float red[128];
    red[t] = g_ssp[n * 128 + t];
    __syncthreads();
    for (int s = 64; s > 0; s >>= 1) {
        if (t < s) red[t] += red[t + s];
        __syncthreads();
    }
    if (t == 0) g_tr[n] = red[0];
}

// ===================== fp16x3 mma.sync batched GEMM =========================
// 19 params: Cout,Amat,Bmat,Dmat,C2out,A2mat,lda,ldb,Ktot,sA,sB,sC,sD,
//            mode,sym,sqr,pass3,ofmt,wlo1
#define STG_B      32768u
#define SMEM_DYN   98304

__global__ __launch_bounds__(256, 2) void gemm_h(
    void* __restrict__ Cout, const __half* __restrict__ Amat,
    const __half* __restrict__ Bmat, const __half* __restrict__ Dmat,
    void* __restrict__ C2out, const __half* __restrict__ A2mat,
    int lda, int ldb, int Ktot,
    long long sA, long long sB, long long sC, long long sD,
    int mode, int sym, int sqr, int pass3, int ofmt, int wlo1)
{
    extern __shared__ char smem[];
    const uint32_t sb = smem_u32(smem);

    const int tid  = threadIdx.x;
    const int wid  = tid >> 5, lane = tid & 31;
    const int wm   = wid & 1;
    const int wn   = wid >> 1;
    const int n    = blockIdx.z;

    int ti, tj, job = 0, mymode = mode;
    if (sym) {
        int tt = blockIdx.x;
        if (tt >= 3) { job = 1; tt -= 3; mymode = 0; }
        ti = (tt == 2) ? 1 : 0; tj = (tt != 0) ? 1 : 0;
    } else {
        ti = blockIdx.x; tj = blockIdx.y;
    }
    const int rb = ti * 128;
    const int cb = tj * 128;

    const bool do_diag = sqr && sym && (job == 0) && (ti == tj);
    const bool need_al = (pass3 != 0) && !do_diag;
    const bool wlo     = job ? (wlo1 != 0) : true;

    const __half* An = (job ? A2mat : Amat) + (size_t)n * sA;
    const __half* Bn = Bmat + (size_t)n * sB;

    const int ld2a = 2 * lda, ld2b = 2 * ldb;

    int srow[4], sg[4];
    uint32_t sdst[4];
    #pragma unroll
    for (int j = 0; j < 4; j++) {
        int idx = tid + 256 * j;
        srow[j] = idx >> 3;
        sg[j]   = idx & 7;
        sdst[j] = (uint32_t)(srow[j] * 128 + ((sg[j] ^ (srow[j] & 7)) << 4));
    }
    // sg[j] == tid & 7 for all j: one uniform predicate picks hi vs lo stagers.
    const bool a_stager = need_al || ((tid & 7) < 4);

    const int t  = lane >> 3, s7 = lane & 7;
    const int chA = t >> 1;
    const int rAl = wm * 64 + (t & 1) * 8 + s7;
    const int chB = t & 1;
    const int rBl = wn * 32 + (t >> 1) * 8 + s7;

    float acc[4][4][4];
    #pragma unroll
    for (int i = 0; i < 4; i++)
        #pragma unroll
        for (int j = 0; j < 4; j++)
            #pragma unroll
            for (int q = 0; q < 4; q++) acc[i][j][q] = 0.f;

    const int nch = Ktot >> 5;

    #pragma unroll
    for (int pc = 0; pc < 2; pc++) {
        const int k0 = pc * 32;
        if (a_stager) {
            #pragma unroll
            for (int j = 0; j < 4; j++) {
                const __half* s = An + (size_t)(rb + srow[j]) * ld2a +
                                  ((sg[j] & 4) ? lda : 0) + k0 + (sg[j] & 3) * 8;
                CP_ASYNC16(sb + pc * STG_B + sdst[j], (const void*)s);
            }
        }
        #pragma unroll
        for (int j = 0; j < 4; j++) {
            const __half* s = Bn + (size_t)(cb + srow[j]) * ld2b +
                              ((sg[j] & 4) ? ldb : 0) + k0 + (sg[j] & 3) * 8;
            CP_ASYNC16(sb + pc * STG_B + 16384u + sdst[j], (const void*)s);
        }
        CP_COMMIT();
    }

    for (int c = 0; c < nch; c++) {
        if (c + 1 < nch) CP_WAIT1(); else CP_WAIT0();
        __syncthreads();

        if (c + 2 < nch) {
            const uint32_t bs = (uint32_t)((c + 2) % 3);
            const int k0 = (c + 2) * 32;
            if (a_stager) {
                #pragma unroll
                for (int j = 0; j < 4; j++) {
                    const __half* s = An + (size_t)(rb + srow[j]) * ld2a +
                                      ((sg[j] & 4) ? lda : 0) + k0 + (sg[j] & 3) * 8;
                    CP_ASYNC16(sb + bs * STG_B + sdst[j], (const void*)s);
                }
            }
            #pragma unroll
            for (int j = 0; j < 4; j++) {
                const __half* s = Bn + (size_t)(cb + srow[j]) * ld2b +
                                  ((sg[j] & 4) ? ldb : 0) + k0 + (sg[j] & 3) * 8;
                CP_ASYNC16(sb + bs * STG_B + 16384u + sdst[j], (const void*)s);
            }
            CP_COMMIT();
        }

        const uint32_t aB = sb + (uint32_t)(c % 3) * STG_B;
        const uint32_t bB = aB + 16384u;

        #pragma unroll
        for (int kk = 0; kk < 2; kk++) {
            uint32_t bh[2][4], bl[2][4], ah[4][4], al[4][4];
            const int ghA = (kk << 1) + chA;
            const int ghB = (kk << 1) + chB;
            #pragma unroll
            for (int p = 0; p < 2; p++) {
                uint32_t h_ = bB + (uint32_t)((rBl + p * 16) * 128 + (ghB ^ s7) * 16);
                LDM_X4(bh[p][0], bh[p][1], bh[p][2], bh[p][3], h_);
            }
            #pragma unroll
            for (int p = 0; p < 2; p++) {
                uint32_t l_ = bB + (uint32_t)((rBl + p * 16) * 128 + ((4 + ghB) ^ s7) * 16);
                LDM_X4(bl[p][0], bl[p][1], bl[p][2], bl[p][3], l_);
            }
            #pragma unroll
            for (int mi = 0; mi < 4; mi++) {
                uint32_t h_ = aB + (uint32_t)((rAl + mi * 16) * 128 + (ghA ^ s7) * 16);
                LDM_X4(ah[mi][0], ah[mi][1], ah[mi][2], ah[mi][3], h_);
            }
            if (need_al) {
                #pragma unroll
                for (int mi = 0; mi < 4; mi++) {
                    uint32_t l_ = aB + (uint32_t)((rAl + mi * 16) * 128 + ((4 + ghA) ^ s7) * 16);
                    LDM_X4(al[mi][0], al[mi][1], al[mi][2], al[mi][3], l_);
                }
            }
            if (do_diag) {
                #pragma unroll
                for (int p = 0; p < 2; p++)
                    #pragma unroll
                    for (int q = 0; q < 4; q++) bh[p][q] = h2_half(bh[p][q]);
            }

            #pragma unroll
            for (int mi = 0; mi < 4; mi++)
                #pragma unroll
                for (int p = 0; p < 2; p++)
                    #pragma unroll
                    for (int q = 0; q < 2; q++)
                        MMA_FP16(acc[mi][p*2+q], ah[mi][0], ah[mi][1], ah[mi][2],
                                 ah[mi][3], bh[p][2*q], bh[p][2*q+1]);
            #pragma unroll
            for (int mi = 0; mi < 4; mi++)
                #pragma unroll
                for (int p = 0; p < 2; p++)
                    #pragma unroll
                    for (int q = 0; q < 2; q++)
                        MMA_FP16(acc[mi][p*2+q], ah[mi][0], ah[mi][1], ah[mi][2],
                                 ah[mi][3], bl[p][2*q], bl[p][2*q+1]);
            if (need_al) {
                #pragma unroll
                for (int mi = 0; mi < 4; mi++)
                    #pragma unroll
                    for (int p = 0; p < 2; p++)
                        #pragma unroll
                        for (int q = 0; q < 2; q++)
                            MMA_FP16(acc[mi][p*2+q], al[mi][0], al[mi][1], al[mi][2],
                                     al[mi][3], bh[p][2*q], bh[p][2*q+1]);
            }
        }
    }
    __syncthreads();

    // ---------------- epilogue ----------------
    const int g = lane >> 2, tig = lane & 3;
    float* stg = reinterpret_cast<float*>(smem);

    if (do_diag) {      // C_raw = acc + acc^T
        #pragma unroll
        for (int mi = 0; mi < 4; mi++)
            #pragma unroll
            for (int nj = 0; nj < 4; nj++) {
                const int cl = wn * 32 + nj * 8 + 2 * tig;
                #pragma unroll
                for (int h = 0; h < 2; h++) {
                    const int rl = wm * 64 + mi * 16 + g + 8 * h;
                    stg[rl * 129 + cl]     = acc[mi][nj][2 * h];
                    stg[rl * 129 + cl + 1] = acc[mi][nj][2 * h + 1];
                }
            }
        __syncthreads();
        #pragma unroll
        for (int mi = 0; mi < 4; mi++)
            #pragma unroll
            for (int nj = 0; nj < 4; nj++) {
                const int cl = wn * 32 + nj * 8 + 2 * tig;
                #pragma unroll
                for (int h = 0; h < 2; h++) {
                    const int rl = wm * 64 + mi * 16 + g + 8 * h;
                    acc[mi][nj][2 * h]     += stg[cl * 129 + rl];
                    acc[mi][nj][2 * h + 1] += stg[(cl + 1) * 129 + rl];
                }
            }
    }

    float ts = 0.f;
    if (mymode >= 2) ts = g_tr[n];
    const float sc2 = (mymode == 2) ? (-0.5f / ts) : 0.f;
    const float sc3 = (mymode == 3) ? rsqrtf(ts / (float)(MM - 1)) : 0.f;
    const __half* Dn = Dmat ? (Dmat + (size_t)n * sD) : nullptr;

    __half* Ch = nullptr;
    float*  Cf = nullptr;
    if (ofmt == 0) Ch = (__half*)(job ? C2out : Cout) + (size_t)n * sC;
    else           Cf = (float*)Cout + (size_t)n * sC;

    const bool do_t = sym && (rb != cb);
    if (do_t) __syncthreads();

    #pragma unroll
    for (int mi = 0; mi < 4; mi++) {
        #pragma unroll
        for (int nj = 0; nj < 4; nj++) {
            const int cl = wn * 32 + nj * 8 + 2 * tig;
            const int col = cb + cl;
            #pragma unroll
            for (int h = 0; h < 2; h++) {
                const int rl = wm * 64 + mi * 16 + g + 8 * h;
                const int row = rb + rl;
                float v0 = acc[mi][nj][2 * h];
                float v1 = acc[mi][nj][2 * h + 1];
                if (mymode == 1) {
                    const float2 dh = __half22float2(*reinterpret_cast<const __half2*>(
                        Dn + (size_t)row * 2 * DD + col));
                    const float2 dl = __half22float2(*reinterpret_cast<const __half2*>(
                        Dn + (size_t)row * 2 * DD + DD + col));
                    v0 -= 1.5f * (dh.x + dl.x);
                    v1 -= 1.5f * (dh.y + dl.y);
                    if (row == col)     v0 += 1.5f;
                    if (row == col + 1) v1 += 1.5f;
                } else if (mymode == 2) {
                    v0 *= sc2; v1 *= sc2;
                    if (row == col)     v0 += 1.5f;
                    if (row == col + 1) v1 += 1.5f;
                } else if (mymode == 3) {
                    v0 *= sc3; v1 *= sc3;
                }
                if (ofmt == 0) {
                    split_store(
                        reinterpret_cast<__half2*>(Ch + (size_t)row * 2 * DD + col),
                        reinterpret_cast<__half2*>(Ch + (size_t)row * 2 * DD + DD + col),
                        v0, v1, wlo);
                } else {
                    *reinterpret_cast<float2*>(Cf + (size_t)row * DD + col) =
                        make_float2(v0, v1);
                }
                if (do_t) {
                    stg[rl * 129 + cl]     = v0;
                    stg[rl * 129 + cl + 1] = v1;
                }
            }
        }
    }

    if (do_t) {
        __syncthreads();
        const int r2    = tid >> 1;
        const int cbase = (tid & 1) * 64;
        __half* orow = Ch + (size_t)(cb + r2) * 2 * DD + rb + cbase;
        #pragma unroll
        for (int q = 0; q < 8; q++) {
            float w0 = stg[(cbase + q * 8 + 0) * 129 + r2];
            float w1 = stg[(cbase + q * 8 + 1) * 129 + r2];
            float w2 = stg[(cbase + q * 8 + 2) * 129 + r2];
            float w3 = stg[(cbase + q * 8 + 3) * 129 + r2];
            float w4 = stg[(cbase + q * 8 + 4) * 129 + r2];
            float w5 = stg[(cbase + q * 8 + 5) * 129 + r2];
            float w6 = stg[(cbase + q * 8 + 6) * 129 + r2];
            float w7 = stg[(cbase + q * 8 + 7) * 129 + r2];
            split_store(reinterpret_cast<__half2*>(orow + q * 8),
                        reinterpret_cast<__half2*>(orow + DD + q * 8), w0, w1, wlo);
            split_store(reinterpret_cast<__half2*>(orow + q * 8 + 2),
                        reinterpret_cast<__half2*>(orow + DD + q * 8 + 2), w2, w3, wlo);
            split_store(reinterpret_cast<__half2*>(orow + q * 8 + 4),
                        reinterpret_cast<__half2*>(orow + DD + q * 8 + 4), w4, w5, wlo);
            split_store(reinterpret_cast<__half2*>(orow + q * 8 + 6),
                        reinterpret_cast<__half2*>(orow + DD + q * 8 + 6), w6, w7, wlo);
        }
    }
}

// ======================= host launcher ======================================
extern "C" void kernel_launch(void* const* d_in, const int* in_sizes, int n_in,
                              void* d_out, int out_size) {
    const float* x = (const float*)d_in[0];
    float* out = (float*)d_out;

    __half *xn, *xnT, *Ba, *Bb, *Cm, *P0, *P1;
    cudaGetSymbolAddress((void**)&xn,  g_xn);
    cudaGetSymbolAddress((void**)&xnT, g_xnT);
    cudaGetSymbolAddress((void**)&Ba,  g_Ba);
    cudaGetSymbolAddress((void**)&Bb,  g_Bb);
    cudaGetSymbolAddress((void**)&Cm,  g_Cm);
    cudaGetSymbolAddress((void**)&P0,  g_P0);
    cudaGetSymbolAddress((void**)&P1,  g_P1);

    cudaFuncSetAttribute(gemm_h,
                         cudaFuncAttributeMaxDynamicSharedMemorySize, SMEM_DYN);

    const long long sM  = (long long)DD * 2 * DD;
    const long long sXT = (long long)DD * 2 * MM;
    const long long sXN = (long long)MM * 2 * DD;
    const long long sO  = (long long)MM * DD;
    const dim3 gSym(3, 1, NB);
    const dim3 gSym2(6, 1, NB);

    mean_kernel<<<NB, 256>>>(x);
    center_kernel<<<dim3(DD / 32, MM / 32, NB), dim3(32, 8)>>>(x);
    reduce_tr_kernel<<<NB, 128>>>();

    // args: C, A, B, D, C2, A2, lda, ldb, K, sA, sB, sC, sD,
    //       mode, sym, sqr, pass3, ofmt, wlo1

    // sigma -> Ba = B0   [K=512, sym, squaring, 3-pass]
    gemm_h<<<gSym, 256, SMEM_DYN>>>(Ba, xnT, xnT, nullptr, nullptr, nullptr,
                                    MM, MM, MM, sXT, sXT, sM, 0,
                                    2, 1, 1, 1, 0, 1);
    // iter 1: Cm = B0^2 (squaring)
    gemm_h<<<gSym, 256, SMEM_DYN>>>(Cm, Ba, Ba, nullptr, nullptr, nullptr,
                                    DD, DD, DD, sM, sM, sM, 0,
                                    0, 1, 1, 1, 0, 1);
    //          Bb = Cm*B0 - 1.5Cm + 1.5I  (B1)
    gemm_h<<<gSym, 256, SMEM_DYN>>>(Bb, Cm, Ba, Cm, nullptr, nullptr,
                                    DD, DD, DD, sM, sM, sM, sM,
                                    1, 1, 0, 1, 0, 1);
    // iter 2: {Cm = B1^2 (squaring) , P0 = B0*B1 (P2)}
    gemm_h<<<gSym2, 256, SMEM_DYN>>>(Cm, Bb, Bb, nullptr, P0, Ba,
                                     DD, DD, DD, sM, sM, sM, 0,
                                     0, 1, 1, 1, 0, 1);
    //          Ba = Cm*B1 - 1.5Cm + 1.5I  (B2)
    gemm_h<<<gSym, 256, SMEM_DYN>>>(Ba, Cm, Bb, Cm, nullptr, nullptr,
                                    DD, DD, DD, sM, sM, sM, sM,
                                    1, 1, 0, 1, 0, 1);
    // iter 3: {Cm = B2^2 (squaring) , P1 = P2*B2 (P3, lo plane dead)}
    gemm_h<<<gSym2, 256, SMEM_DYN>>>(Cm, Ba, Ba, nullptr, P1, P0,
                                     DD, DD, DD, sM, sM, sM, 0,
                                     0, 1, 1, 1, 0, 0);
    //          Bb = Cm*B2 - 1.5Cm + 1.5I  (B3)
    gemm_h<<<gSym, 256, SMEM_DYN>>>(Bb, Cm, Ba, Cm, nullptr, nullptr,
                                    DD, DD, DD, sM, sM, sM, sM,
                                    1, 1, 0, 1, 0, 1);
    // iter 4: P0 = P3*B3 (P4) — 2-pass, A-lo not staged
    gemm_h<<<gSym, 256, SMEM_DYN>>>(P0, P1, Bb, nullptr, nullptr, nullptr,
                                    DD, DD, DD, sM, sM, sM, 0,
                                    0, 1, 0, 0, 0, 1);
    // final: out = xn*P4*rsqrt(sumsq/(M-1)) — 2-pass, A-lo not staged, fp32 out
    gemm_h<<<dim3(4, 2, NB), 256, SMEM_DYN>>>(out, xn, P0, nullptr, nullptr,
                                              nullptr, DD, DD, DD,
                                              sXN, sM, sO, 0,
                                              3, 0, 0, 0, 1, 1);
}

// round 12
// speedup vs baseline: 5.5927x; 1.4718x over previous
#include <cuda_runtime.h>
#include <cuda_fp16.h>
#include <cstdint>
#include <cstddef>

#define NB   256
#define MM   512
#define DD   256

// ======================= scratch (device globals) ===========================
// Split-fp16 matrices stored as 16KB PANELS: panel(pr,pc) = rows pr*128..+127,
// K-cols pc*32..+31. Panel layout = exact smem image: row r at offset r*128,
// 8 x 16B groups (4 hi + 4 lo), group g stored at ((g ^ (r&7))<<4).
__device__ __align__(256) float  g_mean[NB * DD];
__device__ __align__(256) float  g_tr  [NB];
__device__ __align__(256) float  g_ssp [NB * 128];
__device__ __align__(256) __half g_xn  [NB * MM * 2 * DD];  // 4x8 panels/batch
__device__ __align__(256) __half g_xnT [NB * DD * 2 * MM];  // 2x16 panels
__device__ __align__(256) __half g_Ba  [NB * DD * 2 * DD];  // 2x8 panels
__device__ __align__(256) __half g_Bb  [NB * DD * 2 * DD];
__device__ __align__(256) __half g_Cm  [NB * DD * 2 * DD];
__device__ __align__(256) __half g_P0  [NB * DD * 2 * DD];
__device__ __align__(256) __half g_P1  [NB * DD * 2 * DD];

// ======================= PTX helpers ========================================
__device__ __forceinline__ uint32_t smem_u32(const void* p) {
    uint32_t a;
    asm("{ .reg .u64 t; cvta.to.shared.u64 t, %1; cvt.u32.u64 %0, t; }"
        : "=r"(a) : "l"(p));
    return a;
}

#define CP_BULK(dst_u32, src_gptr, bytes, mbar) \
    asm volatile("cp.async.bulk.shared::cluster.global.mbarrier::complete_tx::bytes " \
                 "[%0], [%1], %2, [%3];" \
                 :: "r"(dst_u32), "l"((const void*)(src_gptr)), \
                    "r"((uint32_t)(bytes)), "r"(mbar) : "memory")

#define MBARRIER_INIT(mbar, count) \
    asm volatile("mbarrier.init.shared.b64 [%0], %1;" \
                 :: "r"((uint32_t)(mbar)), "r"((uint32_t)(count)) : "memory")
#define MBARRIER_EXPECT_TX(mbar, tx) \
    asm volatile("mbarrier.arrive.expect_tx.shared.b64 _, [%0], %1;" \
                 :: "r"((uint32_t)(mbar)), "r"((uint32_t)(tx)) : "memory")
#define MBARRIER_WAIT_PARITY(mbar_addr, phase_parity) do {                    \
    uint32_t _mbar = (uint32_t)(mbar_addr);                                   \
    uint32_t _parity = (uint32_t)(phase_parity);                              \
    uint32_t _done;                                                           \
    asm volatile(                                                             \
        "{\n\t.reg .pred p;\n\t"                                              \
        "mbarrier.try_wait.parity.acquire.cta.shared::cta.b64 p, [%1], %2;\n\t" \
        "selp.b32 %0, 1, 0, p;\n\t}"                                          \
        : "=r"(_done) : "r"(_mbar), "r"(_parity) : "memory");                 \
    if (!_done) {                                                             \
        asm volatile(                                                         \
            "{\n\t.reg .pred P1;\n\t"                                         \
            "WAIT_LOOP_%=:\n\t"                                               \
            "mbarrier.try_wait.parity.acquire.cta.shared::cta.b64 P1, [%0], %1, 0x989680;\n\t" \
            "@P1 bra.uni WAIT_DONE_%=;\n\t"                                   \
            "bra.uni WAIT_LOOP_%=;\n\t"                                       \
            "WAIT_DONE_%=:\n\t}"                                              \
            :: "r"(_mbar), "r"(_parity) : "memory");                          \
    }                                                                         \
} while (0)

#define LDM_X4(r0, r1, r2, r3, addr) \
    asm volatile("ldmatrix.sync.aligned.m8n8.x4.shared.b16 {%0,%1,%2,%3}, [%4];" \
                 : "=r"(r0), "=r"(r1), "=r"(r2), "=r"(r3) : "r"(addr))

#define MMA_FP16(d, a0, a1, a2, a3, b0, b1) \
    asm volatile("mma.sync.aligned.m16n8k16.row.col.f32.f16.f16.f32 " \
                 "{%0,%1,%2,%3}, {%4,%5,%6,%7}, {%8,%9}, {%0,%1,%2,%3};" \
                 : "+f"((d)[0]), "+f"((d)[1]), "+f"((d)[2]), "+f"((d)[3]) \
                 : "r"(a0), "r"(a1), "r"(a2), "r"(a3), "r"(b0), "r"(b1))

__device__ __forceinline__ uint32_t h2_half(uint32_t x) {   // *0.5 packed fp16x2
    uint32_t d;
    asm("mul.rn.f16x2 %0, %1, %2;" : "=r"(d) : "r"(x), "r"(0x38003800u));
    return d;
}
__device__ __forceinline__ uint32_t h2_bits(__half2 h) {
    return *reinterpret_cast<uint32_t*>(&h);
}

// ======================= mean over axis 1 ===================================
__global__ __launch_bounds__(256) void mean_kernel(const float* __restrict__ x) {
    int n = blockIdx.x, d = threadIdx.x;
    const float* xp = x + (size_t)n * MM * DD + d;
    float s0 = 0.f, s1 = 0.f, s2 = 0.f, s3 = 0.f;
    #pragma unroll 4
    for (int m = 0; m < MM; m += 4) {
        s0 += xp[(size_t)(m + 0) * DD];
        s1 += xp[(size_t)(m + 1) * DD];
        s2 += xp[(size_t)(m + 2) * DD];
        s3 += xp[(size_t)(m + 3) * DD];
    }
    g_mean[n * DD + d] = (s0 + s1 + s2 + s3) * (1.f / (float)MM);
}

// ==== center: xn hi-only panels, xnT split panels, sumsq partials ===========
__global__ __launch_bounds__(256) void center_kernel(const float* __restrict__ x) {
    const int n  = blockIdx.z;
    const int d0 = blockIdx.x * 32;
    const int m0 = blockIdx.y * 32;
    const int tx = threadIdx.x, ty = threadIdx.y;   // block (32, 8)

    __shared__ float tile[32][33];
    __shared__ float red[256];

    char* xb  = (char*)(g_xn  + (size_t)n * MM * 2 * DD);
    char* xtb = (char*)(g_xnT + (size_t)n * DD * 2 * MM);

    const int d = d0 + tx;
    const float mu = g_mean[n * DD + d];
    float ss = 0.f;
    #pragma unroll
    for (int r = 0; r < 4; r++) {
        int m = m0 + ty + r * 8;
        float v = x[(size_t)n * MM * DD + (size_t)m * DD + d] - mu;
        // xn panel (npr=4, npc=8): pr=m>>7, pc=d0>>5
        size_t pan = ((size_t)(m >> 7) * 8 + (d0 >> 5)) * 16384u;
        int rr = m & 127;
        uint32_t off = (uint32_t)(rr * 128 +
                        ((((d >> 3) & 3) ^ (rr & 7)) << 4) + (d & 7) * 2);
        *(__half*)(xb + pan + off) = __float2half_rn(v);
        tile[ty + r * 8][tx] = v;
        ss += v * v;
    }
    __syncthreads();
    #pragma unroll
    for (int r = 0; r < 4; r++) {
        int dd_ = ty + r * 8;
        float v = tile[tx][dd_];
        __half hh = __float2half_rn(v);
        __half hl = __float2half_rn(v - __half2float(hh));
        // xnT panel (npr=2, npc=16): pr=(d0+dd_)>>7, pc=m0>>5
        int dg = d0 + dd_, mg = m0 + tx;
        size_t pan = ((size_t)(dg >> 7) * 16 + (mg >> 5)) * 16384u;
        int rr = dg & 127;
        uint32_t gh = (uint32_t)((mg >> 3) & 3);
        uint32_t ohi = (uint32_t)(rr * 128 + ((gh ^ (rr & 7)) << 4) + (mg & 7) * 2);
        uint32_t olo = (uint32_t)(rr * 128 + (((4 + gh) ^ (rr & 7)) << 4) + (mg & 7) * 2);
        *(__half*)(xtb + pan + ohi) = hh;
        *(__half*)(xtb + pan + olo) = hl;
    }
    int t = ty * 32 + tx;
    red[t] = ss;
    __syncthreads();
    for (int s = 128; s > 0; s >>= 1) {
        if (t < s) red[t] += red[t + s];
        __syncthreads();
    }
    if (t == 0) g_ssp[n * 128 + blockIdx.y * 8 + blockIdx.x] = red[0];
}

__global__ __launch_bounds__(128) void reduce_tr_kernel() {
    int n = blockIdx.x, t = threadIdx.x;
    __shared__ float red[128];
    red[t] = g_ssp[n * 128 + t];
    __syncthreads();
    for (int s = 64; s > 0; s >>= 1) {
        if (t < s) red[t] += red[t + s];
        __syncthreads();
    }
    if (t == 0) g_tr[n] = red[0];
}

// ===================== fp16x3 mma.sync batched GEMM, bulk-copy panels =======
// 17 params: Cout,Amat,Bmat,Dmat,C2out,A2mat,Ktot,sA,sB,sC,sD,
//            mode,sym,sqr,pass3,ofmt,wlo1
#define STG_B      32768u
#define MBAR_OFF   98304u
#define SMEM_DYN   98432

__global__ __launch_bounds__(256, 2) void gemm_h(
    void* __restrict__ Cout, const __half* __restrict__ Amat,
    const __half* __restrict__ Bmat, const __half* __restrict__ Dmat,
    void* __restrict__ C2out, const __half* __restrict__ A2mat,
    int Ktot, long long sA, long long sB, long long sC, long long sD,
    int mode, int sym, int sqr, int pass3, int ofmt, int wlo1)
{
    extern __shared__ char smem[];
    const uint32_t sb  = smem_u32(smem);
    const uint32_t mb0 = sb + MBAR_OFF;

    const int tid  = threadIdx.x;
    const int wid  = tid >> 5, lane = tid & 31;
    const int wm   = wid & 1;
    const int wn   = wid >> 1;
    const int n    = blockIdx.z;

    int ti, tj, job = 0, mymode = mode;
    if (sym) {
        int tt = blockIdx.x;
        if (tt >= 3) { job = 1; tt -= 3; mymode = 0; }
        ti = (tt == 2) ? 1 : 0; tj = (tt != 0) ? 1 : 0;
    } else {
        ti = blockIdx.x; tj = blockIdx.y;
    }
    const int rb = ti * 128;
    const int cb = tj * 128;

    const bool do_diag = sqr && sym && (job == 0) && (ti == tj);
    const bool need_al = (pass3 != 0) && !do_diag;
    const bool wlo     = job ? (wlo1 != 0) : true;

    const __half* An = (job ? A2mat : Amat) + (size_t)n * sA;
    const __half* Bn = Bmat + (size_t)n * sB;

    const int nch = Ktot >> 5;                 // panels per row-block
    const size_t aprow = (size_t)ti * nch * 16384u;
    const size_t bprow = (size_t)tj * nch * 16384u;

    if (tid == 0) {
        MBARRIER_INIT(mb0,      1);
        MBARRIER_INIT(mb0 + 8,  1);
        MBARRIER_INIT(mb0 + 16, 1);
    }
    __syncthreads();

    if (tid == 0) {
        #pragma unroll
        for (int pc_ = 0; pc_ < 2; pc_++) {
            uint32_t mbar = mb0 + (uint32_t)pc_ * 8u;
            uint32_t dst  = sb + (uint32_t)pc_ * STG_B;
            const char* sa = (const char*)An + aprow + (size_t)pc_ * 16384u;
            const char* sp = (const char*)Bn + bprow + (size_t)pc_ * 16384u;
            if (do_diag) {
                MBARRIER_EXPECT_TX(mbar, 16384u);
                CP_BULK(dst, sa, 16384u, mbar);
            } else {
                MBARRIER_EXPECT_TX(mbar, 32768u);
                CP_BULK(dst, sa, 16384u, mbar);
                CP_BULK(dst + 16384u, sp, 16384u, mbar);
            }
        }
    }

    // ldmatrix lane geometry
    const int t  = lane >> 3, s7 = lane & 7;
    const int chA = t >> 1;
    const int rAl = wm * 64 + (t & 1) * 8 + s7;
    const int chB = t & 1;
    const int rBl = wn * 32 + (t >> 1) * 8 + s7;

    float acc[4][4][4];
    #pragma unroll
    for (int i = 0; i < 4; i++)
        #pragma unroll
        for (int j = 0; j < 4; j++)
            #pragma unroll
            for (int q = 0; q < 4; q++) acc[i][j][q] = 0.f;

    for (int c = 0; c < nch; c++) {
        const int s = c % 3;
        MBARRIER_WAIT_PARITY(mb0 + (uint32_t)s * 8u, (c / 3) & 1);
        __syncthreads();   // all warps done with chunk c-1's buffer

        if (c + 2 < nch && tid == 0) {
            const int c2 = c + 2, s2 = c2 % 3;
            uint32_t mbar = mb0 + (uint32_t)s2 * 8u;
            uint32_t dst  = sb + (uint32_t)s2 * STG_B;
            const char* sa = (const char*)An + aprow + (size_t)c2 * 16384u;
            const char* sp = (const char*)Bn + bprow + (size_t)c2 * 16384u;
            if (do_diag) {
                MBARRIER_EXPECT_TX(mbar, 16384u);
                CP_BULK(dst, sa, 16384u, mbar);
            } else {
                MBARRIER_EXPECT_TX(mbar, 32768u);
                CP_BULK(dst, sa, 16384u, mbar);
                CP_BULK(dst + 16384u, sp, 16384u, mbar);
            }
        }

        const uint32_t aB = sb + (uint32_t)s * STG_B;
        const uint32_t bB = do_diag ? aB : (aB + 16384u);

        #pragma unroll
        for (int kk = 0; kk < 2; kk++) {
            uint32_t bh[2][4], bl[2][4], ah[4][4], al[4][4];
            const int ghA = (kk << 1) + chA;
            const int ghB = (kk << 1) + chB;
            #pragma unroll
            for (int p = 0; p < 2; p++) {
                uint32_t h_ = bB + (uint32_t)((rBl + p * 16) * 128 + (ghB ^ s7) * 16);
                LDM_X4(bh[p][0], bh[p][1], bh[p][2], bh[p][3], h_);
            }
            #pragma unroll
            for (int p = 0; p < 2; p++) {
                uint32_t l_ = bB + (uint32_t)((rBl + p * 16) * 128 + ((4 + ghB) ^ s7) * 16);
                LDM_X4(bl[p][0], bl[p][1], bl[p][2], bl[p][3], l_);
            }
            #pragma unroll
            for (int mi = 0; mi < 4; mi++) {
                uint32_t h_ = aB + (uint32_t)((rAl + mi * 16) * 128 + (ghA ^ s7) * 16);
                LDM_X4(ah[mi][0], ah[mi][1], ah[mi][2], ah[mi][3], h_);
            }
            if (need_al) {
                #pragma unroll
                for (int mi = 0; mi < 4; mi++) {
                    uint32_t l_ = aB + (uint32_t)((rAl + mi * 16) * 128 + ((4 + ghA) ^ s7) * 16);
                    LDM_X4(al[mi][0], al[mi][1], al[mi][2], al[mi][3], l_);
                }
            }
            if (do_diag) {
                #pragma unroll
                for (int p = 0; p < 2; p++)
                    #pragma unroll
                    for (int q = 0; q < 4; q++) bh[p][q] = h2_half(bh[p][q]);
            }

            #pragma unroll
            for (int mi = 0; mi < 4; mi++)
                #pragma unroll
                for (int p = 0; p < 2; p++)
                    #pragma unroll
                    for (int q = 0; q < 2; q++)
                        MMA_FP16(acc[mi][p*2+q], ah[mi][0], ah[mi][1], ah[mi][2],
                                 ah[mi][3], bh[p][2*q], bh[p][2*q+1]);
            #pragma unroll
            for (int mi = 0; mi < 4; mi++)
                #pragma unroll
                for (int p = 0; p < 2; p++)
                    #pragma unroll
                    for (int q = 0; q < 2; q++)
                        MMA_FP16(acc[mi][p*2+q], ah[mi][0], ah[mi][1], ah[mi][2],
                                 ah[mi][3], bl[p][2*q], bl[p][2*q+1]);
            if (need_al) {
                #pragma unroll
                for (int mi = 0; mi < 4; mi++)
                    #pragma unroll
                    for (int p = 0; p < 2; p++)
                        #pragma unroll
                        for (int q = 0; q < 2; q++)
                            MMA_FP16(acc[mi][p*2+q], al[mi][0], al[mi][1], al[mi][2],
                                     al[mi][3], bh[p][2*q], bh[p][2*q+1]);
            }
        }
    }
    __syncthreads();

    // ---------------- epilogue ----------------
    const int g = lane >> 2, tig = lane & 3;
    float* stg = reinterpret_cast<float*>(smem);

    if (do_diag) {      // C_raw = acc + acc^T
        #pragma unroll
        for (int mi = 0; mi < 4; mi++)
            #pragma unroll
            for (int nj = 0; nj < 4; nj++) {
                const int cl = wn * 32 + nj * 8 + 2 * tig;
                #pragma unroll
                for (int h = 0; h < 2; h++) {
                    const int rl = wm * 64 + mi * 16 + g + 8 * h;
                    stg[rl * 129 + cl]     = acc[mi][nj][2 * h];
                    stg[rl * 129 + cl + 1] = acc[mi][nj][2 * h + 1];
                }
            }
        __syncthreads();
        #pragma unroll
        for (int mi = 0; mi < 4; mi++)
            #pragma unroll
            for (int nj = 0; nj < 4; nj++) {
                const int cl = wn * 32 + nj * 8 + 2 * tig;
                #pragma unroll
                for (int h = 0; h < 2; h++) {
                    const int rl = wm * 64 + mi * 16 + g + 8 * h;
                    acc[mi][nj][2 * h]     += stg[cl * 129 + rl];
                    acc[mi][nj][2 * h + 1] += stg[(cl + 1) * 129 + rl];
                }
            }
    }

    float ts = 0.f;
    if (mymode >= 2) ts = g_tr[n];
    const float sc2 = (mymode == 2) ? (-0.5f / ts) : 0.f;
    const float sc3 = (mymode == 3) ? rsqrtf(ts / (float)(MM - 1)) : 0.f;
    const char* DnB = Dmat ? (const char*)(Dmat + (size_t)n * sD) : nullptr;

    char*  ChB = nullptr;
    float* Cf  = nullptr;
    if (ofmt == 0) ChB = (char*)((__half*)(job ? C2out : Cout) + (size_t)n * sC);
    else           Cf  = (float*)Cout + (size_t)n * sC;

    // C/D are 256x256 matrices: npc=8 panels per row-block
    const size_t pidx = ((size_t)ti * 8 + (size_t)tj * 4 + (size_t)wn) * 16384u;
    const bool do_t = sym && (rb != cb);
    if (do_t) __syncthreads();

    #pragma unroll
    for (int mi = 0; mi < 4; mi++) {
        #pragma unroll
        for (int nj = 0; nj < 4; nj++) {
            const int cl = wn * 32 + nj * 8 + 2 * tig;
            const int col = cb + cl;
            #pragma unroll
            for (int h = 0; h < 2; h++) {
                const int rl = wm * 64 + mi * 16 + g + 8 * h;
                const int row = rb + rl;
                float v0 = acc[mi][nj][2 * h];
                float v1 = acc[mi][nj][2 * h + 1];
                const uint32_t ohi = (uint32_t)(rl * 128 +
                                     ((nj ^ (rl & 7)) << 4) + tig * 4);
                const uint32_t olo = (uint32_t)(rl * 128 +
                                     (((4 + nj) ^ (rl & 7)) << 4) + tig * 4);
                if (mymode == 1) {
                    float2 dh = __half22float2(*(const __half2*)(DnB + pidx + ohi));
                    float2 dl = __half22float2(*(const __half2*)(DnB + pidx + olo));
                    v0 -= 1.5f * (dh.x + dl.x);
                    v1 -= 1.5f * (dh.y + dl.y);
                    if (row == col)     v0 += 1.5f;
                    if (row == col + 1) v1 += 1.5f;
                } else if (mymode == 2) {
                    v0 *= sc2; v1 *= sc2;
                    if (row == col)     v0 += 1.5f;
                    if (row == col + 1) v1 += 1.5f;
                } else if (mymode == 3) {
                    v0 *= sc3; v1 *= sc3;
                }
                if (ofmt == 0) {
                    __half2 hh = __float22half2_rn(make_float2(v0, v1));
                    *(__half2*)(ChB + pidx + ohi) = hh;
                    if (wlo) {
                        float2 f = __half22float2(hh);
                        *(__half2*)(ChB + pidx + olo) =
                            __float22half2_rn(make_float2(v0 - f.x, v1 - f.y));
                    }
                } else {
                    *(float2*)(Cf + (size_t)row * DD + col) = make_float2(v0, v1);
                }
                if (do_t) {
                    stg[rl * 129 + cl]     = v0;
                    stg[rl * 129 + cl + 1] = v1;
                }
            }
        }
    }

    // mirrored tile: C[cb..][rb..] = (this tile)^T, panel-format 16B stores
    if (do_t) {
        __syncthreads();
        const int r2    = tid >> 1;
        const int cbase = (tid & 1) * 64;
        #pragma unroll
        for (int q = 0; q < 8; q++) {
            const int c0 = cbase + q * 8;
            float w[8];
            #pragma unroll
            for (int u = 0; u < 8; u++) w[u] = stg[(c0 + u) * 129 + r2];
            __half2 h0 = __float22half2_rn(make_float2(w[0], w[1]));
            __half2 h1 = __float22half2_rn(make_float2(w[2], w[3]));
            __half2 h2 = __float22half2_rn(make_float2(w[4], w[5]));
            __half2 h3 = __float22half2_rn(make_float2(w[6], w[7]));
            const size_t p2 = ((size_t)tj * 8 + (size_t)ti * 4 + (size_t)(c0 >> 5))
                              * 16384u;
            const uint32_t gh2 = (uint32_t)((c0 >> 3) & 3);
            const uint32_t oh2 = (uint32_t)(r2 * 128 + ((gh2 ^ (r2 & 7)) << 4));
            *(uint4*)(ChB + p2 + oh2) =
                make_uint4(h2_bits(h0), h2_bits(h1), h2_bits(h2), h2_bits(h3));
            if (wlo) {
                float2 f0 = __half22float2(h0), f1 = __half22float2(h1);
                float2 f2 = __half22float2(h2), f3 = __half22float2(h3);
                __half2 l0 = __float22half2_rn(make_float2(w[0]-f0.x, w[1]-f0.y));
                __half2 l1 = __float22half2_rn(make_float2(w[2]-f1.x, w[3]-f1.y));
                __half2 l2 = __float22half2_rn(make_float2(w[4]-f2.x, w[5]-f2.y));
                __half2 l3 = __float22half2_rn(make_float2(w[6]-f3.x, w[7]-f3.y));
                const uint32_t ol2 = (uint32_t)(r2 * 128 +
                                     (((4 + gh2) ^ (r2 & 7)) << 4));
                *(uint4*)(ChB + p2 + ol2) =
                    make_uint4(h2_bits(l0), h2_bits(l1), h2_bits(l2), h2_bits(l3));
            }
        }
    }
}

// ======================= host launcher ======================================
extern "C" void kernel_launch(void* const* d_in, const int* in_sizes, int n_in,
                              void* d_out, int out_size) {
    const float* x = (const float*)d_in[0];
    float* out = (float*)d_out;

    __half *xn, *xnT, *Ba, *Bb, *Cm, *P0, *P1;
    cudaGetSymbolAddress((void**)&xn,  g_xn);
    cudaGetSymbolAddress((void**)&xnT, g_xnT);
    cudaGetSymbolAddress((void**)&Ba,  g_Ba);
    cudaGetSymbolAddress((void**)&Bb,  g_Bb);
    cudaGetSymbolAddress((void**)&Cm,  g_Cm);
    cudaGetSymbolAddress((void**)&P0,  g_P0);
    cudaGetSymbolAddress((void**)&P1,  g_P1);

    cudaFuncSetAttribute(gemm_h,
                         cudaFuncAttributeMaxDynamicSharedMemorySize, SMEM_DYN);

    const long long sM  = (long long)DD * 2 * DD;
    const long long sXT = (long long)DD * 2 * MM;
    const long long sXN = (long long)MM * 2 * DD;
    const long long sO  = (long long)MM * DD;
    const dim3 gSym(3, 1, NB);
    const dim3 gSym2(6, 1, NB);

    mean_kernel<<<NB, 256>>>(x);
    center_kernel<<<dim3(DD / 32, MM / 32, NB), dim3(32, 8)>>>(x);
    reduce_tr_kernel<<<NB, 128>>>();

    // args (17): C, A, B, D, C2, A2, K, sA, sB, sC, sD,
    //            mode, sym, sqr, pass3, ofmt, wlo1

    // sigma -> Ba = B0   [K=512, sym, squaring, 3-pass]
    gemm_h<<<gSym, 256, SMEM_DYN>>>(Ba, xnT, xnT, nullptr, nullptr, nullptr,
                                    MM, sXT, sXT, sM, 0,
                                    2, 1, 1, 1, 0, 1);
    // iter 1: Cm = B0^2 (squaring)
    gemm_h<<<gSym, 256, SMEM_DYN>>>(Cm, Ba, Ba, nullptr, nullptr, nullptr,
                                    DD, sM, sM, sM, 0,
                                    0, 1, 1, 1, 0, 1);
    //         Bb = Cm*B0 - 1.5Cm + 1.5I  (B1)
    gemm_h<<<gSym, 256, SMEM_DYN>>>(Bb, Cm, Ba, Cm, nullptr, nullptr,
                                    DD, sM, sM, sM, sM,
                                    1, 1, 0, 1, 0, 1);
    // iter 2: {Cm = B1^2 (squaring) , P0 = B0*B1 (P2)}
    gemm_h<<<gSym2, 256, SMEM_DYN>>>(Cm, Bb, Bb, nullptr, P0, Ba,
                                     DD, sM, sM, sM, 0,
                                     0, 1, 1, 1, 0, 1);
    //         Ba = Cm*B1 - 1.5Cm + 1.5I  (B2)
    gemm_h<<<gSym, 256, SMEM_DYN>>>(Ba, Cm, Bb, Cm, nullptr, nullptr,
                                    DD, sM, sM, sM, sM,
                                    1, 1, 0, 1, 0, 1);
    // iter 3: {Cm = B2^2 (squaring) , P1 = P2*B2 (P3, lo plane dead)}
    gemm_h<<<gSym2, 256, SMEM_DYN>>>(Cm, Ba, Ba, nullptr, P1, P0,
                                     DD, sM, sM, sM, 0,
                                     0, 1, 1, 1, 0, 0);
    //         Bb = Cm*B2 - 1.5Cm + 1.5I  (B3)
    gemm_h<<<gSym, 256, SMEM_DYN>>>(Bb, Cm, Ba, Cm, nullptr, nullptr,
                                    DD, sM, sM, sM, sM,
                                    1, 1, 0, 1, 0, 1);
    // iter 4: P0 = P3*B3 (P4) — 2-pass
    gemm_h<<<gSym, 256, SMEM_DYN>>>(P0, P1, Bb, nullptr, nullptr, nullptr,
                                    DD, sM, sM, sM, 0,
                                    0, 1, 0, 0, 0, 1);
    // final: out = xn*P4*rsqrt(sumsq/(M-1)) — 2-pass, fp32 row-major out
    gemm_h<<<dim3(4, 2, NB), 256, SMEM_DYN>>>(out, xn, P0, nullptr, nullptr,
                                              nullptr, DD, sXN, sM, sO, 0,
                                              3, 0, 0, 0, 1, 1);
}

// round 13
// speedup vs baseline: 5.7261x; 1.0238x over previous
#include <cuda_runtime.h>
#include <cuda_fp16.h>
#include <cstdint>
#include <cstddef>

#define NB   256
#define MM   512
#define DD   256

// ======================= scratch (device globals) ===========================
// Split-fp16 matrices stored as 16KB PANELS: panel(pr,pc) = rows pr*128..+127,
// K-cols pc*32..+31. Panel layout = exact smem image: row r at offset r*128,
// 8 x 16B groups (4 hi + 4 lo), group g stored at ((g ^ (r&7))<<4).
__device__ __align__(256) float  g_mean[NB * DD];
__device__ __align__(256) float  g_tr  [NB];
__device__ __align__(256) float  g_ssp [NB * 128];
__device__ __align__(256) __half g_xn  [NB * MM * 2 * DD];
__device__ __align__(256) __half g_xnT [NB * DD * 2 * MM];
__device__ __align__(256) __half g_Ba  [NB * DD * 2 * DD];
__device__ __align__(256) __half g_Bb  [NB * DD * 2 * DD];
__device__ __align__(256) __half g_Cm  [NB * DD * 2 * DD];
__device__ __align__(256) __half g_P0  [NB * DD * 2 * DD];
__device__ __align__(256) __half g_P1  [NB * DD * 2 * DD];

// ======================= PTX helpers ========================================
__device__ __forceinline__ uint32_t smem_u32(const void* p) {
    uint32_t a;
    asm("{ .reg .u64 t; cvta.to.shared.u64 t, %1; cvt.u32.u64 %0, t; }"
        : "=r"(a) : "l"(p));
    return a;
}

#define CP_BULK(dst_u32, src_gptr, bytes, mbar) \
    asm volatile("cp.async.bulk.shared::cluster.global.mbarrier::complete_tx::bytes " \
                 "[%0], [%1], %2, [%3];" \
                 :: "r"(dst_u32), "l"((const void*)(src_gptr)), \
                    "r"((uint32_t)(bytes)), "r"(mbar) : "memory")

#define MBARRIER_INIT(mbar, count) \
    asm volatile("mbarrier.init.shared.b64 [%0], %1;" \
                 :: "r"((uint32_t)(mbar)), "r"((uint32_t)(count)) : "memory")
#define MBARRIER_EXPECT_TX(mbar, tx) \
    asm volatile("mbarrier.arrive.expect_tx.shared.b64 _, [%0], %1;" \
                 :: "r"((uint32_t)(mbar)), "r"((uint32_t)(tx)) : "memory")
#define MBARRIER_WAIT_PARITY(mbar_addr, phase_parity) do {                    \
    uint32_t _mbar = (uint32_t)(mbar_addr);                                   \
    uint32_t _parity = (uint32_t)(phase_parity);                              \
    uint32_t _done;                                                           \
    asm volatile(                                                             \
        "{\n\t.reg .pred p;\n\t"                                              \
        "mbarrier.try_wait.parity.acquire.cta.shared::cta.b64 p, [%1], %2;\n\t" \
        "selp.b32 %0, 1, 0, p;\n\t}"                                          \
        : "=r"(_done) : "r"(_mbar), "r"(_parity) : "memory");                 \
    if (!_done) {                                                             \
        asm volatile(                                                         \
            "{\n\t.reg .pred P1;\n\t"                                         \
            "WAIT_LOOP_%=:\n\t"                                               \
            "mbarrier.try_wait.parity.acquire.cta.shared::cta.b64 P1, [%0], %1, 0x989680;\n\t" \
            "@P1 bra.uni WAIT_DONE_%=;\n\t"                                   \
            "bra.uni WAIT_LOOP_%=;\n\t"                                       \
            "WAIT_DONE_%=:\n\t}"                                              \
            :: "r"(_mbar), "r"(_parity) : "memory");                          \
    }                                                                         \
} while (0)

#define LDM_X4(r0, r1, r2, r3, addr) \
    asm volatile("ldmatrix.sync.aligned.m8n8.x4.shared.b16 {%0,%1,%2,%3}, [%4];" \
                 : "=r"(r0), "=r"(r1), "=r"(r2), "=r"(r3) : "r"(addr))

#define MMA_FP16(d, a0, a1, a2, a3, b0, b1) \
    asm volatile("mma.sync.aligned.m16n8k16.row.col.f32.f16.f16.f32 " \
                 "{%0,%1,%2,%3}, {%4,%5,%6,%7}, {%8,%9}, {%0,%1,%2,%3};" \
                 : "+f"((d)[0]), "+f"((d)[1]), "+f"((d)[2]), "+f"((d)[3]) \
                 : "r"(a0), "r"(a1), "r"(a2), "r"(a3), "r"(b0), "r"(b1))

__device__ __forceinline__ uint32_t h2_half(uint32_t x) {   // *0.5 packed fp16x2
    uint32_t d;
    asm("mul.rn.f16x2 %0, %1, %2;" : "=r"(d) : "r"(x), "r"(0x38003800u));
    return d;
}
__device__ __forceinline__ uint32_t h2_bits(__half2 h) {
    return *reinterpret_cast<uint32_t*>(&h);
}

// ======================= mean over axis 1 ===================================
__global__ __launch_bounds__(256) void mean_kernel(const float* __restrict__ x) {
    int n = blockIdx.x, d = threadIdx.x;
    const float* xp = x + (size_t)n * MM * DD + d;
    float s0 = 0.f, s1 = 0.f, s2 = 0.f, s3 = 0.f;
    #pragma unroll 4
    for (int m = 0; m < MM; m += 4) {
        s0 += xp[(size_t)(m + 0) * DD];
        s1 += xp[(size_t)(m + 1) * DD];
        s2 += xp[(size_t)(m + 2) * DD];
        s3 += xp[(size_t)(m + 3) * DD];
    }
    g_mean[n * DD + d] = (s0 + s1 + s2 + s3) * (1.f / (float)MM);
}

// ==== center: xn hi-only panels, xnT split panels, sumsq partials ===========
__global__ __launch_bounds__(256) void center_kernel(const float* __restrict__ x) {
    const int n  = blockIdx.z;
    const int d0 = blockIdx.x * 32;
    const int m0 = blockIdx.y * 32;
    const int tx = threadIdx.x, ty = threadIdx.y;   // block (32, 8)

    __shared__ float tile[32][33];
    __shared__ float red[256];

    char* xb  = (char*)(g_xn  + (size_t)n * MM * 2 * DD);
    char* xtb = (char*)(g_xnT + (size_t)n * DD * 2 * MM);

    const int d = d0 + tx;
    const float mu = g_mean[n * DD + d];
    float ss = 0.f;
    #pragma unroll
    for (int r = 0; r < 4; r++) {
        int m = m0 + ty + r * 8;
        float v = x[(size_t)n * MM * DD + (size_t)m * DD + d] - mu;
        size_t pan = ((size_t)(m >> 7) * 8 + (d0 >> 5)) * 16384u;
        int rr = m & 127;
        uint32_t off = (uint32_t)(rr * 128 +
                        ((((d >> 3) & 3) ^ (rr & 7)) << 4) + (d & 7) * 2);
        *(__half*)(xb + pan + off) = __float2half_rn(v);
        tile[ty + r * 8][tx] = v;
        ss += v * v;
    }
    __syncthreads();
    #pragma unroll
    for (int r = 0; r < 4; r++) {
        int dd_ = ty + r * 8;
        float v = tile[tx][dd_];
        __half hh = __float2half_rn(v);
        __half hl = __float2half_rn(v - __half2float(hh));
        int dg = d0 + dd_, mg = m0 + tx;
        size_t pan = ((size_t)(dg >> 7) * 16 + (mg >> 5)) * 16384u;
        int rr = dg & 127;
        uint32_t gh = (uint32_t)((mg >> 3) & 3);
        uint32_t ohi = (uint32_t)(rr * 128 + ((gh ^ (rr & 7)) << 4) + (mg & 7) * 2);
        uint32_t olo = (uint32_t)(rr * 128 + (((4 + gh) ^ (rr & 7)) << 4) + (mg & 7) * 2);
        *(__half*)(xtb + pan + ohi) = hh;
        *(__half*)(xtb + pan + olo) = hl;
    }
    int t = ty * 32 + tx;
    red[t] = ss;
    __syncthreads();
    for (int s = 128; s > 0; s >>= 1) {
        if (t < s) red[t] += red[t + s];
        __syncthreads();
    }
    if (t == 0) g_ssp[n * 128 + blockIdx.y * 8 + blockIdx.x] = red[0];
}

__global__ __launch_bounds__(128) void reduce_tr_kernel() {
    int n = blockIdx.x, t = threadIdx.x;
    __shared__ float red[128];
    red[t] = g_ssp[n * 128 + t];
    __syncthreads();
    for (int s = 64; s > 0; s >>= 1) {
        if (t < s) red[t] += red[t + s];
        __syncthreads();
    }
    if (t == 0) g_tr[n] = red[0];
}

// ===================== fp16 mma.sync batched GEMM, bulk-copy panels =========
// 18 params: Cout,Amat,Bmat,Dmat,C2out,A2mat,Ktot,sA,sB,sC,sD,
//            mode,sym,sqr,pass3,pass3b,ofmt,wlo1
// pass3b = pass3 flag for job1 (the merged second GEMM).
// mode-1 launches prefetch D panels into freed staging slots (non-mirror CTAs).
#define STG_B      32768u
#define MBAR_OFF   98304u
#define SMEM_DYN   98432

__global__ __launch_bounds__(256, 2) void gemm_h(
    void* __restrict__ Cout, const __half* __restrict__ Amat,
    const __half* __restrict__ Bmat, const __half* __restrict__ Dmat,
    void* __restrict__ C2out, const __half* __restrict__ A2mat,
    int Ktot, long long sA, long long sB, long long sC, long long sD,
    int mode, int sym, int sqr, int pass3, int pass3b, int ofmt, int wlo1)
{
    extern __shared__ char smem[];
    const uint32_t sb  = smem_u32(smem);
    const uint32_t mb0 = sb + MBAR_OFF;

    const int tid  = threadIdx.x;
    const int wid  = tid >> 5, lane = tid & 31;
    const int wm   = wid & 1;
    const int wn   = wid >> 1;
    const int n    = blockIdx.z;

    int ti, tj, job = 0, mymode = mode;
    if (sym) {
        int tt = blockIdx.x;
        if (tt >= 3) { job = 1; tt -= 3; mymode = 0; }
        ti = (tt == 2) ? 1 : 0; tj = (tt != 0) ? 1 : 0;
    } else {
        ti = blockIdx.x; tj = blockIdx.y;
    }
    const int rb = ti * 128;
    const int cb = tj * 128;

    const bool do_diag = sqr && sym && (job == 0) && (ti == tj);
    const bool need_al = ((job ? pass3b : pass3) != 0) && !do_diag;
    const bool wlo     = job ? (wlo1 != 0) : true;
    const bool do_t    = sym && (rb != cb);

    const __half* An = (job ? A2mat : Amat) + (size_t)n * sA;
    const __half* Bn = Bmat + (size_t)n * sB;
    const char* DnB = Dmat ? (const char*)(Dmat + (size_t)n * sD) : nullptr;

    const int nch = Ktot >> 5;
    const size_t aprow = (size_t)ti * nch * 16384u;
    const size_t bprow = (size_t)tj * nch * 16384u;

    // D prefetch applies to mode-1 non-mirror CTAs (mirror needs stg smem).
    const bool dpref = (mymode == 1) && (DnB != nullptr) && !do_t;
    const uint32_t sD1 = (uint32_t)(nch % 3);
    const uint32_t sD2 = (uint32_t)((nch + 1) % 3);
    const size_t dpanbase = ((size_t)ti * 8 + (size_t)tj * 4) * 16384u;

    if (tid == 0) {
        MBARRIER_INIT(mb0,      1);
        MBARRIER_INIT(mb0 + 8,  1);
        MBARRIER_INIT(mb0 + 16, 1);
        MBARRIER_INIT(mb0 + 24, 1);
        MBARRIER_INIT(mb0 + 32, 1);
    }
    __syncthreads();

    if (tid == 0) {
        #pragma unroll
        for (int pc_ = 0; pc_ < 2; pc_++) {
            uint32_t mbar = mb0 + (uint32_t)pc_ * 8u;
            uint32_t dst  = sb + (uint32_t)pc_ * STG_B;
            const char* sa = (const char*)An + aprow + (size_t)pc_ * 16384u;
            const char* sp = (const char*)Bn + bprow + (size_t)pc_ * 16384u;
            if (do_diag) {
                MBARRIER_EXPECT_TX(mbar, 16384u);
                CP_BULK(dst, sa, 16384u, mbar);
            } else {
                MBARRIER_EXPECT_TX(mbar, 32768u);
                CP_BULK(dst, sa, 16384u, mbar);
                CP_BULK(dst + 16384u, sp, 16384u, mbar);
            }
        }
    }

    // ldmatrix lane geometry
    const int t  = lane >> 3, s7 = lane & 7;
    const int chA = t >> 1;
    const int rAl = wm * 64 + (t & 1) * 8 + s7;
    const int chB = t & 1;
    const int rBl = wn * 32 + (t >> 1) * 8 + s7;

    float acc[4][4][4];
    #pragma unroll
    for (int i = 0; i < 4; i++)
        #pragma unroll
        for (int j = 0; j < 4; j++)
            #pragma unroll
            for (int q = 0; q < 4; q++) acc[i][j][q] = 0.f;

    for (int c = 0; c < nch; c++) {
        const int s = c % 3;
        MBARRIER_WAIT_PARITY(mb0 + (uint32_t)s * 8u, (c / 3) & 1);
        __syncthreads();

        if (tid == 0) {
            if (c + 2 < nch) {
                const int c2 = c + 2, s2 = c2 % 3;
                uint32_t mbar = mb0 + (uint32_t)s2 * 8u;
                uint32_t dst  = sb + (uint32_t)s2 * STG_B;
                const char* sa = (const char*)An + aprow + (size_t)c2 * 16384u;
                const char* sp = (const char*)Bn + bprow + (size_t)c2 * 16384u;
                if (do_diag) {
                    MBARRIER_EXPECT_TX(mbar, 16384u);
                    CP_BULK(dst, sa, 16384u, mbar);
                } else {
                    MBARRIER_EXPECT_TX(mbar, 32768u);
                    CP_BULK(dst, sa, 16384u, mbar);
                    CP_BULK(dst + 16384u, sp, 16384u, mbar);
                }
            } else if (dpref && c == nch - 2) {
                // D panels 0,1 into freed slot sD1
                uint32_t dst = sb + sD1 * STG_B;
                MBARRIER_EXPECT_TX(mb0 + 24, 32768u);
                CP_BULK(dst,           DnB + dpanbase,            16384u, mb0 + 24);
                CP_BULK(dst + 16384u,  DnB + dpanbase + 16384u,   16384u, mb0 + 24);
            } else if (dpref && c == nch - 1) {
                // D panels 2,3 into freed slot sD2
                uint32_t dst = sb + sD2 * STG_B;
                MBARRIER_EXPECT_TX(mb0 + 32, 32768u);
                CP_BULK(dst,           DnB + dpanbase + 32768u,   16384u, mb0 + 32);
                CP_BULK(dst + 16384u,  DnB + dpanbase + 49152u,   16384u, mb0 + 32);
            }
        }

        const uint32_t aB = sb + (uint32_t)s * STG_B;
        const uint32_t bB = do_diag ? aB : (aB + 16384u);

        #pragma unroll
        for (int kk = 0; kk < 2; kk++) {
            uint32_t bh[2][4], bl[2][4], ah[4][4], al[4][4];
            const int ghA = (kk << 1) + chA;
            const int ghB = (kk << 1) + chB;
            #pragma unroll
            for (int p = 0; p < 2; p++) {
                uint32_t h_ = bB + (uint32_t)((rBl + p * 16) * 128 + (ghB ^ s7) * 16);
                LDM_X4(bh[p][0], bh[p][1], bh[p][2], bh[p][3], h_);
            }
            #pragma unroll
            for (int p = 0; p < 2; p++) {
                uint32_t l_ = bB + (uint32_t)((rBl + p * 16) * 128 + ((4 + ghB) ^ s7) * 16);
                LDM_X4(bl[p][0], bl[p][1], bl[p][2], bl[p][3], l_);
            }
            #pragma unroll
            for (int mi = 0; mi < 4; mi++) {
                uint32_t h_ = aB + (uint32_t)((rAl + mi * 16) * 128 + (ghA ^ s7) * 16);
                LDM_X4(ah[mi][0], ah[mi][1], ah[mi][2], ah[mi][3], h_);
            }
            if (need_al) {
                #pragma unroll
                for (int mi = 0; mi < 4; mi++) {
                    uint32_t l_ = aB + (uint32_t)((rAl + mi * 16) * 128 + ((4 + ghA) ^ s7) * 16);
                    LDM_X4(al[mi][0], al[mi][1], al[mi][2], al[mi][3], l_);
                }
            }
            if (do_diag) {
                #pragma unroll
                for (int p = 0; p < 2; p++)
                    #pragma unroll
                    for (int q = 0; q < 4; q++) bh[p][q] = h2_half(bh[p][q]);
            }

            #pragma unroll
            for (int mi = 0; mi < 4; mi++)
                #pragma unroll
                for (int p = 0; p < 2; p++)
                    #pragma unroll
                    for (int q = 0; q < 2; q++)
                        MMA_FP16(acc[mi][p*2+q], ah[mi][0], ah[mi][1], ah[mi][2],
                                 ah[mi][3], bh[p][2*q], bh[p][2*q+1]);
            #pragma unroll
            for (int mi = 0; mi < 4; mi++)
                #pragma unroll
                for (int p = 0; p < 2; p++)
                    #pragma unroll
                    for (int q = 0; q < 2; q++)
                        MMA_FP16(acc[mi][p*2+q], ah[mi][0], ah[mi][1], ah[mi][2],
                                 ah[mi][3], bl[p][2*q], bl[p][2*q+1]);
            if (need_al) {
                #pragma unroll
                for (int mi = 0; mi < 4; mi++)
                    #pragma unroll
                    for (int p = 0; p < 2; p++)
                        #pragma unroll
                        for (int q = 0; q < 2; q++)
                            MMA_FP16(acc[mi][p*2+q], al[mi][0], al[mi][1], al[mi][2],
                                     al[mi][3], bh[p][2*q], bh[p][2*q+1]);
            }
        }
    }
    __syncthreads();

    // ---------------- epilogue ----------------
    if (dpref) {
        MBARRIER_WAIT_PARITY(mb0 + 24, 0);
        MBARRIER_WAIT_PARITY(mb0 + 32, 0);
    }

    const int g = lane >> 2, tig = lane & 3;
    float* stg = reinterpret_cast<float*>(smem);

    if (do_diag) {      // C_raw = acc + acc^T
        #pragma unroll
        for (int mi = 0; mi < 4; mi++)
            #pragma unroll
            for (int nj = 0; nj < 4; nj++) {
                const int cl = wn * 32 + nj * 8 + 2 * tig;
                #pragma unroll
                for (int h = 0; h < 2; h++) {
                    const int rl = wm * 64 + mi * 16 + g + 8 * h;
                    stg[rl * 129 + cl]     = acc[mi][nj][2 * h];
                    stg[rl * 129 + cl + 1] = acc[mi][nj][2 * h + 1];
                }
            }
        __syncthreads();
        #pragma unroll
        for (int mi = 0; mi < 4; mi++)
            #pragma unroll
            for (int nj = 0; nj < 4; nj++) {
                const int cl = wn * 32 + nj * 8 + 2 * tig;
                #pragma unroll
                for (int h = 0; h < 2; h++) {
                    const int rl = wm * 64 + mi * 16 + g + 8 * h;
                    acc[mi][nj][2 * h]     += stg[cl * 129 + rl];
                    acc[mi][nj][2 * h + 1] += stg[(cl + 1) * 129 + rl];
                }
            }
    }

    float ts = 0.f;
    if (mymode >= 2) ts = g_tr[n];
    const float sc2 = (mymode == 2) ? (-0.5f / ts) : 0.f;
    const float sc3 = (mymode == 3) ? rsqrtf(ts / (float)(MM - 1)) : 0.f;

    char*  ChB = nullptr;
    float* Cf  = nullptr;
    if (ofmt == 0) ChB = (char*)((__half*)(job ? C2out : Cout) + (size_t)n * sC);
    else           Cf  = (float*)Cout + (size_t)n * sC;

    const size_t pidx = dpanbase + (size_t)wn * 16384u;
    const char* dsm = smem + (size_t)(wn < 2 ? sD1 : sD2) * STG_B +
                      (size_t)(wn & 1) * 16384u;
    if (do_t) __syncthreads();

    #pragma unroll
    for (int mi = 0; mi < 4; mi++) {
        #pragma unroll
        for (int nj = 0; nj < 4; nj++) {
            const int cl = wn * 32 + nj * 8 + 2 * tig;
            const int col = cb + cl;
            #pragma unroll
            for (int h = 0; h < 2; h++) {
                const int rl = wm * 64 + mi * 16 + g + 8 * h;
                const int row = rb + rl;
                float v0 = acc[mi][nj][2 * h];
                float v1 = acc[mi][nj][2 * h + 1];
                const uint32_t ohi = (uint32_t)(rl * 128 +
                                     ((nj ^ (rl & 7)) << 4) + tig * 4);
                const uint32_t olo = (uint32_t)(rl * 128 +
                                     (((4 + nj) ^ (rl & 7)) << 4) + tig * 4);
                if (mymode == 1) {
                    float2 dh, dl;
                    if (dpref) {
                        dh = __half22float2(*(const __half2*)(dsm + ohi));
                        dl = __half22float2(*(const __half2*)(dsm + olo));
                    } else {
                        dh = __half22float2(*(const __half2*)(DnB + pidx + ohi));
                        dl = __half22float2(*(const __half2*)(DnB + pidx + olo));
                    }
                    v0 -= 1.5f * (dh.x + dl.x);
                    v1 -= 1.5f * (dh.y + dl.y);
                    if (row == col)     v0 += 1.5f;
                    if (row == col + 1) v1 += 1.5f;
                } else if (mymode == 2) {
                    v0 *= sc2; v1 *= sc2;
                    if (row == col)     v0 += 1.5f;
                    if (row == col + 1) v1 += 1.5f;
                } else if (mymode == 3) {
                    v0 *= sc3; v1 *= sc3;
                }
                if (ofmt == 0) {
                    __half2 hh = __float22half2_rn(make_float2(v0, v1));
                    *(__half2*)(ChB + pidx + ohi) = hh;
                    if (wlo) {
                        float2 f = __half22float2(hh);
                        *(__half2*)(ChB + pidx + olo) =
                            __float22half2_rn(make_float2(v0 - f.x, v1 - f.y));
                    }
                } else {
                    *(float2*)(Cf + (size_t)row * DD + col) = make_float2(v0, v1);
                }
                if (do_t) {
                    stg[rl * 129 + cl]     = v0;
                    stg[rl * 129 + cl + 1] = v1;
                }
            }
        }
    }

    // mirrored tile: C[cb..][rb..] = (this tile)^T, panel-format 16B stores
    if (do_t) {
        __syncthreads();
        const int r2    = tid >> 1;
        const int cbase = (tid & 1) * 64;
        #pragma unroll
        for (int q = 0; q < 8; q++) {
            const int c0 = cbase + q * 8;
            float w[8];
            #pragma unroll
            for (int u = 0; u < 8; u++) w[u] = stg[(c0 + u) * 129 + r2];
            __half2 h0 = __float22half2_rn(make_float2(w[0], w[1]));
            __half2 h1 = __float22half2_rn(make_float2(w[2], w[3]));
            __half2 h2 = __float22half2_rn(make_float2(w[4], w[5]));
            __half2 h3 = __float22half2_rn(make_float2(w[6], w[7]));
            const size_t p2 = ((size_t)tj * 8 + (size_t)ti * 4 + (size_t)(c0 >> 5))
                              * 16384u;
            const uint32_t gh2 = (uint32_t)((c0 >> 3) & 3);
            const uint32_t oh2 = (uint32_t)(r2 * 128 + ((gh2 ^ (r2 & 7)) << 4));
            *(uint4*)(ChB + p2 + oh2) =
                make_uint4(h2_bits(h0), h2_bits(h1), h2_bits(h2), h2_bits(h3));
            if (wlo) {
                float2 f0 = __half22float2(h0), f1 = __half22float2(h1);
                float2 f2 = __half22float2(h2), f3 = __half22float2(h3);
                __half2 l0 = __float22half2_rn(make_float2(w[0]-f0.x, w[1]-f0.y));
                __half2 l1 = __float22half2_rn(make_float2(w[2]-f1.x, w[3]-f1.y));
                __half2 l2 = __float22half2_rn(make_float2(w[4]-f2.x, w[5]-f2.y));
                __half2 l3 = __float22half2_rn(make_float2(w[6]-f3.x, w[7]-f3.y));
                const uint32_t ol2 = (uint32_t)(r2 * 128 +
                                     (((4 + gh2) ^ (r2 & 7)) << 4));
                *(uint4*)(ChB + p2 + ol2) =
                    make_uint4(h2_bits(l0), h2_bits(l1), h2_bits(l2), h2_bits(l3));
            }
        }
    }
}

// ======================= host launcher ======================================
extern "C" void kernel_launch(void* const* d_in, const int* in_sizes, int n_in,
                              void* d_out, int out_size) {
    const float* x = (const float*)d_in[0];
    float* out = (float*)d_out;

    __half *xn, *xnT, *Ba, *Bb, *Cm, *P0, *P1;
    cudaGetSymbolAddress((void**)&xn,  g_xn);
    cudaGetSymbolAddress((void**)&xnT, g_xnT);
    cudaGetSymbolAddress((void**)&Ba,  g_Ba);
    cudaGetSymbolAddress((void**)&Bb,  g_Bb);
    cudaGetSymbolAddress((void**)&Cm,  g_Cm);
    cudaGetSymbolAddress((void**)&P0,  g_P0);
    cudaGetSymbolAddress((void**)&P1,  g_P1);

    cudaFuncSetAttribute(gemm_h,
                         cudaFuncAttributeMaxDynamicSharedMemorySize, SMEM_DYN);

    const long long sM  = (long long)DD * 2 * DD;
    const long long sXT = (long long)DD * 2 * MM;
    const long long sXN = (long long)MM * 2 * DD;
    const long long sO  = (long long)MM * DD;
    const dim3 gSym(3, 1, NB);
    const dim3 gSym2(6, 1, NB);

    mean_kernel<<<NB, 256>>>(x);
    center_kernel<<<dim3(DD / 32, MM / 32, NB), dim3(32, 8)>>>(x);
    reduce_tr_kernel<<<NB, 128>>>();

    // args (18): C, A, B, D, C2, A2, K, sA, sB, sC, sD,
    //            mode, sym, sqr, pass3, pass3b, ofmt, wlo1

    // sigma -> Ba = B0   [K=512, sym, squaring, 3-pass]
    gemm_h<<<gSym, 256, SMEM_DYN>>>(Ba, xnT, xnT, nullptr, nullptr, nullptr,
                                    MM, sXT, sXT, sM, 0,
                                    2, 1, 1, 1, 1, 0, 1);
    // iter 1: Cm = B0^2 (squaring)
    gemm_h<<<gSym, 256, SMEM_DYN>>>(Cm, Ba, Ba, nullptr, nullptr, nullptr,
                                    DD, sM, sM, sM, 0,
                                    0, 1, 1, 1, 1, 0, 1);
    //         Bb = Cm*B0 - 1.5Cm + 1.5I  (B1)  [D prefetch]
    gemm_h<<<gSym, 256, SMEM_DYN>>>(Bb, Cm, Ba, Cm, nullptr, nullptr,
                                    DD, sM, sM, sM, sM,
                                    1, 1, 0, 1, 1, 0, 1);
    // iter 2: {Cm = B1^2 (squaring) , P0 = B0*B1 (P2, 2-pass job1)}
    gemm_h<<<gSym2, 256, SMEM_DYN>>>(Cm, Bb, Bb, nullptr, P0, Ba,
                                     DD, sM, sM, sM, 0,
                                     0, 1, 1, 1, 0, 0, 1);
    //         Ba = Cm*B1 - 1.5Cm + 1.5I  (B2)  [D prefetch]
    gemm_h<<<gSym, 256, SMEM_DYN>>>(Ba, Cm, Bb, Cm, nullptr, nullptr,
                                    DD, sM, sM, sM, sM,
                                    1, 1, 0, 1, 1, 0, 1);
    // iter 3: {Cm = B2^2 (squaring) , P1 = P2*B2 (P3, 2-pass job1, lo dead)}
    gemm_h<<<gSym2, 256, SMEM_DYN>>>(Cm, Ba, Ba, nullptr, P1, P0,
                                     DD, sM, sM, sM, 0,
                                     0, 1, 1, 1, 0, 0, 0);
    //         Bb = Cm*B2 - 1.5Cm + 1.5I  (B3)  [D prefetch]
    gemm_h<<<gSym, 256, SMEM_DYN>>>(Bb, Cm, Ba, Cm, nullptr, nullptr,
                                    DD, sM, sM, sM, sM,
                                    1, 1, 0, 1, 1, 0, 1);
    // iter 4: P0 = P3*B3 (P4) — 2-pass
    gemm_h<<<gSym, 256, SMEM_DYN>>>(P0, P1, Bb, nullptr, nullptr, nullptr,
                                    DD, sM, sM, sM, 0,
                                    0, 1, 0, 0, 0, 0, 1);
    // final: out = xn*P4*rsqrt(sumsq/(M-1)) — 2-pass, fp32 row-major out
    gemm_h<<<dim3(4, 2, NB), 256, SMEM_DYN>>>(out, xn, P0, nullptr, nullptr,
                                              nullptr, DD, sXN, sM, sO, 0,
                                              3, 0, 0, 0, 0, 1, 1);
}

// round 14
// speedup vs baseline: 5.7839x; 1.0101x over previous
#include <cuda_runtime.h>
#include <cuda_fp16.h>
#include <cstdint>
#include <cstddef>

#define NB   256
#define MM   512
#define DD   256

// ======================= scratch (device globals) ===========================
// Split-fp16 matrices stored as 16KB PANELS: panel(pr,pc) = rows pr*128..+127,
// K-cols pc*32..+31. Panel layout = exact smem image: row r at offset r*128,
// 8 x 16B groups (4 hi + 4 lo), group g stored at ((g ^ (r&7))<<4).
__device__ __align__(256) float  g_mean[NB * DD];
__device__ __align__(256) float  g_tr  [NB];
__device__ __align__(256) float  g_ssp [NB * 128];
__device__ __align__(256) __half g_xn  [NB * MM * 2 * DD];
__device__ __align__(256) __half g_xnT [NB * DD * 2 * MM];
__device__ __align__(256) __half g_Ba  [NB * DD * 2 * DD];
__device__ __align__(256) __half g_Bb  [NB * DD * 2 * DD];
__device__ __align__(256) __half g_Cm  [NB * DD * 2 * DD];
__device__ __align__(256) __half g_P0  [NB * DD * 2 * DD];
__device__ __align__(256) __half g_P1  [NB * DD * 2 * DD];

// ======================= PTX helpers ========================================
__device__ __forceinline__ uint32_t smem_u32(const void* p) {
    uint32_t a;
    asm("{ .reg .u64 t; cvta.to.shared.u64 t, %1; cvt.u32.u64 %0, t; }"
        : "=r"(a) : "l"(p));
    return a;
}

#define CP_BULK(dst_u32, src_gptr, bytes, mbar) \
    asm volatile("cp.async.bulk.shared::cluster.global.mbarrier::complete_tx::bytes " \
                 "[%0], [%1], %2, [%3];" \
                 :: "r"(dst_u32), "l"((const void*)(src_gptr)), \
                    "r"((uint32_t)(bytes)), "r"(mbar) : "memory")

#define MBARRIER_INIT(mbar, count) \
    asm volatile("mbarrier.init.shared.b64 [%0], %1;" \
                 :: "r"((uint32_t)(mbar)), "r"((uint32_t)(count)) : "memory")
#define MBARRIER_EXPECT_TX(mbar, tx) \
    asm volatile("mbarrier.arrive.expect_tx.shared.b64 _, [%0], %1;" \
                 :: "r"((uint32_t)(mbar)), "r"((uint32_t)(tx)) : "memory")
#define MBARRIER_WAIT_PARITY(mbar_addr, phase_parity) do {                    \
    uint32_t _mbar = (uint32_t)(mbar_addr);                                   \
    uint32_t _parity = (uint32_t)(phase_parity);                              \
    uint32_t _done;                                                           \
    asm volatile(                                                             \
        "{\n\t.reg .pred p;\n\t"                                              \
        "mbarrier.try_wait.parity.acquire.cta.shared::cta.b64 p, [%1], %2;\n\t" \
        "selp.b32 %0, 1, 0, p;\n\t}"                                          \
        : "=r"(_done) : "r"(_mbar), "r"(_parity) : "memory");                 \
    if (!_done) {                                                             \
        asm volatile(                                                         \
            "{\n\t.reg .pred P1;\n\t"                                         \
            "WAIT_LOOP_%=:\n\t"                                               \
            "mbarrier.try_wait.parity.acquire.cta.shared::cta.b64 P1, [%0], %1, 0x989680;\n\t" \
            "@P1 bra.uni WAIT_DONE_%=;\n\t"                                   \
            "bra.uni WAIT_LOOP_%=;\n\t"                                       \
            "WAIT_DONE_%=:\n\t}"                                              \
            :: "r"(_mbar), "r"(_parity) : "memory");                          \
    }                                                                         \
} while (0)

#define LDM_X4(r0, r1, r2, r3, addr) \
    asm volatile("ldmatrix.sync.aligned.m8n8.x4.shared.b16 {%0,%1,%2,%3}, [%4];" \
                 : "=r"(r0), "=r"(r1), "=r"(r2), "=r"(r3) : "r"(addr))

// NOT volatile: pure register op; lets ptxas interleave next-step ldmatrix
// under current-step MMAs (data deps via "+f" keep correctness).
#define MMA_FP16(d, a0, a1, a2, a3, b0, b1) \
    asm("mma.sync.aligned.m16n8k16.row.col.f32.f16.f16.f32 " \
        "{%0,%1,%2,%3}, {%4,%5,%6,%7}, {%8,%9}, {%0,%1,%2,%3};" \
        : "+f"((d)[0]), "+f"((d)[1]), "+f"((d)[2]), "+f"((d)[3]) \
        : "r"(a0), "r"(a1), "r"(a2), "r"(a3), "r"(b0), "r"(b1))

__device__ __forceinline__ uint32_t h2_half(uint32_t x) {   // *0.5 packed fp16x2
    uint32_t d;
    asm("mul.rn.f16x2 %0, %1, %2;" : "=r"(d) : "r"(x), "r"(0x38003800u));
    return d;
}
__device__ __forceinline__ uint32_t h2_bits(__half2 h) {
    return *reinterpret_cast<uint32_t*>(&h);
}

// ======================= mean over axis 1 ===================================
__global__ __launch_bounds__(256) void mean_kernel(const float* __restrict__ x) {
    int n = blockIdx.x, d = threadIdx.x;
    const float* xp = x + (size_t)n * MM * DD + d;
    float s0 = 0.f, s1 = 0.f, s2 = 0.f, s3 = 0.f;
    #pragma unroll 4
    for (int m = 0; m < MM; m += 4) {
        s0 += xp[(size_t)(m + 0) * DD];
        s1 += xp[(size_t)(m + 1) * DD];
        s2 += xp[(size_t)(m + 2) * DD];
        s3 += xp[(size_t)(m + 3) * DD];
    }
    g_mean[n * DD + d] = (s0 + s1 + s2 + s3) * (1.f / (float)MM);
}

// ==== center: xn hi-only panels, xnT split panels, sumsq partials ===========
__global__ __launch_bounds__(256) void center_kernel(const float* __restrict__ x) {
    const int n  = blockIdx.z;
    const int d0 = blockIdx.x * 32;
    const int m0 = blockIdx.y * 32;
    const int tx = threadIdx.x, ty = threadIdx.y;   // block (32, 8)

    __shared__ float tile[32][33];
    __shared__ float red[256];

    char* xb  = (char*)(g_xn  + (size_t)n * MM * 2 * DD);
    char* xtb = (char*)(g_xnT + (size_t)n * DD * 2 * MM);

    const int d = d0 + tx;
    const float mu = g_mean[n * DD + d];
    float ss = 0.f;
    #pragma unroll
    for (int r = 0; r < 4; r++) {
        int m = m0 + ty + r * 8;
        float v = x[(size_t)n * MM * DD + (size_t)m * DD + d] - mu;
        size_t pan = ((size_t)(m >> 7) * 8 + (d0 >> 5)) * 16384u;
        int rr = m & 127;
        uint32_t off = (uint32_t)(rr * 128 +
                        ((((d >> 3) & 3) ^ (rr & 7)) << 4) + (d & 7) * 2);
        *(__half*)(xb + pan + off) = __float2half_rn(v);
        tile[ty + r * 8][tx] = v;
        ss += v * v;
    }
    __syncthreads();
    #pragma unroll
    for (int r = 0; r < 4; r++) {
        int dd_ = ty + r * 8;
        float v = tile[tx][dd_];
        __half hh = __float2half_rn(v);
        __half hl = __float2half_rn(v - __half2float(hh));
        int dg = d0 + dd_, mg = m0 + tx;
        size_t pan = ((size_t)(dg >> 7) * 16 + (mg >> 5)) * 16384u;
        int rr = dg & 127;
        uint32_t gh = (uint32_t)((mg >> 3) & 3);
        uint32_t ohi = (uint32_t)(rr * 128 + ((gh ^ (rr & 7)) << 4) + (mg & 7) * 2);
        uint32_t olo = (uint32_t)(rr * 128 + (((4 + gh) ^ (rr & 7)) << 4) + (mg & 7) * 2);
        *(__half*)(xtb + pan + ohi) = hh;
        *(__half*)(xtb + pan + olo) = hl;
    }
    int t = ty * 32 + tx;
    red[t] = ss;
    __syncthreads();
    for (int s = 128; s > 0; s >>= 1) {
        if (t < s) red[t] += red[t + s];
        __syncthreads();
    }
    if (t == 0) g_ssp[n * 128 + blockIdx.y * 8 + blockIdx.x] = red[0];
}

__global__ __launch_bounds__(128) void reduce_tr_kernel() {
    int n = blockIdx.x, t = threadIdx.x;
    __shared__ float red[128];
    red[t] = g_ssp[n * 128 + t];
    __syncthreads();
    for (int s = 64; s > 0; s >>= 1) {
        if (t < s) red[t] += red[t + s];
        __syncthreads();
    }
    if (t == 0) g_tr[n] = red[0];
}

// ===================== fp16 mma.sync batched GEMM, bulk-copy panels =========
// 18 params: Cout,Amat,Bmat,Dmat,C2out,A2mat,Ktot,sA,sB,sC,sD,
//            mode,sym,sqr,pass3,pass3b,ofmt,wlo1
#define STG_B      32768u
#define MBAR_OFF   98304u
#define SMEM_DYN   98432

__global__ __launch_bounds__(256, 2) void gemm_h(
    void* __restrict__ Cout, const __half* __restrict__ Amat,
    const __half* __restrict__ Bmat, const __half* __restrict__ Dmat,
    void* __restrict__ C2out, const __half* __restrict__ A2mat,
    int Ktot, long long sA, long long sB, long long sC, long long sD,
    int mode, int sym, int sqr, int pass3, int pass3b, int ofmt, int wlo1)
{
    extern __shared__ char smem[];
    const uint32_t sb  = smem_u32(smem);
    const uint32_t mb0 = sb + MBAR_OFF;

    const int tid  = threadIdx.x;
    const int wid  = tid >> 5, lane = tid & 31;
    const int wm   = wid & 1;
    const int wn   = wid >> 1;
    const int n    = blockIdx.z;

    int ti, tj, job = 0, mymode = mode;
    if (sym) {
        int tt = blockIdx.x;
        if (tt >= 3) { job = 1; tt -= 3; mymode = 0; }
        ti = (tt == 2) ? 1 : 0; tj = (tt != 0) ? 1 : 0;
    } else {
        ti = blockIdx.x; tj = blockIdx.y;
    }
    const int rb = ti * 128;
    const int cb = tj * 128;

    const bool do_diag = sqr && sym && (job == 0) && (ti == tj);
    const bool need_al = ((job ? pass3b : pass3) != 0) && !do_diag;
    const bool wlo     = job ? (wlo1 != 0) : true;
    const bool do_t    = sym && (rb != cb);

    const __half* An = (job ? A2mat : Amat) + (size_t)n * sA;
    const __half* Bn = Bmat + (size_t)n * sB;
    const char* DnB = Dmat ? (const char*)(Dmat + (size_t)n * sD) : nullptr;

    const int nch = Ktot >> 5;
    const size_t aprow = (size_t)ti * nch * 16384u;
    const size_t bprow = (size_t)tj * nch * 16384u;

    const bool dpref = (mymode == 1) && (DnB != nullptr) && !do_t;
    const uint32_t sD1 = (uint32_t)(nch % 3);
    const uint32_t sD2 = (uint32_t)((nch + 1) % 3);
    const size_t dpanbase = ((size_t)ti * 8 + (size_t)tj * 4) * 16384u;

    if (tid == 0) {
        MBARRIER_INIT(mb0,      1);
        MBARRIER_INIT(mb0 + 8,  1);
        MBARRIER_INIT(mb0 + 16, 1);
        MBARRIER_INIT(mb0 + 24, 1);
        MBARRIER_INIT(mb0 + 32, 1);
    }
    __syncthreads();

    if (tid == 0) {
        #pragma unroll
        for (int pc_ = 0; pc_ < 2; pc_++) {
            uint32_t mbar = mb0 + (uint32_t)pc_ * 8u;
            uint32_t dst  = sb + (uint32_t)pc_ * STG_B;
            const char* sa = (const char*)An + aprow + (size_t)pc_ * 16384u;
            const char* sp = (const char*)Bn + bprow + (size_t)pc_ * 16384u;
            if (do_diag) {
                MBARRIER_EXPECT_TX(mbar, 16384u);
                CP_BULK(dst, sa, 16384u, mbar);
            } else {
                MBARRIER_EXPECT_TX(mbar, 32768u);
                CP_BULK(dst, sa, 16384u, mbar);
                CP_BULK(dst + 16384u, sp, 16384u, mbar);
            }
        }
    }

    // ldmatrix lane geometry
    const int t  = lane >> 3, s7 = lane & 7;
    const int chA = t >> 1;
    const int rAl = wm * 64 + (t & 1) * 8 + s7;
    const int chB = t & 1;
    const int rBl = wn * 32 + (t >> 1) * 8 + s7;

    float acc[4][4][4];
    #pragma unroll
    for (int i = 0; i < 4; i++)
        #pragma unroll
        for (int j = 0; j < 4; j++)
            #pragma unroll
            for (int q = 0; q < 4; q++) acc[i][j][q] = 0.f;

    for (int c = 0; c < nch; c++) {
        const int s = c % 3;
        MBARRIER_WAIT_PARITY(mb0 + (uint32_t)s * 8u, (c / 3) & 1);
        __syncthreads();

        if (tid == 0) {
            if (c + 2 < nch) {
                const int c2 = c + 2, s2 = c2 % 3;
                uint32_t mbar = mb0 + (uint32_t)s2 * 8u;
                uint32_t dst  = sb + (uint32_t)s2 * STG_B;
                const char* sa = (const char*)An + aprow + (size_t)c2 * 16384u;
                const char* sp = (const char*)Bn + bprow + (size_t)c2 * 16384u;
                if (do_diag) {
                    MBARRIER_EXPECT_TX(mbar, 16384u);
                    CP_BULK(dst, sa, 16384u, mbar);
                } else {
                    MBARRIER_EXPECT_TX(mbar, 32768u);
                    CP_BULK(dst, sa, 16384u, mbar);
                    CP_BULK(dst + 16384u, sp, 16384u, mbar);
                }
            } else if (dpref && c == nch - 2) {
                uint32_t dst = sb + sD1 * STG_B;
                MBARRIER_EXPECT_TX(mb0 + 24, 32768u);
                CP_BULK(dst,           DnB + dpanbase,            16384u, mb0 + 24);
                CP_BULK(dst + 16384u,  DnB + dpanbase + 16384u,   16384u, mb0 + 24);
            } else if (dpref && c == nch - 1) {
                uint32_t dst = sb + sD2 * STG_B;
                MBARRIER_EXPECT_TX(mb0 + 32, 32768u);
                CP_BULK(dst,           DnB + dpanbase + 32768u,   16384u, mb0 + 32);
                CP_BULK(dst + 16384u,  DnB + dpanbase + 49152u,   16384u, mb0 + 32);
            }
        }

        const uint32_t aB = sb + (uint32_t)s * STG_B;
        const uint32_t bB = do_diag ? aB : (aB + 16384u);

        #pragma unroll
        for (int kk = 0; kk < 2; kk++) {
            uint32_t bh[2][4], bl[2][4], ah[4][4], al[4][4];
            const int ghA = (kk << 1) + chA;
            const int ghB = (kk << 1) + chB;
            #pragma unroll
            for (int p = 0; p < 2; p++) {
                uint32_t h_ = bB + (uint32_t)((rBl + p * 16) * 128 + (ghB ^ s7) * 16);
                LDM_X4(bh[p][0], bh[p][1], bh[p][2], bh[p][3], h_);
            }
            #pragma unroll
            for (int p = 0; p < 2; p++) {
                uint32_t l_ = bB + (uint32_t)((rBl + p * 16) * 128 + ((4 + ghB) ^ s7) * 16);
                LDM_X4(bl[p][0], bl[p][1], bl[p][2], bl[p][3], l_);
            }
            #pragma unroll
            for (int mi = 0; mi < 4; mi++) {
                uint32_t h_ = aB + (uint32_t)((rAl + mi * 16) * 128 + (ghA ^ s7) * 16);
                LDM_X4(ah[mi][0], ah[mi][1], ah[mi][2], ah[mi][3], h_);
            }
            if (need_al) {
                #pragma unroll
                for (int mi = 0; mi < 4; mi++) {
                    uint32_t l_ = aB + (uint32_t)((rAl + mi * 16) * 128 + ((4 + ghA) ^ s7) * 16);
                    LDM_X4(al[mi][0], al[mi][1], al[mi][2], al[mi][3], l_);
                }
            }
            if (do_diag) {
                #pragma unroll
                for (int p = 0; p < 2; p++)
                    #pragma unroll
                    for (int q = 0; q < 4; q++) bh[p][q] = h2_half(bh[p][q]);
            }

            #pragma unroll
            for (int mi = 0; mi < 4; mi++)
                #pragma unroll
                for (int p = 0; p < 2; p++)
                    #pragma unroll
                    for (int q = 0; q < 2; q++)
                        MMA_FP16(acc[mi][p*2+q], ah[mi][0], ah[mi][1], ah[mi][2],
                                 ah[mi][3], bh[p][2*q], bh[p][2*q+1]);
            #pragma unroll
            for (int mi = 0; mi < 4; mi++)
                #pragma unroll
                for (int p = 0; p < 2; p++)
                    #pragma unroll
                    for (int q = 0; q < 2; q++)
                        MMA_FP16(acc[mi][p*2+q], ah[mi][0], ah[mi][1], ah[mi][2],
                                 ah[mi][3], bl[p][2*q], bl[p][2*q+1]);
            if (need_al) {
                #pragma unroll
                for (int mi = 0; mi < 4; mi++)
                    #pragma unroll
                    for (int p = 0; p < 2; p++)
                        #pragma unroll
                        for (int q = 0; q < 2; q++)
                            MMA_FP16(acc[mi][p*2+q], al[mi][0], al[mi][1], al[mi][2],
                                     al[mi][3], bh[p][2*q], bh[p][2*q+1]);
            }
        }
    }
    __syncthreads();

    // ---------------- epilogue ----------------
    if (dpref) {
        MBARRIER_WAIT_PARITY(mb0 + 24, 0);
        MBARRIER_WAIT_PARITY(mb0 + 32, 0);
    }

    const int g = lane >> 2, tig = lane & 3;
    float* stg = reinterpret_cast<float*>(smem);

    if (do_diag) {      // C_raw = acc + acc^T
        #pragma unroll
        for (int mi = 0; mi < 4; mi++)
            #pragma unroll
            for (int nj = 0; nj < 4; nj++) {
                const int cl = wn * 32 + nj * 8 + 2 * tig;
                #pragma unroll
                for (int h = 0; h < 2; h++) {
                    const int rl = wm * 64 + mi * 16 + g + 8 * h;
                    stg[rl * 129 + cl]     = acc[mi][nj][2 * h];
                    stg[rl * 129 + cl + 1] = acc[mi][nj][2 * h + 1];
                }
            }
        __syncthreads();
        #pragma unroll
        for (int mi = 0; mi < 4; mi++)
            #pragma unroll
            for (int nj = 0; nj < 4; nj++) {
                const int cl = wn * 32 + nj * 8 + 2 * tig;
                #pragma unroll
                for (int h = 0; h < 2; h++) {
                    const int rl = wm * 64 + mi * 16 + g + 8 * h;
                    acc[mi][nj][2 * h]     += stg[cl * 129 + rl];
                    acc[mi][nj][2 * h + 1] += stg[(cl + 1) * 129 + rl];
                }
            }
    }

    float ts = 0.f;
    if (mymode >= 2) ts = g_tr[n];
    const float sc2 = (mymode == 2) ? (-0.5f / ts) : 0.f;
    const float sc3 = (mymode == 3) ? rsqrtf(ts / (float)(MM - 1)) : 0.f;

    char*  ChB = nullptr;
    float* Cf  = nullptr;
    if (ofmt == 0) ChB = (char*)((__half*)(job ? C2out : Cout) + (size_t)n * sC);
    else           Cf  = (float*)Cout + (size_t)n * sC;

    const size_t pidx = dpanbase + (size_t)wn * 16384u;
    const char* dsm = smem + (size_t)(wn < 2 ? sD1 : sD2) * STG_B +
                      (size_t)(wn & 1) * 16384u;
    if (do_t) __syncthreads();

    #pragma unroll
    for (int mi = 0; mi < 4; mi++) {
        #pragma unroll
        for (int nj = 0; nj < 4; nj++) {
            const int cl = wn * 32 + nj * 8 + 2 * tig;
            const int col = cb + cl;
            #pragma unroll
            for (int h = 0; h < 2; h++) {
                const int rl = wm * 64 + mi * 16 + g + 8 * h;
                const int row = rb + rl;
                float v0 = acc[mi][nj][2 * h];
                float v1 = acc[mi][nj][2 * h + 1];
                const uint32_t ohi = (uint32_t)(rl * 128 +
                                     ((nj ^ (rl & 7)) << 4) + tig * 4);
                const uint32_t olo = (uint32_t)(rl * 128 +
                                     (((4 + nj) ^ (rl & 7)) << 4) + tig * 4);
                if (mymode == 1) {
                    float2 dh, dl;
                    if (dpref) {
                        dh = __half22float2(*(const __half2*)(dsm + ohi));
                        dl = __half22float2(*(const __half2*)(dsm + olo));
                    } else {
                        dh = __half22float2(*(const __half2*)(DnB + pidx + ohi));
                        dl = __half22float2(*(const __half2*)(DnB + pidx + olo));
                    }
                    v0 -= 1.5f * (dh.x + dl.x);
                    v1 -= 1.5f * (dh.y + dl.y);
                    if (row == col)     v0 += 1.5f;
                    if (row == col + 1) v1 += 1.5f;
                } else if (mymode == 2) {
                    v0 *= sc2; v1 *= sc2;
                    if (row == col)     v0 += 1.5f;
                    if (row == col + 1) v1 += 1.5f;
                } else if (mymode == 3) {
                    v0 *= sc3; v1 *= sc3;
                }
                if (ofmt == 0) {
                    __half2 hh = __float22half2_rn(make_float2(v0, v1));
                    *(__half2*)(ChB + pidx + ohi) = hh;
                    if (wlo) {
                        float2 f = __half22float2(hh);
                        *(__half2*)(ChB + pidx + olo) =
                            __float22half2_rn(make_float2(v0 - f.x, v1 - f.y));
                    }
                } else {
                    *(float2*)(Cf + (size_t)row * DD + col) = make_float2(v0, v1);
                }
                if (do_t) {
                    stg[rl * 129 + cl]     = v0;
                    stg[rl * 129 + cl + 1] = v1;
                }
            }
        }
    }

    // mirrored tile: C[cb..][rb..] = (this tile)^T, panel-format 16B stores
    if (do_t) {
        __syncthreads();
        const int r2    = tid >> 1;
        const int cbase = (tid & 1) * 64;
        #pragma unroll
        for (int q = 0; q < 8; q++) {
            const int c0 = cbase + q * 8;
            float w[8];
            #pragma unroll
            for (int u = 0; u < 8; u++) w[u] = stg[(c0 + u) * 129 + r2];
            __half2 h0 = __float22half2_rn(make_float2(w[0], w[1]));
            __half2 h1 = __float22half2_rn(make_float2(w[2], w[3]));
            __half2 h2 = __float22half2_rn(make_float2(w[4], w[5]));
            __half2 h3 = __float22half2_rn(make_float2(w[6], w[7]));
            const size_t p2 = ((size_t)tj * 8 + (size_t)ti * 4 + (size_t)(c0 >> 5))
                              * 16384u;
            const uint32_t gh2 = (uint32_t)((c0 >> 3) & 3);
            const uint32_t oh2 = (uint32_t)(r2 * 128 + ((gh2 ^ (r2 & 7)) << 4));
            *(uint4*)(ChB + p2 + oh2) =
                make_uint4(h2_bits(h0), h2_bits(h1), h2_bits(h2), h2_bits(h3));
            if (wlo) {
                float2 f0 = __half22float2(h0), f1 = __half22float2(h1);
                float2 f2 = __half22float2(h2), f3 = __half22float2(h3);
                __half2 l0 = __float22half2_rn(make_float2(w[0]-f0.x, w[1]-f0.y));
                __half2 l1 = __float22half2_rn(make_float2(w[2]-f1.x, w[3]-f1.y));
                __half2 l2 = __float22half2_rn(make_float2(w[4]-f2.x, w[5]-f2.y));
                __half2 l3 = __float22half2_rn(make_float2(w[6]-f3.x, w[7]-f3.y));
                const uint32_t ol2 = (uint32_t)(r2 * 128 +
                                     (((4 + gh2) ^ (r2 & 7)) << 4));
                *(uint4*)(ChB + p2 + ol2) =
                    make_uint4(h2_bits(l0), h2_bits(l1), h2_bits(l2), h2_bits(l3));
            }
        }
    }
}

// ======================= host launcher ======================================
extern "C" void kernel_launch(void* const* d_in, const int* in_sizes, int n_in,
                              void* d_out, int out_size) {
    const float* x = (const float*)d_in[0];
    float* out = (float*)d_out;

    __half *xn, *xnT, *Ba, *Bb, *Cm, *P0, *P1;
    cudaGetSymbolAddress((void**)&xn,  g_xn);
    cudaGetSymbolAddress((void**)&xnT, g_xnT);
    cudaGetSymbolAddress((void**)&Ba,  g_Ba);
    cudaGetSymbolAddress((void**)&Bb,  g_Bb);
    cudaGetSymbolAddress((void**)&Cm,  g_Cm);
    cudaGetSymbolAddress((void**)&P0,  g_P0);
    cudaGetSymbolAddress((void**)&P1,  g_P1);

    cudaFuncSetAttribute(gemm_h,
                         cudaFuncAttributeMaxDynamicSharedMemorySize, SMEM_DYN);

    const long long sM  = (long long)DD * 2 * DD;
    const long long sXT = (long long)DD * 2 * MM;
    const long long sXN = (long long)MM * 2 * DD;
    const long long sO  = (long long)MM * DD;
    const dim3 gSym(3, 1, NB);
    const dim3 gSym2(6, 1, NB);

    mean_kernel<<<NB, 256>>>(x);
    center_kernel<<<dim3(DD / 32, MM / 32, NB), dim3(32, 8)>>>(x);
    reduce_tr_kernel<<<NB, 128>>>();

    // args (18): C, A, B, D, C2, A2, K, sA, sB, sC, sD,
    //            mode, sym, sqr, pass3, pass3b, ofmt, wlo1

    // sigma -> Ba = B0   [K=512, sym, squaring, 3-pass]
    gemm_h<<<gSym, 256, SMEM_DYN>>>(Ba, xnT, xnT, nullptr, nullptr, nullptr,
                                    MM, sXT, sXT, sM, 0,
                                    2, 1, 1, 1, 1, 0, 1);
    // iter 1: Cm = B0^2 (squaring)
    gemm_h<<<gSym, 256, SMEM_DYN>>>(Cm, Ba, Ba, nullptr, nullptr, nullptr,
                                    DD, sM, sM, sM, 0,
                                    0, 1, 1, 1, 1, 0, 1);
    //         Bb = Cm*B0 - 1.5Cm + 1.5I  (B1)  [D prefetch, 3-pass]
    gemm_h<<<gSym, 256, SMEM_DYN>>>(Bb, Cm, Ba, Cm, nullptr, nullptr,
                                    DD, sM, sM, sM, sM,
                                    1, 1, 0, 1, 1, 0, 1);
    // iter 2: {Cm = B1^2 (squaring) , P0 = B0*B1 (P2, 2-pass job1)}
    gemm_h<<<gSym2, 256, SMEM_DYN>>>(Cm, Bb, Bb, nullptr, P0, Ba,
                                     DD, sM, sM, sM, 0,
                                     0, 1, 1, 1, 0, 0, 1);
    //         Ba = Cm*B1 - 1.5Cm + 1.5I  (B2)  [D prefetch, 3-pass]
    gemm_h<<<gSym, 256, SMEM_DYN>>>(Ba, Cm, Bb, Cm, nullptr, nullptr,
                                    DD, sM, sM, sM, sM,
                                    1, 1, 0, 1, 1, 0, 1);
    // iter 3: {Cm = B2^2 (squaring) , P1 = P2*B2 (P3, 2-pass job1, lo dead)}
    gemm_h<<<gSym2, 256, SMEM_DYN>>>(Cm, Ba, Ba, nullptr, P1, P0,
                                     DD, sM, sM, sM, 0,
                                     0, 1, 1, 1, 0, 0, 0);
    //         Bb = Cm*B2 - 1.5Cm + 1.5I  (B3)  [D prefetch, 2-pass: B3 feeds
    //         only P4 -> unamplified single hop]
    gemm_h<<<gSym, 256, SMEM_DYN>>>(Bb, Cm, Ba, Cm, nullptr, nullptr,
                                    DD, sM, sM, sM, sM,
                                    1, 1, 0, 0, 0, 0, 1);
    // iter 4: P0 = P3*B3 (P4) — 2-pass
    gemm_h<<<gSym, 256, SMEM_DYN>>>(P0, P1, Bb, nullptr, nullptr, nullptr,
                                    DD, sM, sM, sM, 0,
                                    0, 1, 0, 0, 0, 0, 1);
    // final: out = xn*P4*rsqrt(sumsq/(M-1)) — 2-pass, fp32 row-major out
    gemm_h<<<dim3(4, 2, NB), 256, SMEM_DYN>>>(out, xn, P0, nullptr, nullptr,
                                              nullptr, DD, sXN, sM, sO, 0,
                                              3, 0, 0, 0, 0, 1, 1);
}

// round 15
// speedup vs baseline: 5.9766x; 1.0333x over previous
#include <cuda_runtime.h>
#include <cuda_fp16.h>
#include <cstdint>
#include <cstddef>

#define NB   256
#define MM   512
#define DD   256

// ======================= scratch (device globals) ===========================
// Split-fp16 matrices stored as 16KB PANELS: panel(pr,pc) = rows pr*128..+127,
// K-cols pc*32..+31. Panel layout = exact smem image: row r at offset r*128,
// 8 x 16B groups (4 hi + 4 lo), group g stored at ((g ^ (r&7))<<4).
__device__ __align__(256) float  g_mean[NB * DD];
__device__ __align__(256) float  g_tr  [NB];
__device__ __align__(256) float  g_ssp [NB * 128];
__device__ __align__(256) __half g_xn  [NB * MM * 2 * DD];
__device__ __align__(256) __half g_xnT [NB * DD * 2 * MM];
__device__ __align__(256) __half g_Ba  [NB * DD * 2 * DD];
__device__ __align__(256) __half g_Bb  [NB * DD * 2 * DD];
__device__ __align__(256) __half g_Cm  [NB * DD * 2 * DD];
__device__ __align__(256) __half g_P0  [NB * DD * 2 * DD];
__device__ __align__(256) __half g_P1  [NB * DD * 2 * DD];

// ======================= PTX helpers ========================================
__device__ __forceinline__ uint32_t smem_u32(const void* p) {
    uint32_t a;
    asm("{ .reg .u64 t; cvta.to.shared.u64 t, %1; cvt.u32.u64 %0, t; }"
        : "=r"(a) : "l"(p));
    return a;
}

#define CP_BULK(dst_u32, src_gptr, bytes, mbar) \
    asm volatile("cp.async.bulk.shared::cluster.global.mbarrier::complete_tx::bytes " \
                 "[%0], [%1], %2, [%3];" \
                 :: "r"(dst_u32), "l"((const void*)(src_gptr)), \
                    "r"((uint32_t)(bytes)), "r"(mbar) : "memory")

#define MBARRIER_INIT(mbar, count) \
    asm volatile("mbarrier.init.shared.b64 [%0], %1;" \
                 :: "r"((uint32_t)(mbar)), "r"((uint32_t)(count)) : "memory")
#define MBARRIER_EXPECT_TX(mbar, tx) \
    asm volatile("mbarrier.arrive.expect_tx.shared.b64 _, [%0], %1;" \
                 :: "r"((uint32_t)(mbar)), "r"((uint32_t)(tx)) : "memory")
#define MBARRIER_WAIT_PARITY(mbar_addr, phase_parity) do {                    \
    uint32_t _mbar = (uint32_t)(mbar_addr);                                   \
    uint32_t _parity = (uint32_t)(phase_parity);                              \
    uint32_t _done;                                                           \
    asm volatile(                                                             \
        "{\n\t.reg .pred p;\n\t"                                              \
        "mbarrier.try_wait.parity.acquire.cta.shared::cta.b64 p, [%1], %2;\n\t" \
        "selp.b32 %0, 1, 0, p;\n\t}"                                          \
        : "=r"(_done) : "r"(_mbar), "r"(_parity) : "memory");                 \
    if (!_done) {                                                             \
        asm volatile(                                                         \
            "{\n\t.reg .pred P1;\n\t"                                         \
            "WAIT_LOOP_%=:\n\t"                                               \
            "mbarrier.try_wait.parity.acquire.cta.shared::cta.b64 P1, [%0], %1, 0x989680;\n\t" \
            "@P1 bra.uni WAIT_DONE_%=;\n\t"                                   \
            "bra.uni WAIT_LOOP_%=;\n\t"                                       \
            "WAIT_DONE_%=:\n\t}"                                              \
            :: "r"(_mbar), "r"(_parity) : "memory");                          \
    }                                                                         \
} while (0)

#define LDM_X4(r0, r1, r2, r3, addr) \
    asm volatile("ldmatrix.sync.aligned.m8n8.x4.shared.b16 {%0,%1,%2,%3}, [%4];" \
                 : "=r"(r0), "=r"(r1), "=r"(r2), "=r"(r3) : "r"(addr))

#define MMA_FP16(d, a0, a1, a2, a3, b0, b1) \
    asm("mma.sync.aligned.m16n8k16.row.col.f32.f16.f16.f32 " \
        "{%0,%1,%2,%3}, {%4,%5,%6,%7}, {%8,%9}, {%0,%1,%2,%3};" \
        : "+f"((d)[0]), "+f"((d)[1]), "+f"((d)[2]), "+f"((d)[3]) \
        : "r"(a0), "r"(a1), "r"(a2), "r"(a3), "r"(b0), "r"(b1))

__device__ __forceinline__ uint32_t h2_half(uint32_t x) {   // *0.5 packed fp16x2
    uint32_t d;
    asm("mul.rn.f16x2 %0, %1, %2;" : "=r"(d) : "r"(x), "r"(0x38003800u));
    return d;
}
__device__ __forceinline__ uint32_t h2_bits(__half2 h) {
    return *reinterpret_cast<uint32_t*>(&h);
}

// ======================= mean over axis 1 ===================================
__global__ __launch_bounds__(256) void mean_kernel(const float* __restrict__ x) {
    int n = blockIdx.x, d = threadIdx.x;
    const float* xp = x + (size_t)n * MM * DD + d;
    float s0 = 0.f, s1 = 0.f, s2 = 0.f, s3 = 0.f;
    #pragma unroll 4
    for (int m = 0; m < MM; m += 4) {
        s0 += xp[(size_t)(m + 0) * DD];
        s1 += xp[(size_t)(m + 1) * DD];
        s2 += xp[(size_t)(m + 2) * DD];
        s3 += xp[(size_t)(m + 3) * DD];
    }
    g_mean[n * DD + d] = (s0 + s1 + s2 + s3) * (1.f / (float)MM);
}

// ==== center: xn hi-only panels, xnT split panels, sumsq partials ===========
__global__ __launch_bounds__(256) void center_kernel(const float* __restrict__ x) {
    const int n  = blockIdx.z;
    const int d0 = blockIdx.x * 32;
    const int m0 = blockIdx.y * 32;
    const int tx = threadIdx.x, ty = threadIdx.y;   // block (32, 8)

    __shared__ float tile[32][33];
    __shared__ float red[256];

    char* xb  = (char*)(g_xn  + (size_t)n * MM * 2 * DD);
    char* xtb = (char*)(g_xnT + (size_t)n * DD * 2 * MM);

    const int d = d0 + tx;
    const float mu = g_mean[n * DD + d];
    float ss = 0.f;
    #pragma unroll
    for (int r = 0; r < 4; r++) {
        int m = m0 + ty + r * 8;
        float v = x[(size_t)n * MM * DD + (size_t)m * DD + d] - mu;
        size_t pan = ((size_t)(m >> 7) * 8 + (d0 >> 5)) * 16384u;
        int rr = m & 127;
        uint32_t off = (uint32_t)(rr * 128 +
                        ((((d >> 3) & 3) ^ (rr & 7)) << 4) + (d & 7) * 2);
        *(__half*)(xb + pan + off) = __float2half_rn(v);
        tile[ty + r * 8][tx] = v;
        ss += v * v;
    }
    __syncthreads();
    #pragma unroll
    for (int r = 0; r < 4; r++) {
        int dd_ = ty + r * 8;
        float v = tile[tx][dd_];
        __half hh = __float2half_rn(v);
        __half hl = __float2half_rn(v - __half2float(hh));
        int dg = d0 + dd_, mg = m0 + tx;
        size_t pan = ((size_t)(dg >> 7) * 16 + (mg >> 5)) * 16384u;
        int rr = dg & 127;
        uint32_t gh = (uint32_t)((mg >> 3) & 3);
        uint32_t ohi = (uint32_t)(rr * 128 + ((gh ^ (rr & 7)) << 4) + (mg & 7) * 2);
        uint32_t olo = (uint32_t)(rr * 128 + (((4 + gh) ^ (rr & 7)) << 4) + (mg & 7) * 2);
        *(__half*)(xtb + pan + ohi) = hh;
        *(__half*)(xtb + pan + olo) = hl;
    }
    int t = ty * 32 + tx;
    red[t] = ss;
    __syncthreads();
    for (int s = 128; s > 0; s >>= 1) {
        if (t < s) red[t] += red[t + s];
        __syncthreads();
    }
    if (t == 0) g_ssp[n * 128 + blockIdx.y * 8 + blockIdx.x] = red[0];
}

__global__ __launch_bounds__(128) void reduce_tr_kernel() {
    int n = blockIdx.x, t = threadIdx.x;
    __shared__ float red[128];
    red[t] = g_ssp[n * 128 + t];
    __syncthreads();
    for (int s = 64; s > 0; s >>= 1) {
        if (t < s) red[t] += red[t + s];
        __syncthreads();
    }
    if (t == 0) g_tr[n] = red[0];
}

// ===================== fp16 mma.sync batched GEMM, bulk-copy panels =========
// 19 params: Cout,Amat,Bmat,Dmat,C2out,A2mat,Ktot,sA,sB,sC,sD,
//            mode,sym,sqr,npass,npassb,ofmt,wlo0,wlo1
// npass/npassb: 1 = AhBh ; 2 = +AhBl ; 3 = +AlBh   (job0 / job1)
#define STG_B      32768u
#define MBAR_OFF   98304u
#define SMEM_DYN   98432

__global__ __launch_bounds__(256, 2) void gemm_h(
    void* __restrict__ Cout, const __half* __restrict__ Amat,
    const __half* __restrict__ Bmat, const __half* __restrict__ Dmat,
    void* __restrict__ C2out, const __half* __restrict__ A2mat,
    int Ktot, long long sA, long long sB, long long sC, long long sD,
    int mode, int sym, int sqr, int npass, int npassb,
    int ofmt, int wlo0, int wlo1)
{
    extern __shared__ char smem[];
    const uint32_t sb  = smem_u32(smem);
    const uint32_t mb0 = sb + MBAR_OFF;

    const int tid  = threadIdx.x;
    const int wid  = tid >> 5, lane = tid & 31;
    const int wm   = wid & 1;
    const int wn   = wid >> 1;
    const int n    = blockIdx.z;

    int ti, tj, job = 0, mymode = mode;
    if (sym) {
        int tt = blockIdx.x;
        if (tt >= 3) { job = 1; tt -= 3; mymode = 0; }
        ti = (tt == 2) ? 1 : 0; tj = (tt != 0) ? 1 : 0;
    } else {
        ti = blockIdx.x; tj = blockIdx.y;
    }
    const int rb = ti * 128;
    const int cb = tj * 128;

    const int  mynp    = job ? npassb : npass;
    const bool do_diag = sqr && sym && (job == 0) && (ti == tj);
    const bool need_al = (mynp >= 3) && !do_diag;
    const bool need_bl = (mynp >= 2) || do_diag;
    const bool wlo     = job ? (wlo1 != 0) : (wlo0 != 0);
    const bool do_t    = sym && (rb != cb);

    const __half* An = (job ? A2mat : Amat) + (size_t)n * sA;
    const __half* Bn = Bmat + (size_t)n * sB;
    const char* DnB = Dmat ? (const char*)(Dmat + (size_t)n * sD) : nullptr;

    const int nch = Ktot >> 5;
    const size_t aprow = (size_t)ti * nch * 16384u;
    const size_t bprow = (size_t)tj * nch * 16384u;

    const bool dpref = (mymode == 1) && (DnB != nullptr) && !do_t;
    const uint32_t sD1 = (uint32_t)(nch % 3);
    const uint32_t sD2 = (uint32_t)((nch + 1) % 3);
    const size_t dpanbase = ((size_t)ti * 8 + (size_t)tj * 4) * 16384u;

    if (tid == 0) {
        MBARRIER_INIT(mb0,      1);
        MBARRIER_INIT(mb0 + 8,  1);
        MBARRIER_INIT(mb0 + 16, 1);
        MBARRIER_INIT(mb0 + 24, 1);
        MBARRIER_INIT(mb0 + 32, 1);
    }
    __syncthreads();

    if (tid == 0) {
        #pragma unroll
        for (int pc_ = 0; pc_ < 2; pc_++) {
            uint32_t mbar = mb0 + (uint32_t)pc_ * 8u;
            uint32_t dst  = sb + (uint32_t)pc_ * STG_B;
            const char* sa = (const char*)An + aprow + (size_t)pc_ * 16384u;
            const char* sp = (const char*)Bn + bprow + (size_t)pc_ * 16384u;
            if (do_diag) {
                MBARRIER_EXPECT_TX(mbar, 16384u);
                CP_BULK(dst, sa, 16384u, mbar);
            } else {
                MBARRIER_EXPECT_TX(mbar, 32768u);
                CP_BULK(dst, sa, 16384u, mbar);
                CP_BULK(dst + 16384u, sp, 16384u, mbar);
            }
        }
    }

    // ldmatrix lane geometry
    const int t  = lane >> 3, s7 = lane & 7;
    const int chA = t >> 1;
    const int rAl = wm * 64 + (t & 1) * 8 + s7;
    const int chB = t & 1;
    const int rBl = wn * 32 + (t >> 1) * 8 + s7;

    float acc[4][4][4];
    #pragma unroll
    for (int i = 0; i < 4; i++)
        #pragma unroll
        for (int j = 0; j < 4; j++)
            #pragma unroll
            for (int q = 0; q < 4; q++) acc[i][j][q] = 0.f;

    for (int c = 0; c < nch; c++) {
        const int s = c % 3;
        MBARRIER_WAIT_PARITY(mb0 + (uint32_t)s * 8u, (c / 3) & 1);
        __syncthreads();

        if (tid == 0) {
            if (c + 2 < nch) {
                const int c2 = c + 2, s2 = c2 % 3;
                uint32_t mbar = mb0 + (uint32_t)s2 * 8u;
                uint32_t dst  = sb + (uint32_t)s2 * STG_B;
                const char* sa = (const char*)An + aprow + (size_t)c2 * 16384u;
                const char* sp = (const char*)Bn + bprow + (size_t)c2 * 16384u;
                if (do_diag) {
                    MBARRIER_EXPECT_TX(mbar, 16384u);
                    CP_BULK(dst, sa, 16384u, mbar);
                } else {
                    MBARRIER_EXPECT_TX(mbar, 32768u);
                    CP_BULK(dst, sa, 16384u, mbar);
                    CP_BULK(dst + 16384u, sp, 16384u, mbar);
                }
            } else if (dpref && c == nch - 2) {
                uint32_t dst = sb + sD1 * STG_B;
                MBARRIER_EXPECT_TX(mb0 + 24, 32768u);
                CP_BULK(dst,           DnB + dpanbase,            16384u, mb0 + 24);
                CP_BULK(dst + 16384u,  DnB + dpanbase + 16384u,   16384u, mb0 + 24);
            } else if (dpref && c == nch - 1) {
                uint32_t dst = sb + sD2 * STG_B;
                MBARRIER_EXPECT_TX(mb0 + 32, 32768u);
                CP_BULK(dst,           DnB + dpanbase + 32768u,   16384u, mb0 + 32);
                CP_BULK(dst + 16384u,  DnB + dpanbase + 49152u,   16384u, mb0 + 32);
            }
        }

        const uint32_t aB = sb + (uint32_t)s * STG_B;
        const uint32_t bB = do_diag ? aB : (aB + 16384u);

        #pragma unroll
        for (int kk = 0; kk < 2; kk++) {
            uint32_t bh[2][4], bl[2][4], ah[4][4], al[4][4];
            const int ghA = (kk << 1) + chA;
            const int ghB = (kk << 1) + chB;
            #pragma unroll
            for (int p = 0; p < 2; p++) {
                uint32_t h_ = bB + (uint32_t)((rBl + p * 16) * 128 + (ghB ^ s7) * 16);
                LDM_X4(bh[p][0], bh[p][1], bh[p][2], bh[p][3], h_);
            }
            if (need_bl) {
                #pragma unroll
                for (int p = 0; p < 2; p++) {
                    uint32_t l_ = bB + (uint32_t)((rBl + p * 16) * 128 + ((4 + ghB) ^ s7) * 16);
                    LDM_X4(bl[p][0], bl[p][1], bl[p][2], bl[p][3], l_);
                }
            }
            #pragma unroll
            for (int mi = 0; mi < 4; mi++) {
                uint32_t h_ = aB + (uint32_t)((rAl + mi * 16) * 128 + (ghA ^ s7) * 16);
                LDM_X4(ah[mi][0], ah[mi][1], ah[mi][2], ah[mi][3], h_);
            }
            if (need_al) {
                #pragma unroll
                for (int mi = 0; mi < 4; mi++) {
                    uint32_t l_ = aB + (uint32_t)((rAl + mi * 16) * 128 + ((4 + ghA) ^ s7) * 16);
                    LDM_X4(al[mi][0], al[mi][1], al[mi][2], al[mi][3], l_);
                }
            }
            if (do_diag) {
                #pragma unroll
                for (int p = 0; p < 2; p++)
                    #pragma unroll
                    for (int q = 0; q < 4; q++) bh[p][q] = h2_half(bh[p][q]);
            }

            // pass 1: Ah x Bh
            #pragma unroll
            for (int mi = 0; mi < 4; mi++)
                #pragma unroll
                for (int p = 0; p < 2; p++)
                    #pragma unroll
                    for (int q = 0; q < 2; q++)
                        MMA_FP16(acc[mi][p*2+q], ah[mi][0], ah[mi][1], ah[mi][2],
                                 ah[mi][3], bh[p][2*q], bh[p][2*q+1]);
            // pass 2: Ah x Bl
            if (need_bl) {
                #pragma unroll
                for (int mi = 0; mi < 4; mi++)
                    #pragma unroll
                    for (int p = 0; p < 2; p++)
                        #pragma unroll
                        for (int q = 0; q < 2; q++)
                            MMA_FP16(acc[mi][p*2+q], ah[mi][0], ah[mi][1], ah[mi][2],
                                     ah[mi][3], bl[p][2*q], bl[p][2*q+1]);
            }
            // pass 3: Al x Bh
            if (need_al) {
                #pragma unroll
                for (int mi = 0; mi < 4; mi++)
                    #pragma unroll
                    for (int p = 0; p < 2; p++)
                        #pragma unroll
                        for (int q = 0; q < 2; q++)
                            MMA_FP16(acc[mi][p*2+q], al[mi][0], al[mi][1], al[mi][2],
                                     al[mi][3], bh[p][2*q], bh[p][2*q+1]);
            }
        }
    }
    __syncthreads();

    // ---------------- epilogue ----------------
    if (dpref) {
        MBARRIER_WAIT_PARITY(mb0 + 24, 0);
        MBARRIER_WAIT_PARITY(mb0 + 32, 0);
    }

    const int g = lane >> 2, tig = lane & 3;
    float* stg = reinterpret_cast<float*>(smem);

    if (do_diag) {      // C_raw = acc + acc^T
        #pragma unroll
        for (int mi = 0; mi < 4; mi++)
            #pragma unroll
            for (int nj = 0; nj < 4; nj++) {
                const int cl = wn * 32 + nj * 8 + 2 * tig;
                #pragma unroll
                for (int h = 0; h < 2; h++) {
                    const int rl = wm * 64 + mi * 16 + g + 8 * h;
                    stg[rl * 129 + cl]     = acc[mi][nj][2 * h];
                    stg[rl * 129 + cl + 1] = acc[mi][nj][2 * h + 1];
                }
            }
        __syncthreads();
        #pragma unroll
        for (int mi = 0; mi < 4; mi++)
            #pragma unroll
            for (int nj = 0; nj < 4; nj++) {
                const int cl = wn * 32 + nj * 8 + 2 * tig;
                #pragma unroll
                for (int h = 0; h < 2; h++) {
                    const int rl = wm * 64 + mi * 16 + g + 8 * h;
                    acc[mi][nj][2 * h]     += stg[cl * 129 + rl];
                    acc[mi][nj][2 * h + 1] += stg[(cl + 1) * 129 + rl];
                }
            }
    }

    float ts = 0.f;
    if (mymode >= 2) ts = g_tr[n];
    const float sc2 = (mymode == 2) ? (-0.5f / ts) : 0.f;
    const float sc3 = (mymode == 3) ? rsqrtf(ts / (float)(MM - 1)) : 0.f;

    char*  ChB = nullptr;
    float* Cf  = nullptr;
    if (ofmt == 0) ChB = (char*)((__half*)(job ? C2out : Cout) + (size_t)n * sC);
    else           Cf  = (float*)Cout + (size_t)n * sC;

    const size_t pidx = dpanbase + (size_t)wn * 16384u;
    const char* dsm = smem + (size_t)(wn < 2 ? sD1 : sD2) * STG_B +
                      (size_t)(wn & 1) * 16384u;
    if (do_t) __syncthreads();

    #pragma unroll
    for (int mi = 0; mi < 4; mi++) {
        #pragma unroll
        for (int nj = 0; nj < 4; nj++) {
            const int cl = wn * 32 + nj * 8 + 2 * tig;
            const int col = cb + cl;
            #pragma unroll
            for (int h = 0; h < 2; h++) {
                const int rl = wm * 64 + mi * 16 + g + 8 * h;
                const int row = rb + rl;
                float v0 = acc[mi][nj][2 * h];
                float v1 = acc[mi][nj][2 * h + 1];
                const uint32_t ohi = (uint32_t)(rl * 128 +
                                     ((nj ^ (rl & 7)) << 4) + tig * 4);
                const uint32_t olo = (uint32_t)(rl * 128 +
                                     (((4 + nj) ^ (rl & 7)) << 4) + tig * 4);
                if (mymode == 1) {
                    float2 dh, dl;
                    if (dpref) {
                        dh = __half22float2(*(const __half2*)(dsm + ohi));
                        dl = __half22float2(*(const __half2*)(dsm + olo));
                    } else {
                        dh = __half22float2(*(const __half2*)(DnB + pidx + ohi));
                        dl = __half22float2(*(const __half2*)(DnB + pidx + olo));
                    }
                    v0 -= 1.5f * (dh.x + dl.x);
                    v1 -= 1.5f * (dh.y + dl.y);
                    if (row == col)     v0 += 1.5f;
                    if (row == col + 1) v1 += 1.5f;
                } else if (mymode == 2) {
                    v0 *= sc2; v1 *= sc2;
                    if (row == col)     v0 += 1.5f;
                    if (row == col + 1) v1 += 1.5f;
                } else if (mymode == 3) {
                    v0 *= sc3; v1 *= sc3;
                }
                if (ofmt == 0) {
                    __half2 hh = __float22half2_rn(make_float2(v0, v1));
                    *(__half2*)(ChB + pidx + ohi) = hh;
                    if (wlo) {
                        float2 f = __half22float2(hh);
                        *(__half2*)(ChB + pidx + olo) =
                            __float22half2_rn(make_float2(v0 - f.x, v1 - f.y));
                    }
                } else {
                    *(float2*)(Cf + (size_t)row * DD + col) = make_float2(v0, v1);
                }
                if (do_t) {
                    stg[rl * 129 + cl]     = v0;
                    stg[rl * 129 + cl + 1] = v1;
                }
            }
        }
    }

    // mirrored tile: C[cb..][rb..] = (this tile)^T, panel-format 16B stores
    if (do_t) {
        __syncthreads();
        const int r2    = tid >> 1;
        const int cbase = (tid & 1) * 64;
        #pragma unroll
        for (int q = 0; q < 8; q++) {
            const int c0 = cbase + q * 8;
            float w[8];
            #pragma unroll
            for (int u = 0; u < 8; u++) w[u] = stg[(c0 + u) * 129 + r2];
            __half2 h0 = __float22half2_rn(make_float2(w[0], w[1]));
            __half2 h1 = __float22half2_rn(make_float2(w[2], w[3]));
            __half2 h2 = __float22half2_rn(make_float2(w[4], w[5]));
            __half2 h3 = __float22half2_rn(make_float2(w[6], w[7]));
            const size_t p2 = ((size_t)tj * 8 + (size_t)ti * 4 + (size_t)(c0 >> 5))
                              * 16384u;
            const uint32_t gh2 = (uint32_t)((c0 >> 3) & 3);
            const uint32_t oh2 = (uint32_t)(r2 * 128 + ((gh2 ^ (r2 & 7)) << 4));
            *(uint4*)(ChB + p2 + oh2) =
                make_uint4(h2_bits(h0), h2_bits(h1), h2_bits(h2), h2_bits(h3));
            if (wlo) {
                float2 f0 = __half22float2(h0), f1 = __half22float2(h1);
                float2 f2 = __half22float2(h2), f3 = __half22float2(h3);
                __half2 l0 = __float22half2_rn(make_float2(w[0]-f0.x, w[1]-f0.y));
                __half2 l1 = __float22half2_rn(make_float2(w[2]-f1.x, w[3]-f1.y));
                __half2 l2 = __float22half2_rn(make_float2(w[4]-f2.x, w[5]-f2.y));
                __half2 l3 = __float22half2_rn(make_float2(w[6]-f3.x, w[7]-f3.y));
                const uint32_t ol2 = (uint32_t)(r2 * 128 +
                                     (((4 + gh2) ^ (r2 & 7)) << 4));
                *(uint4*)(ChB + p2 + ol2) =
                    make_uint4(h2_bits(l0), h2_bits(l1), h2_bits(l2), h2_bits(l3));
            }
        }
    }
}

// ======================= host launcher ======================================
extern "C" void kernel_launch(void* const* d_in, const int* in_sizes, int n_in,
                              void* d_out, int out_size) {
    const float* x = (const float*)d_in[0];
    float* out = (float*)d_out;

    __half *xn, *xnT, *Ba, *Bb, *Cm, *P0, *P1;
    cudaGetSymbolAddress((void**)&xn,  g_xn);
    cudaGetSymbolAddress((void**)&xnT, g_xnT);
    cudaGetSymbolAddress((void**)&Ba,  g_Ba);
    cudaGetSymbolAddress((void**)&Bb,  g_Bb);
    cudaGetSymbolAddress((void**)&Cm,  g_Cm);
    cudaGetSymbolAddress((void**)&P0,  g_P0);
    cudaGetSymbolAddress((void**)&P1,  g_P1);

    cudaFuncSetAttribute(gemm_h,
                         cudaFuncAttributeMaxDynamicSharedMemorySize, SMEM_DYN);

    const long long sM  = (long long)DD * 2 * DD;
    const long long sXT = (long long)DD * 2 * MM;
    const long long sXN = (long long)MM * 2 * DD;
    const long long sO  = (long long)MM * DD;
    const dim3 gSym(3, 1, NB);
    const dim3 gSym2(6, 1, NB);

    mean_kernel<<<NB, 256>>>(x);
    center_kernel<<<dim3(DD / 32, MM / 32, NB), dim3(32, 8)>>>(x);
    reduce_tr_kernel<<<NB, 128>>>();

    // args (19): C, A, B, D, C2, A2, K, sA, sB, sC, sD,
    //            mode, sym, sqr, npass, npassb, ofmt, wlo0, wlo1

    // sigma -> Ba = B0   [K=512, sym, squaring, 3-pass]
    gemm_h<<<gSym, 256, SMEM_DYN>>>(Ba, xnT, xnT, nullptr, nullptr, nullptr,
                                    MM, sXT, sXT, sM, 0,
                                    2, 1, 1, 3, 3, 0, 1, 1);
    // iter 1: Cm = B0^2 (squaring, 3-pass)
    gemm_h<<<gSym, 256, SMEM_DYN>>>(Cm, Ba, Ba, nullptr, nullptr, nullptr,
                                    DD, sM, sM, sM, 0,
                                    0, 1, 1, 3, 3, 0, 1, 1);
    //         Bb = Cm*B0 - 1.5Cm + 1.5I  (B1)  [D prefetch, 3-pass]
    gemm_h<<<gSym, 256, SMEM_DYN>>>(Bb, Cm, Ba, Cm, nullptr, nullptr,
                                    DD, sM, sM, sM, sM,
                                    1, 1, 0, 3, 3, 0, 1, 1);
    // iter 2: {Cm = B1^2 (squaring) , P0 = B0*B1 (P2, 2-pass, lo dead)}
    gemm_h<<<gSym2, 256, SMEM_DYN>>>(Cm, Bb, Bb, nullptr, P0, Ba,
                                     DD, sM, sM, sM, 0,
                                     0, 1, 1, 3, 2, 0, 1, 0);
    //         Ba = Cm*B1 - 1.5Cm + 1.5I  (B2)  [D prefetch, 3-pass]
    gemm_h<<<gSym, 256, SMEM_DYN>>>(Ba, Cm, Bb, Cm, nullptr, nullptr,
                                    DD, sM, sM, sM, sM,
                                    1, 1, 0, 3, 3, 0, 1, 1);
    // iter 3: {Cm = B2^2 (squaring) , P1 = P2*B2 (P3, 2-pass, lo dead)}
    gemm_h<<<gSym2, 256, SMEM_DYN>>>(Cm, Ba, Ba, nullptr, P1, P0,
                                     DD, sM, sM, sM, 0,
                                     0, 1, 1, 3, 2, 0, 1, 0);
    //         Bb = Cm*B2 - 1.5Cm + 1.5I  (B3)  [D prefetch, 3-pass RESTORED]
    gemm_h<<<gSym, 256, SMEM_DYN>>>(Bb, Cm, Ba, Cm, nullptr, nullptr,
                                    DD, sM, sM, sM, sM,
                                    1, 1, 0, 3, 3, 0, 1, 1);
    // iter 4: P0 = P3*B3 (P4) — 2-pass, P4-lo dead (final is 1-pass)
    gemm_h<<<gSym, 256, SMEM_DYN>>>(P0, P1, Bb, nullptr, nullptr, nullptr,
                                    DD, sM, sM, sM, 0,
                                    0, 1, 0, 2, 2, 0, 0, 1);
    // final: out = xn*P4*rsqrt(sumsq/(M-1)) — 1-pass (AhBh), fp32 out
    gemm_h<<<dim3(4, 2, NB), 256, SMEM_DYN>>>(out, xn, P0, nullptr, nullptr,
                                              nullptr, DD, sXN, sM, sO, 0,
                                              3, 0, 0, 1, 1, 1, 1, 1);
}